// round 1
// baseline (speedup 1.0000x reference)
#include <cuda_runtime.h>
#include <cuda_bf16.h>
#include <math.h>

// Problem constants
#define BSZ 2
#define SEQ 2048
#define DIM 2048
#define NH 16
#define NKV 8
#define HD 128
#define QKVD 4096          // (16 + 2*8) * 128
#define NTOK (BSZ*SEQ)     // 4096

// ---------------- scratch (static __device__, no allocations) ----------------
static __device__ float g_qkv[(size_t)NTOK * QKVD];                  // 64 MB
static __device__ float g_q  [(size_t)BSZ * NH  * SEQ * HD];         // 32 MB
static __device__ float g_k  [(size_t)BSZ * NKV * SEQ * HD];         // 16 MB
static __device__ float g_vt [(size_t)BSZ * NKV * HD  * SEQ];        // 16 MB (V transposed per kv-head)
static __device__ float g_sc [(size_t)BSZ * NH  * SEQ * SEQ];        // 512 MB scores
static __device__ float g_att[(size_t)NTOK * DIM];                   // 32 MB

// ---------------- generalized batched A*B^T GEMM ----------------
// C[z][m][n] = sum_k A[z][m][k] * B[z][n][k]
// per-z base offsets: off = (z>>sh)*stH + (z&mk)*stL
struct Off { int sh; long long stH; int mk; long long stL; };
__device__ __forceinline__ size_t offz(Off o, int z) {
    return (size_t)((long long)(z >> o.sh) * o.stH + (long long)(z & o.mk) * o.stL);
}

#define BM 64
#define BN 64
#define BK 16

__global__ __launch_bounds__(256)
void gemm_abt(const float* __restrict__ A, const float* __restrict__ B,
              float* __restrict__ C,
              int M, int N, int K, int lda, int ldb, int ldc,
              Off oa, Off ob, Off oc)
{
    __shared__ float As[BK][BM + 4];
    __shared__ float Bs[BK][BN + 4];

    int z = blockIdx.z;
    A += offz(oa, z);
    B += offz(ob, z);
    C += offz(oc, z);

    int bm = blockIdx.y * BM;
    int bn = blockIdx.x * BN;
    int tid = threadIdx.x;
    int tx = tid & 15;        // n direction
    int ty = tid >> 4;        // m direction

    int lr = tid >> 2;        // 0..63 : row within tile
    int lk = (tid & 3) * 4;   // 0,4,8,12 : k offset (float4)

    float acc[4][4] = {};

    for (int k0 = 0; k0 < K; k0 += BK) {
        float4 a4 = *(const float4*)&A[(size_t)(bm + lr) * lda + k0 + lk];
        float4 b4 = *(const float4*)&B[(size_t)(bn + lr) * ldb + k0 + lk];
        __syncthreads();
        As[lk + 0][lr] = a4.x; As[lk + 1][lr] = a4.y;
        As[lk + 2][lr] = a4.z; As[lk + 3][lr] = a4.w;
        Bs[lk + 0][lr] = b4.x; Bs[lk + 1][lr] = b4.y;
        Bs[lk + 2][lr] = b4.z; Bs[lk + 3][lr] = b4.w;
        __syncthreads();

        #pragma unroll
        for (int k = 0; k < BK; k++) {
            float4 av = *(const float4*)&As[k][ty * 4];
            float4 bv = *(const float4*)&Bs[k][tx * 4];
            float a[4] = {av.x, av.y, av.z, av.w};
            float b[4] = {bv.x, bv.y, bv.z, bv.w};
            #pragma unroll
            for (int i = 0; i < 4; i++)
                #pragma unroll
                for (int j = 0; j < 4; j++)
                    acc[i][j] += a[i] * b[j];
        }
    }

    #pragma unroll
    for (int i = 0; i < 4; i++) {
        int row = bm + ty * 4 + i;
        float4 o = make_float4(acc[i][0], acc[i][1], acc[i][2], acc[i][3]);
        *(float4*)&C[(size_t)row * ldc + bn + tx * 4] = o;
    }
}

// ---------------- RMSNorm + RoPE for Q and K heads ----------------
// grid: (NTOK, NH+NKV), block: 64 (one thread per (even,odd) pair)
__global__ __launch_bounds__(64)
void norm_rope(const float* __restrict__ qkv,
               const float* __restrict__ cosb, const float* __restrict__ sinb,
               const float* __restrict__ qw, const float* __restrict__ kw,
               float* __restrict__ q, float* __restrict__ k)
{
    int tok = blockIdx.x;
    int h   = blockIdx.y;            // 0..15 -> Q head, 16..23 -> K head
    int i   = threadIdx.x;           // 0..63
    int b   = tok >> 11;             // tok / SEQ
    int s   = tok & (SEQ - 1);

    const float* src = qkv + (size_t)tok * QKVD + h * HD;
    float x0 = src[2 * i];
    float x1 = src[2 * i + 1];

    float ss = x0 * x0 + x1 * x1;
    #pragma unroll
    for (int off = 16; off > 0; off >>= 1)
        ss += __shfl_xor_sync(0xFFFFFFFFu, ss, off);
    __shared__ float red[2];
    if ((i & 31) == 0) red[i >> 5] = ss;
    __syncthreads();
    float total = red[0] + red[1];

    float inv = rsqrtf(total * (1.0f / HD) + 1e-5f);
    const float* w = (h < NH) ? qw : kw;
    float y0 = x0 * inv * w[2 * i];
    float y1 = x1 * inv * w[2 * i + 1];

    float c  = cosb[(size_t)s * (HD / 2) + i];
    float sn = sinb[(size_t)s * (HD / 2) + i];
    float o0 = y0 * c - y1 * sn;
    float o1 = y0 * sn + y1 * c;

    float* dst;
    if (h < NH)  dst = q + ((size_t)(b * NH + h) * SEQ + s) * HD;
    else         dst = k + ((size_t)(b * NKV + (h - NH)) * SEQ + s) * HD;
    dst[2 * i]     = o0;
    dst[2 * i + 1] = o1;
}

// ---------------- V transpose: qkv[tok][3072 + kh*128 + d] -> vt[(b*NKV+kh)][d][s] ----------------
// grid: (SEQ/32, HD/32, BSZ*NKV), block (32, 8)
__global__ __launch_bounds__(256)
void vtrans(const float* __restrict__ qkv, float* __restrict__ vt)
{
    __shared__ float tile[32][33];
    int zz = blockIdx.z;            // b*NKV + kh
    int b  = zz >> 3;
    int kh = zz & 7;
    int s0 = blockIdx.x * 32;
    int d0 = blockIdx.y * 32;

    #pragma unroll
    for (int j = 0; j < 4; j++) {
        int s = s0 + threadIdx.y + j * 8;
        tile[threadIdx.y + j * 8][threadIdx.x] =
            qkv[((size_t)(b * SEQ + s)) * QKVD + (NH + NKV) * HD + kh * HD + d0 + threadIdx.x];
    }
    __syncthreads();
    #pragma unroll
    for (int j = 0; j < 4; j++) {
        int d = d0 + threadIdx.y + j * 8;
        vt[((size_t)zz * HD + d) * SEQ + s0 + threadIdx.x] =
            tile[threadIdx.x][threadIdx.y + j * 8];
    }
}

// ---------------- masked scaled softmax over k (in place on g_sc) ----------------
// grid: (SEQ, BSZ*NH), block: 256 — one block per score row
__global__ __launch_bounds__(256)
void softmax_rows(float* __restrict__ sc, const int* __restrict__ mask, float scale)
{
    int qrow = blockIdx.x;
    int z    = blockIdx.y;          // b*NH + h
    int b    = z >> 4;
    float* row = sc + ((size_t)z * SEQ + qrow) * SEQ;
    const int* mrow = mask + (size_t)b * SEQ;

    int t = threadIdx.x;
    float v[8];
    float mx = -INFINITY;
    #pragma unroll
    for (int j = 0; j < 8; j++) {
        int kk = t + j * 256;
        float x = row[kk];
        x = mrow[kk] ? x * scale : -1e30f;
        v[j] = x;
        mx = fmaxf(mx, x);
    }
    __shared__ float smax[8];
    __shared__ float ssum[8];
    #pragma unroll
    for (int off = 16; off > 0; off >>= 1)
        mx = fmaxf(mx, __shfl_xor_sync(0xFFFFFFFFu, mx, off));
    if ((t & 31) == 0) smax[t >> 5] = mx;
    __syncthreads();
    float M = smax[0];
    #pragma unroll
    for (int w = 1; w < 8; w++) M = fmaxf(M, smax[w]);

    float s = 0.0f;
    #pragma unroll
    for (int j = 0; j < 8; j++) {
        float p = __expf(v[j] - M);
        v[j] = p;
        s += p;
    }
    #pragma unroll
    for (int off = 16; off > 0; off >>= 1)
        s += __shfl_xor_sync(0xFFFFFFFFu, s, off);
    if ((t & 31) == 0) ssum[t >> 5] = s;
    __syncthreads();
    float S = 0.0f;
    #pragma unroll
    for (int w = 0; w < 8; w++) S += ssum[w];
    float invS = 1.0f / S;

    #pragma unroll
    for (int j = 0; j < 8; j++)
        row[t + j * 256] = v[j] * invS;
}

// ---------------- launch ----------------
extern "C" void kernel_launch(void* const* d_in, const int* in_sizes, int n_in,
                              void* d_out, int out_size)
{
    const float* x     = (const float*)d_in[0];
    const int*   xmask = (const int*)  d_in[1];
    const float* fcos  = (const float*)d_in[2];
    const float* fsin  = (const float*)d_in[3];
    const float* Wqkv  = (const float*)d_in[4];
    const float* Wout  = (const float*)d_in[5];
    const float* qw    = (const float*)d_in[6];
    const float* kw    = (const float*)d_in[7];
    float* out = (float*)d_out;

    float *qkv, *q, *k, *vt, *sc, *att;
    cudaGetSymbolAddress((void**)&qkv, g_qkv);
    cudaGetSymbolAddress((void**)&q,   g_q);
    cudaGetSymbolAddress((void**)&k,   g_k);
    cudaGetSymbolAddress((void**)&vt,  g_vt);
    cudaGetSymbolAddress((void**)&sc,  g_sc);
    cudaGetSymbolAddress((void**)&att, g_att);

    Off zo = {0, 0, 0, 0};

    // 1) qkv = x @ Wqkv^T : M=4096, N=4096, K=2048
    gemm_abt<<<dim3(QKVD / BN, NTOK / BM, 1), 256>>>(
        x, Wqkv, qkv, NTOK, QKVD, DIM, DIM, DIM, QKVD, zo, zo, zo);

    // 2) RMSNorm + RoPE on Q,K
    norm_rope<<<dim3(NTOK, NH + NKV), 64>>>(qkv, fcos, fsin, qw, kw, q, k);

    // 3) V transpose
    vtrans<<<dim3(SEQ / 32, HD / 32, BSZ * NKV), dim3(32, 8)>>>(qkv, vt);

    // 4) scores[z] = Q[z] @ K[z>>1]^T : M=N=2048, K=128, z in [0,32)
    {
        Off oa = {0, (long long)SEQ * HD, 0, 0};
        Off ob = {1, (long long)SEQ * HD, 0, 0};
        Off oc = {0, (long long)SEQ * SEQ, 0, 0};
        gemm_abt<<<dim3(SEQ / BN, SEQ / BM, BSZ * NH), 256>>>(
            q, k, sc, SEQ, SEQ, HD, HD, HD, SEQ, oa, ob, oc);
    }

    // 5) masked softmax (scale folded in)
    softmax_rows<<<dim3(SEQ, BSZ * NH), 256>>>(sc, xmask, rsqrtf((float)HD));

    // 6) att[b,q,h*128+d] = P[z] @ Vt[z>>1]^T : M=2048, N=128, K=2048
    {
        Off oa = {0, (long long)SEQ * SEQ, 0, 0};
        Off ob = {1, (long long)HD * SEQ, 0, 0};
        Off oc = {4, (long long)SEQ * DIM, 15, (long long)HD};
        gemm_abt<<<dim3(HD / BN, SEQ / BM, BSZ * NH), 256>>>(
            sc, vt, att, SEQ, HD, SEQ, SEQ, SEQ, DIM, oa, ob, oc);
    }

    // 7) out = att @ Wout^T : M=4096, N=2048, K=2048
    gemm_abt<<<dim3(DIM / BN, NTOK / BM, 1), 256>>>(
        att, Wout, out, NTOK, DIM, DIM, DIM, DIM, DIM, zo, zo, zo);
}

// round 3
// speedup vs baseline: 2.6300x; 2.6300x over previous
#include <cuda_runtime.h>
#include <cuda_bf16.h>
#include <math.h>
#include <stdint.h>

// Problem constants
#define BSZ 2
#define SEQ 2048
#define DIM 2048
#define NH 16
#define NKV 8
#define HD 128
#define QKVD 4096          // (16 + 2*8) * 128
#define NTOK (BSZ*SEQ)     // 4096

// ---------------- scratch (static __device__, no allocations) ----------------
static __device__ float g_qkv[(size_t)NTOK * QKVD];                  // 64 MB
static __device__ float g_q  [(size_t)BSZ * NH  * SEQ * HD];         // 32 MB
static __device__ float g_k  [(size_t)BSZ * NKV * SEQ * HD];         // 16 MB
static __device__ float g_vt [(size_t)BSZ * NKV * HD  * SEQ];        // 16 MB
static __device__ float g_sc [(size_t)BSZ * NH  * SEQ * SEQ];        // 512 MB
static __device__ float g_att[(size_t)NTOK * DIM];                   // 32 MB

// batching descriptor: per-z offset = (z>>sh)*stH + (z&mk)*stL
struct Off { int sh; long long stH; int mk; long long stL; };
__device__ __forceinline__ size_t offz(Off o, int z) {
    return (size_t)((long long)(z >> o.sh) * o.stH + (long long)(z & o.mk) * o.stL);
}

__device__ __forceinline__ uint32_t smem_u32(const void* p) {
    uint32_t a;
    asm("{ .reg .u64 t; cvta.to.shared.u64 t, %1; cvt.u32.u64 %0, t; }" : "=r"(a) : "l"(p));
    return a;
}

__device__ __forceinline__ void cpa16(uint32_t saddr, const void* g) {
    asm volatile("cp.async.cg.shared.global [%0], [%1], 16;" :: "r"(saddr), "l"(g));
}

// fp32 bits -> tf32 with round-to-nearest (add half-ULP of the 13 dropped bits)
__device__ __forceinline__ uint32_t tf32r(float f) { return __float_as_uint(f) + 0x1000u; }

// smem tile: 128 rows x 32 k, row stride 36 floats (conflict-free frag loads)
#define TSTRIDE 36
#define TFLOATS (128 * TSTRIDE)          // 4608 floats per tile buffer
#define SMEM_TOTAL (4 * TFLOATS * 4)     // A0,A1,B0,B1 = 73728 bytes

// ---------------- tensor-core TF32 batched GEMM: C[z] = A[z] * B[z]^T ----------------
// CTA tile 128x128, 8 warps (2m x 4n), warp tile 64x32, K chunk 32, cp.async double buffer
__global__ __launch_bounds__(256)
void mma_gemm(const float* __restrict__ A, const float* __restrict__ B, float* __restrict__ C,
              int K, int lda, int ldb, int ldc, Off oa, Off ob, Off oc)
{
    extern __shared__ float sm[];
    float* Abuf[2] = { sm,               sm + TFLOATS };
    float* Bbuf[2] = { sm + 2 * TFLOATS, sm + 3 * TFLOATS };
    uint32_t sA[2] = { smem_u32(Abuf[0]), smem_u32(Abuf[1]) };
    uint32_t sB[2] = { smem_u32(Bbuf[0]), smem_u32(Bbuf[1]) };

    int tid = threadIdx.x;
    int wid = tid >> 5, lane = tid & 31;
    int g = lane >> 2, t4 = lane & 3;
    int wm = wid & 1, wn = wid >> 1;
    int m0base = wm * 64, n0base = wn * 32;

    int z = blockIdx.z;
    A += offz(oa, z); B += offz(ob, z); C += offz(oc, z);
    size_t bm = (size_t)blockIdx.y * 128;
    size_t bn = (size_t)blockIdx.x * 128;

    const int NC = K >> 5;

    float acc[4][4][4];
    #pragma unroll
    for (int i = 0; i < 4; i++)
        #pragma unroll
        for (int j = 0; j < 4; j++)
            #pragma unroll
            for (int r = 0; r < 4; r++) acc[i][j][r] = 0.0f;

    // ---- async load of chunk c into buffer b ----
    auto load_chunk = [&](int c, int b) {
        const float* Ak = A + c * 32;
        const float* Bk = B + c * 32;
        #pragma unroll
        for (int i = 0; i < 4; i++) {
            int idx = tid + i * 256;            // 0..1023
            int row = idx >> 3, kc = idx & 7;   // kc: which 16B of the 32-wide k chunk
            cpa16(sA[b] + (uint32_t)(row * TSTRIDE + kc * 4) * 4,
                  Ak + (bm + row) * (size_t)lda + kc * 4);
            cpa16(sB[b] + (uint32_t)(row * TSTRIDE + kc * 4) * 4,
                  Bk + (bn + row) * (size_t)ldb + kc * 4);
        }
        asm volatile("cp.async.commit_group;" ::: "memory");
    };

    load_chunk(0, 0);

    for (int c = 0; c < NC; c++) {
        int b = c & 1;
        if (c + 1 < NC) {
            load_chunk(c + 1, (c + 1) & 1);
            asm volatile("cp.async.wait_group 1;" ::: "memory");
        } else {
            asm volatile("cp.async.wait_group 0;" ::: "memory");
        }
        __syncthreads();

        const float* Ab = Abuf[b];
        const float* Bb = Bbuf[b];

        #pragma unroll
        for (int ks = 0; ks < 4; ks++) {
            int k = ks * 8;
            uint32_t a[4][4], bb[4][2];
            #pragma unroll
            for (int mt = 0; mt < 4; mt++) {
                int r0 = m0base + mt * 16 + g;
                a[mt][0] = tf32r(Ab[r0 * TSTRIDE + k + t4]);
                a[mt][1] = tf32r(Ab[(r0 + 8) * TSTRIDE + k + t4]);
                a[mt][2] = tf32r(Ab[r0 * TSTRIDE + k + t4 + 4]);
                a[mt][3] = tf32r(Ab[(r0 + 8) * TSTRIDE + k + t4 + 4]);
            }
            #pragma unroll
            for (int nt = 0; nt < 4; nt++) {
                int nr = n0base + nt * 8 + g;
                bb[nt][0] = tf32r(Bb[nr * TSTRIDE + k + t4]);
                bb[nt][1] = tf32r(Bb[nr * TSTRIDE + k + t4 + 4]);
            }
            #pragma unroll
            for (int mt = 0; mt < 4; mt++)
                #pragma unroll
                for (int nt = 0; nt < 4; nt++)
                    asm volatile(
                        "mma.sync.aligned.m16n8k8.row.col.f32.tf32.tf32.f32 "
                        "{%0,%1,%2,%3}, {%4,%5,%6,%7}, {%8,%9}, {%0,%1,%2,%3};"
                        : "+f"(acc[mt][nt][0]), "+f"(acc[mt][nt][1]),
                          "+f"(acc[mt][nt][2]), "+f"(acc[mt][nt][3])
                        : "r"(a[mt][0]), "r"(a[mt][1]), "r"(a[mt][2]), "r"(a[mt][3]),
                          "r"(bb[nt][0]), "r"(bb[nt][1]));
        }
        __syncthreads();
    }

    // ---- epilogue: fragment layout c0,c1 at (g, 2*t4), c2,c3 at (g+8, 2*t4) ----
    #pragma unroll
    for (int mt = 0; mt < 4; mt++) {
        size_t row = bm + m0base + mt * 16 + g;
        #pragma unroll
        for (int nt = 0; nt < 4; nt++) {
            size_t col = bn + n0base + nt * 8 + 2 * t4;
            *(float2*)&C[row * (size_t)ldc + col] =
                make_float2(acc[mt][nt][0], acc[mt][nt][1]);
            *(float2*)&C[(row + 8) * (size_t)ldc + col] =
                make_float2(acc[mt][nt][2], acc[mt][nt][3]);
        }
    }
}

// ---------------- RMSNorm + RoPE for Q and K heads ----------------
__global__ __launch_bounds__(64)
void norm_rope(const float* __restrict__ qkv,
               const float* __restrict__ cosb, const float* __restrict__ sinb,
               const float* __restrict__ qw, const float* __restrict__ kw,
               float* __restrict__ q, float* __restrict__ k)
{
    int tok = blockIdx.x;
    int h   = blockIdx.y;
    int i   = threadIdx.x;
    int b   = tok >> 11;
    int s   = tok & (SEQ - 1);

    const float* src = qkv + (size_t)tok * QKVD + h * HD;
    float x0 = src[2 * i];
    float x1 = src[2 * i + 1];

    float ss = x0 * x0 + x1 * x1;
    #pragma unroll
    for (int off = 16; off > 0; off >>= 1)
        ss += __shfl_xor_sync(0xFFFFFFFFu, ss, off);
    __shared__ float red[2];
    if ((i & 31) == 0) red[i >> 5] = ss;
    __syncthreads();
    float total = red[0] + red[1];

    float inv = rsqrtf(total * (1.0f / HD) + 1e-5f);
    const float* w = (h < NH) ? qw : kw;
    float y0 = x0 * inv * w[2 * i];
    float y1 = x1 * inv * w[2 * i + 1];

    float c  = cosb[(size_t)s * (HD / 2) + i];
    float sn = sinb[(size_t)s * (HD / 2) + i];
    float o0 = y0 * c - y1 * sn;
    float o1 = y0 * sn + y1 * c;

    float* dst;
    if (h < NH)  dst = q + ((size_t)(b * NH + h) * SEQ + s) * HD;
    else         dst = k + ((size_t)(b * NKV + (h - NH)) * SEQ + s) * HD;
    dst[2 * i]     = o0;
    dst[2 * i + 1] = o1;
}

// ---------------- V transpose ----------------
__global__ __launch_bounds__(256)
void vtrans(const float* __restrict__ qkv, float* __restrict__ vt)
{
    __shared__ float tile[32][33];
    int zz = blockIdx.z;
    int b  = zz >> 3;
    int kh = zz & 7;
    int s0 = blockIdx.x * 32;
    int d0 = blockIdx.y * 32;

    #pragma unroll
    for (int j = 0; j < 4; j++) {
        int s = s0 + threadIdx.y + j * 8;
        tile[threadIdx.y + j * 8][threadIdx.x] =
            qkv[((size_t)(b * SEQ + s)) * QKVD + (NH + NKV) * HD + kh * HD + d0 + threadIdx.x];
    }
    __syncthreads();
    #pragma unroll
    for (int j = 0; j < 4; j++) {
        int d = d0 + threadIdx.y + j * 8;
        vt[((size_t)zz * HD + d) * SEQ + s0 + threadIdx.x] =
            tile[threadIdx.x][threadIdx.y + j * 8];
    }
}

// ---------------- masked scaled softmax (in place) ----------------
__global__ __launch_bounds__(256)
void softmax_rows(float* __restrict__ sc, const int* __restrict__ mask, float scale)
{
    int qrow = blockIdx.x;
    int z    = blockIdx.y;
    int b    = z >> 4;
    float* row = sc + ((size_t)z * SEQ + qrow) * SEQ;
    const int* mrow = mask + (size_t)b * SEQ;

    int t = threadIdx.x;
    float v[8];
    float mx = -INFINITY;
    #pragma unroll
    for (int j = 0; j < 8; j++) {
        int kk = t + j * 256;
        float x = row[kk];
        x = mrow[kk] ? x * scale : -1e30f;
        v[j] = x;
        mx = fmaxf(mx, x);
    }
    __shared__ float smax[8];
    __shared__ float ssum[8];
    #pragma unroll
    for (int off = 16; off > 0; off >>= 1)
        mx = fmaxf(mx, __shfl_xor_sync(0xFFFFFFFFu, mx, off));
    if ((t & 31) == 0) smax[t >> 5] = mx;
    __syncthreads();
    float M = smax[0];
    #pragma unroll
    for (int w = 1; w < 8; w++) M = fmaxf(M, smax[w]);

    float s = 0.0f;
    #pragma unroll
    for (int j = 0; j < 8; j++) {
        float p = __expf(v[j] - M);
        v[j] = p;
        s += p;
    }
    #pragma unroll
    for (int off = 16; off > 0; off >>= 1)
        s += __shfl_xor_sync(0xFFFFFFFFu, s, off);
    if ((t & 31) == 0) ssum[t >> 5] = s;
    __syncthreads();
    float S = 0.0f;
    #pragma unroll
    for (int w = 0; w < 8; w++) S += ssum[w];
    float invS = 1.0f / S;

    #pragma unroll
    for (int j = 0; j < 8; j++)
        row[t + j * 256] = v[j] * invS;
}

// ---------------- launch ----------------
extern "C" void kernel_launch(void* const* d_in, const int* in_sizes, int n_in,
                              void* d_out, int out_size)
{
    const float* x     = (const float*)d_in[0];
    const int*   xmask = (const int*)  d_in[1];
    const float* fcos  = (const float*)d_in[2];
    const float* fsin  = (const float*)d_in[3];
    const float* Wqkv  = (const float*)d_in[4];
    const float* Wout  = (const float*)d_in[5];
    const float* qw    = (const float*)d_in[6];
    const float* kw    = (const float*)d_in[7];
    float* out = (float*)d_out;

    float *qkv, *q, *k, *vt, *sc, *att;
    cudaGetSymbolAddress((void**)&qkv, g_qkv);
    cudaGetSymbolAddress((void**)&q,   g_q);
    cudaGetSymbolAddress((void**)&k,   g_k);
    cudaGetSymbolAddress((void**)&vt,  g_vt);
    cudaGetSymbolAddress((void**)&sc,  g_sc);
    cudaGetSymbolAddress((void**)&att, g_att);

    cudaFuncSetAttribute(mma_gemm, cudaFuncAttributeMaxDynamicSharedMemorySize, SMEM_TOTAL);

    Off zo = {0, 0, 0, 0};

    // 1) qkv = x @ Wqkv^T : M=4096, N=4096, K=2048
    mma_gemm<<<dim3(QKVD / 128, NTOK / 128, 1), 256, SMEM_TOTAL>>>(
        x, Wqkv, qkv, DIM, DIM, DIM, QKVD, zo, zo, zo);

    // 2) RMSNorm + RoPE on Q,K
    norm_rope<<<dim3(NTOK, NH + NKV), 64>>>(qkv, fcos, fsin, qw, kw, q, k);

    // 3) V transpose
    vtrans<<<dim3(SEQ / 32, HD / 32, BSZ * NKV), dim3(32, 8)>>>(qkv, vt);

    // 4) scores[z] = Q[z] @ K[z>>1]^T : M=N=2048, K=128
    {
        Off oa = {0, (long long)SEQ * HD, 0, 0};
        Off ob = {1, (long long)SEQ * HD, 0, 0};
        Off oc = {0, (long long)SEQ * SEQ, 0, 0};
        mma_gemm<<<dim3(SEQ / 128, SEQ / 128, BSZ * NH), 256, SMEM_TOTAL>>>(
            q, k, sc, HD, HD, HD, SEQ, oa, ob, oc);
    }

    // 5) masked softmax (scale folded in)
    softmax_rows<<<dim3(SEQ, BSZ * NH), 256>>>(sc, xmask, rsqrtf((float)HD));

    // 6) att = P[z] @ Vt[z>>1]^T : M=2048, N=128, K=2048
    {
        Off oa = {0, (long long)SEQ * SEQ, 0, 0};
        Off ob = {1, (long long)HD * SEQ, 0, 0};
        Off oc = {4, (long long)SEQ * DIM, 15, (long long)HD};
        mma_gemm<<<dim3(1, SEQ / 128, BSZ * NH), 256, SMEM_TOTAL>>>(
            sc, vt, att, SEQ, SEQ, SEQ, DIM, oa, ob, oc);
    }

    // 7) out = att @ Wout^T : M=4096, N=2048, K=2048
    mma_gemm<<<dim3(DIM / 128, NTOK / 128, 1), 256, SMEM_TOTAL>>>(
        att, Wout, out, DIM, DIM, DIM, DIM, zo, zo, zo);
}

// round 4
// speedup vs baseline: 3.5496x; 1.3497x over previous
#include <cuda_runtime.h>
#include <cuda_bf16.h>
#include <math.h>
#include <stdint.h>

// Problem constants
#define BSZ 2
#define SEQ 2048
#define DIM 2048
#define NH 16
#define NKV 8
#define HD 128
#define QKVD 4096          // (16 + 2*8) * 128
#define NTOK (BSZ*SEQ)     // 4096

// ---------------- scratch (static __device__, no allocations) ----------------
static __device__ float g_qkv[(size_t)NTOK * QKVD];                  // 64 MB
static __device__ float g_q  [(size_t)BSZ * NH  * SEQ * HD];         // 32 MB
static __device__ float g_k  [(size_t)BSZ * NKV * SEQ * HD];         // 16 MB
static __device__ float g_vt [(size_t)BSZ * NKV * HD  * SEQ];        // 16 MB
static __device__ float g_sc [(size_t)BSZ * NH  * SEQ * SEQ];        // 512 MB
static __device__ float g_att[(size_t)NTOK * DIM];                   // 32 MB

// batching descriptor: per-z offset = (z>>sh)*stH + (z&mk)*stL
struct Off { int sh; long long stH; int mk; long long stL; };
__device__ __forceinline__ size_t offz(Off o, int z) {
    return (size_t)((long long)(z >> o.sh) * o.stH + (long long)(z & o.mk) * o.stL);
}

__device__ __forceinline__ uint32_t smem_u32(const void* p) {
    uint32_t a;
    asm("{ .reg .u64 t; cvta.to.shared.u64 t, %1; cvt.u32.u64 %0, t; }" : "=r"(a) : "l"(p));
    return a;
}

__device__ __forceinline__ void cpa16(uint32_t saddr, const void* g) {
    asm volatile("cp.async.cg.shared.global [%0], [%1], 16;" :: "r"(saddr), "l"(g));
}

// fp32 bits -> tf32 with round-to-nearest (add half-ULP of the 13 dropped bits)
__device__ __forceinline__ uint32_t tf32r(float f) { return __float_as_uint(f) + 0x1000u; }

// smem tile: 128 rows x 32 k, row stride 36 floats (conflict-free frag loads)
#define TSTRIDE 36
#define TFLOATS (128 * TSTRIDE)              // 4608 floats per tile buffer
#define STAGES 3
#define STAGE_FLOATS (2 * TFLOATS)           // A then B per stage
#define SMEM_TOTAL (STAGES * STAGE_FLOATS * 4)  // 110592 bytes

// ---------------- tensor-core TF32 batched GEMM: C[z] = A[z] * B[z]^T ----------------
// CTA tile 128x128, 8 warps (2m x 4n), warp tile 64x32, K chunk 32,
// 3-stage cp.async ring, 2 CTAs/SM.
__global__ __launch_bounds__(256, 2)
void mma_gemm(const float* __restrict__ A, const float* __restrict__ B, float* __restrict__ C,
              int K, int lda, int ldb, int ldc, Off oa, Off ob, Off oc)
{
    extern __shared__ float sm[];

    int tid = threadIdx.x;
    int wid = tid >> 5, lane = tid & 31;
    int g = lane >> 2, t4 = lane & 3;
    int wm = wid & 1, wn = wid >> 1;
    int m0base = wm * 64, n0base = wn * 32;

    int z = blockIdx.z;
    A += offz(oa, z); B += offz(ob, z); C += offz(oc, z);
    size_t bm = (size_t)blockIdx.y * 128;
    size_t bn = (size_t)blockIdx.x * 128;

    const int NC = K >> 5;

    float acc[4][4][4];
    #pragma unroll
    for (int i = 0; i < 4; i++)
        #pragma unroll
        for (int j = 0; j < 4; j++)
            #pragma unroll
            for (int r = 0; r < 4; r++) acc[i][j][r] = 0.0f;

    // per-thread load coords (8 threads per row-pair of the k-chunk)
    int lrow = tid >> 3;            // 0..31 base row (x4 iterations of 32)
    int lkc  = tid & 7;             // which 16B of the 32-wide k chunk
    uint32_t sbase = smem_u32(sm);

    auto load_chunk = [&](int c, int st) {
        const float* Ak = A + c * 32;
        const float* Bk = B + c * 32;
        uint32_t sA = sbase + (uint32_t)(st * STAGE_FLOATS) * 4;
        uint32_t sB = sA + TFLOATS * 4;
        #pragma unroll
        for (int i = 0; i < 4; i++) {
            int row = lrow + i * 32;
            uint32_t so = (uint32_t)(row * TSTRIDE + lkc * 4) * 4;
            cpa16(sA + so, Ak + (bm + row) * (size_t)lda + lkc * 4);
            cpa16(sB + so, Bk + (bn + row) * (size_t)ldb + lkc * 4);
        }
        asm volatile("cp.async.commit_group;" ::: "memory");
    };

    load_chunk(0, 0);
    if (NC > 1) load_chunk(1, 1);

    int st = 0;
    for (int c = 0; c < NC; c++) {
        if (c + 2 < NC) {
            load_chunk(c + 2, (st + 2) % STAGES);
            asm volatile("cp.async.wait_group 2;" ::: "memory");
        } else if (c + 1 < NC) {
            asm volatile("cp.async.wait_group 1;" ::: "memory");
        } else {
            asm volatile("cp.async.wait_group 0;" ::: "memory");
        }
        __syncthreads();

        const float* Ab = sm + st * STAGE_FLOATS;
        const float* Bb = Ab + TFLOATS;

        #pragma unroll
        for (int ks = 0; ks < 4; ks++) {
            int k = ks * 8;
            uint32_t bb[4][2];
            #pragma unroll
            for (int nt = 0; nt < 4; nt++) {
                const float* bp = Bb + (n0base + nt * 8 + g) * TSTRIDE + k + t4;
                bb[nt][0] = tf32r(bp[0]);
                bb[nt][1] = tf32r(bp[4]);
            }
            #pragma unroll
            for (int mt = 0; mt < 4; mt++) {
                const float* ap = Ab + (m0base + mt * 16 + g) * TSTRIDE + k + t4;
                uint32_t a0 = tf32r(ap[0]);
                uint32_t a1 = tf32r(ap[8 * TSTRIDE]);
                uint32_t a2 = tf32r(ap[4]);
                uint32_t a3 = tf32r(ap[8 * TSTRIDE + 4]);
                #pragma unroll
                for (int nt = 0; nt < 4; nt++)
                    asm volatile(
                        "mma.sync.aligned.m16n8k8.row.col.f32.tf32.tf32.f32 "
                        "{%0,%1,%2,%3}, {%4,%5,%6,%7}, {%8,%9}, {%0,%1,%2,%3};"
                        : "+f"(acc[mt][nt][0]), "+f"(acc[mt][nt][1]),
                          "+f"(acc[mt][nt][2]), "+f"(acc[mt][nt][3])
                        : "r"(a0), "r"(a1), "r"(a2), "r"(a3),
                          "r"(bb[nt][0]), "r"(bb[nt][1]));
            }
        }
        __syncthreads();
        st = (st + 1) % STAGES;
    }

    // ---- epilogue: fragment layout c0,c1 at (g, 2*t4), c2,c3 at (g+8, 2*t4) ----
    #pragma unroll
    for (int mt = 0; mt < 4; mt++) {
        size_t row = bm + m0base + mt * 16 + g;
        #pragma unroll
        for (int nt = 0; nt < 4; nt++) {
            size_t col = bn + n0base + nt * 8 + 2 * t4;
            *(float2*)&C[row * (size_t)ldc + col] =
                make_float2(acc[mt][nt][0], acc[mt][nt][1]);
            *(float2*)&C[(row + 8) * (size_t)ldc + col] =
                make_float2(acc[mt][nt][2], acc[mt][nt][3]);
        }
    }
}

// ---------------- RMSNorm + RoPE for Q and K heads ----------------
__global__ __launch_bounds__(64)
void norm_rope(const float* __restrict__ qkv,
               const float* __restrict__ cosb, const float* __restrict__ sinb,
               const float* __restrict__ qw, const float* __restrict__ kw,
               float* __restrict__ q, float* __restrict__ k)
{
    int tok = blockIdx.x;
    int h   = blockIdx.y;
    int i   = threadIdx.x;
    int b   = tok >> 11;
    int s   = tok & (SEQ - 1);

    const float* src = qkv + (size_t)tok * QKVD + h * HD;
    float x0 = src[2 * i];
    float x1 = src[2 * i + 1];

    float ss = x0 * x0 + x1 * x1;
    #pragma unroll
    for (int off = 16; off > 0; off >>= 1)
        ss += __shfl_xor_sync(0xFFFFFFFFu, ss, off);
    __shared__ float red[2];
    if ((i & 31) == 0) red[i >> 5] = ss;
    __syncthreads();
    float total = red[0] + red[1];

    float inv = rsqrtf(total * (1.0f / HD) + 1e-5f);
    const float* w = (h < NH) ? qw : kw;
    float y0 = x0 * inv * w[2 * i];
    float y1 = x1 * inv * w[2 * i + 1];

    float c  = cosb[(size_t)s * (HD / 2) + i];
    float sn = sinb[(size_t)s * (HD / 2) + i];
    float o0 = y0 * c - y1 * sn;
    float o1 = y0 * sn + y1 * c;

    float* dst;
    if (h < NH)  dst = q + ((size_t)(b * NH + h) * SEQ + s) * HD;
    else         dst = k + ((size_t)(b * NKV + (h - NH)) * SEQ + s) * HD;
    dst[2 * i]     = o0;
    dst[2 * i + 1] = o1;
}

// ---------------- V transpose ----------------
__global__ __launch_bounds__(256)
void vtrans(const float* __restrict__ qkv, float* __restrict__ vt)
{
    __shared__ float tile[32][33];
    int zz = blockIdx.z;
    int b  = zz >> 3;
    int kh = zz & 7;
    int s0 = blockIdx.x * 32;
    int d0 = blockIdx.y * 32;

    #pragma unroll
    for (int j = 0; j < 4; j++) {
        int s = s0 + threadIdx.y + j * 8;
        tile[threadIdx.y + j * 8][threadIdx.x] =
            qkv[((size_t)(b * SEQ + s)) * QKVD + (NH + NKV) * HD + kh * HD + d0 + threadIdx.x];
    }
    __syncthreads();
    #pragma unroll
    for (int j = 0; j < 4; j++) {
        int d = d0 + threadIdx.y + j * 8;
        vt[((size_t)zz * HD + d) * SEQ + s0 + threadIdx.x] =
            tile[threadIdx.x][threadIdx.y + j * 8];
    }
}

// ---------------- masked scaled softmax (in place) ----------------
__global__ __launch_bounds__(256)
void softmax_rows(float* __restrict__ sc, const int* __restrict__ mask, float scale)
{
    int qrow = blockIdx.x;
    int z    = blockIdx.y;
    int b    = z >> 4;
    float* row = sc + ((size_t)z * SEQ + qrow) * SEQ;
    const int* mrow = mask + (size_t)b * SEQ;

    int t = threadIdx.x;
    float v[8];
    float mx = -INFINITY;
    #pragma unroll
    for (int j = 0; j < 8; j++) {
        int kk = t + j * 256;
        float x = row[kk];
        x = mrow[kk] ? x * scale : -1e30f;
        v[j] = x;
        mx = fmaxf(mx, x);
    }
    __shared__ float smax[8];
    __shared__ float ssum[8];
    #pragma unroll
    for (int off = 16; off > 0; off >>= 1)
        mx = fmaxf(mx, __shfl_xor_sync(0xFFFFFFFFu, mx, off));
    if ((t & 31) == 0) smax[t >> 5] = mx;
    __syncthreads();
    float M = smax[0];
    #pragma unroll
    for (int w = 1; w < 8; w++) M = fmaxf(M, smax[w]);

    float s = 0.0f;
    #pragma unroll
    for (int j = 0; j < 8; j++) {
        float p = __expf(v[j] - M);
        v[j] = p;
        s += p;
    }
    #pragma unroll
    for (int off = 16; off > 0; off >>= 1)
        s += __shfl_xor_sync(0xFFFFFFFFu, s, off);
    if ((t & 31) == 0) ssum[t >> 5] = s;
    __syncthreads();
    float S = 0.0f;
    #pragma unroll
    for (int w = 0; w < 8; w++) S += ssum[w];
    float invS = 1.0f / S;

    #pragma unroll
    for (int j = 0; j < 8; j++)
        row[t + j * 256] = v[j] * invS;
}

// ---------------- launch ----------------
extern "C" void kernel_launch(void* const* d_in, const int* in_sizes, int n_in,
                              void* d_out, int out_size)
{
    const float* x     = (const float*)d_in[0];
    const int*   xmask = (const int*)  d_in[1];
    const float* fcos  = (const float*)d_in[2];
    const float* fsin  = (const float*)d_in[3];
    const float* Wqkv  = (const float*)d_in[4];
    const float* Wout  = (const float*)d_in[5];
    const float* qw    = (const float*)d_in[6];
    const float* kw    = (const float*)d_in[7];
    float* out = (float*)d_out;

    float *qkv, *q, *k, *vt, *sc, *att;
    cudaGetSymbolAddress((void**)&qkv, g_qkv);
    cudaGetSymbolAddress((void**)&q,   g_q);
    cudaGetSymbolAddress((void**)&k,   g_k);
    cudaGetSymbolAddress((void**)&vt,  g_vt);
    cudaGetSymbolAddress((void**)&sc,  g_sc);
    cudaGetSymbolAddress((void**)&att, g_att);

    cudaFuncSetAttribute(mma_gemm, cudaFuncAttributeMaxDynamicSharedMemorySize, SMEM_TOTAL);

    Off zo = {0, 0, 0, 0};

    // 1) qkv = x @ Wqkv^T : M=4096, N=4096, K=2048
    mma_gemm<<<dim3(QKVD / 128, NTOK / 128, 1), 256, SMEM_TOTAL>>>(
        x, Wqkv, qkv, DIM, DIM, DIM, QKVD, zo, zo, zo);

    // 2) RMSNorm + RoPE on Q,K
    norm_rope<<<dim3(NTOK, NH + NKV), 64>>>(qkv, fcos, fsin, qw, kw, q, k);

    // 3) V transpose
    vtrans<<<dim3(SEQ / 32, HD / 32, BSZ * NKV), dim3(32, 8)>>>(qkv, vt);

    // 4) scores[z] = Q[z] @ K[z>>1]^T : M=N=2048, K=128
    {
        Off oa = {0, (long long)SEQ * HD, 0, 0};
        Off ob = {1, (long long)SEQ * HD, 0, 0};
        Off oc = {0, (long long)SEQ * SEQ, 0, 0};
        mma_gemm<<<dim3(SEQ / 128, SEQ / 128, BSZ * NH), 256, SMEM_TOTAL>>>(
            q, k, sc, HD, HD, HD, SEQ, oa, ob, oc);
    }

    // 5) masked softmax (scale folded in)
    softmax_rows<<<dim3(SEQ, BSZ * NH), 256>>>(sc, xmask, rsqrtf((float)HD));

    // 6) att = P[z] @ Vt[z>>1]^T : M=2048, N=128, K=2048
    {
        Off oa = {0, (long long)SEQ * SEQ, 0, 0};
        Off ob = {1, (long long)HD * SEQ, 0, 0};
        Off oc = {4, (long long)SEQ * DIM, 15, (long long)HD};
        mma_gemm<<<dim3(1, SEQ / 128, BSZ * NH), 256, SMEM_TOTAL>>>(
            sc, vt, att, SEQ, SEQ, SEQ, DIM, oa, ob, oc);
    }

    // 7) out = att @ Wout^T : M=4096, N=2048, K=2048
    mma_gemm<<<dim3(DIM / 128, NTOK / 128, 1), 256, SMEM_TOTAL>>>(
        att, Wout, out, DIM, DIM, DIM, DIM, zo, zo, zo);
}

// round 5
// speedup vs baseline: 3.8337x; 1.0800x over previous
#include <cuda_runtime.h>
#include <cuda_bf16.h>
#include <math.h>
#include <stdint.h>

// Problem constants
#define BSZ 2
#define SEQ 2048
#define DIM 2048
#define NH 16
#define NKV 8
#define HD 128
#define QKVD 4096          // (16 + 2*8) * 128
#define NTOK (BSZ*SEQ)     // 4096

// ---------------- scratch (static __device__, no allocations) ----------------
static __device__ float g_qkv[(size_t)NTOK * QKVD];                  // 64 MB
static __device__ float g_q  [(size_t)BSZ * NH  * SEQ * HD];         // 32 MB
static __device__ float g_k  [(size_t)BSZ * NKV * SEQ * HD];         // 16 MB
static __device__ float g_vt [(size_t)BSZ * NKV * HD  * SEQ];        // 16 MB
static __device__ float g_sc [(size_t)BSZ * NH  * SEQ * SEQ];        // 512 MB (unnormalized P)
static __device__ float g_att[(size_t)NTOK * DIM];                   // 32 MB
static __device__ float g_part[(size_t)BSZ * NH * SEQ * 16];         // 4 MB row partials
static __device__ float g_rinv[(size_t)BSZ * NH * SEQ];              // 256 KB reciprocal row sums

// batching descriptor: per-z offset = (z>>sh)*stH + (z&mk)*stL
struct Off { int sh; long long stH; int mk; long long stL; };
__device__ __forceinline__ size_t offz(Off o, int z) {
    return (size_t)((long long)(z >> o.sh) * o.stH + (long long)(z & o.mk) * o.stL);
}

__device__ __forceinline__ uint32_t smem_u32(const void* p) {
    uint32_t a;
    asm("{ .reg .u64 t; cvta.to.shared.u64 t, %1; cvt.u32.u64 %0, t; }" : "=r"(a) : "l"(p));
    return a;
}

__device__ __forceinline__ void cpa16(uint32_t saddr, const void* g) {
    asm volatile("cp.async.cg.shared.global [%0], [%1], 16;" :: "r"(saddr), "l"(g));
}

// fp32 bits -> tf32 with round-to-nearest (add half-ULP of the 13 dropped bits)
__device__ __forceinline__ uint32_t tf32r(float f) { return __float_as_uint(f) + 0x1000u; }

// smem tile: 128 rows x 32 k, row stride 36 floats (conflict-free frag loads)
#define TSTRIDE 36
#define TFLOATS (128 * TSTRIDE)              // 4608 floats per tile buffer
#define STAGES 3
#define STAGE_FLOATS (2 * TFLOATS)           // A then B per stage
#define SMEM_TOTAL (STAGES * STAGE_FLOATS * 4)  // 110592 bytes

#define EPI_NONE 0
#define EPI_EXP  1
#define EPI_DIV  2

// ---------------- tensor-core TF32 batched GEMM: C[z] = A[z] * B[z]^T ----------------
// CTA tile 128x128, 8 warps (2m x 4n), warp tile 64x32, K chunk 32,
// 3-stage cp.async ring (single __syncthreads per chunk), 2 CTAs/SM.
// EPI_EXP: C = exp(acc*scale)*mask, emit per-CTA row partial sums.
// EPI_DIV: C = acc * rinv[row].
template<int EPI>
__global__ __launch_bounds__(256, 2)
void mma_gemm(const float* __restrict__ A, const float* __restrict__ B, float* __restrict__ C,
              int K, int lda, int ldb, int ldc, Off oa, Off ob, Off oc,
              const int* __restrict__ mask, float scale,
              float* __restrict__ part, const float* __restrict__ rinv)
{
    extern __shared__ float sm[];

    int tid = threadIdx.x;
    int wid = tid >> 5, lane = tid & 31;
    int g = lane >> 2, t4 = lane & 3;
    int wm = wid & 1, wn = wid >> 1;
    int m0base = wm * 64, n0base = wn * 32;

    int z = blockIdx.z;
    A += offz(oa, z); B += offz(ob, z); C += offz(oc, z);
    size_t bm = (size_t)blockIdx.y * 128;
    size_t bn = (size_t)blockIdx.x * 128;

    const int NC = K >> 5;

    float acc[4][4][4];
    #pragma unroll
    for (int i = 0; i < 4; i++)
        #pragma unroll
        for (int j = 0; j < 4; j++)
            #pragma unroll
            for (int r = 0; r < 4; r++) acc[i][j][r] = 0.0f;

    int lrow = tid >> 3;            // 0..31 base row (x4 iterations of 32)
    int lkc  = tid & 7;             // which 16B of the 32-wide k chunk
    uint32_t sbase = smem_u32(sm);

    auto load_chunk = [&](int c, int st) {
        const float* Ak = A + c * 32;
        const float* Bk = B + c * 32;
        uint32_t sA = sbase + (uint32_t)(st * STAGE_FLOATS) * 4;
        uint32_t sB = sA + TFLOATS * 4;
        #pragma unroll
        for (int i = 0; i < 4; i++) {
            int row = lrow + i * 32;
            uint32_t so = (uint32_t)(row * TSTRIDE + lkc * 4) * 4;
            cpa16(sA + so, Ak + (bm + row) * (size_t)lda + lkc * 4);
            cpa16(sB + so, Bk + (bn + row) * (size_t)ldb + lkc * 4);
        }
        asm volatile("cp.async.commit_group;" ::: "memory");
    };

    load_chunk(0, 0);
    if (NC > 1) load_chunk(1, 1);

    int st = 0;
    for (int c = 0; c < NC; c++) {
        if (c + 1 < NC)
            asm volatile("cp.async.wait_group 1;" ::: "memory");
        else
            asm volatile("cp.async.wait_group 0;" ::: "memory");
        __syncthreads();   // chunk c visible to all; all warps done reading stage (st+2)%3

        if (c + 2 < NC) load_chunk(c + 2, (st + 2) % STAGES);

        const float* Ab = sm + st * STAGE_FLOATS;
        const float* Bb = Ab + TFLOATS;

        #pragma unroll
        for (int ks = 0; ks < 4; ks++) {
            int k = ks * 8;
            uint32_t bb[4][2];
            #pragma unroll
            for (int nt = 0; nt < 4; nt++) {
                const float* bp = Bb + (n0base + nt * 8 + g) * TSTRIDE + k + t4;
                bb[nt][0] = tf32r(bp[0]);
                bb[nt][1] = tf32r(bp[4]);
            }
            #pragma unroll
            for (int mt = 0; mt < 4; mt++) {
                const float* ap = Ab + (m0base + mt * 16 + g) * TSTRIDE + k + t4;
                uint32_t a0 = tf32r(ap[0]);
                uint32_t a1 = tf32r(ap[8 * TSTRIDE]);
                uint32_t a2 = tf32r(ap[4]);
                uint32_t a3 = tf32r(ap[8 * TSTRIDE + 4]);
                #pragma unroll
                for (int nt = 0; nt < 4; nt++)
                    asm volatile(
                        "mma.sync.aligned.m16n8k8.row.col.f32.tf32.tf32.f32 "
                        "{%0,%1,%2,%3}, {%4,%5,%6,%7}, {%8,%9}, {%0,%1,%2,%3};"
                        : "+f"(acc[mt][nt][0]), "+f"(acc[mt][nt][1]),
                          "+f"(acc[mt][nt][2]), "+f"(acc[mt][nt][3])
                        : "r"(a0), "r"(a1), "r"(a2), "r"(a3),
                          "r"(bb[nt][0]), "r"(bb[nt][1]));
            }
        }
        st = (st + 1) % STAGES;
    }

    // ---- epilogue transforms ----
    float rs[4][2];
    if (EPI == EPI_EXP) {
        const int* mrow = mask + ((size_t)(z >> 4)) * SEQ + bn;
        #pragma unroll
        for (int mt = 0; mt < 4; mt++) { rs[mt][0] = 0.0f; rs[mt][1] = 0.0f; }
        #pragma unroll
        for (int nt = 0; nt < 4; nt++) {
            int c0 = n0base + nt * 8 + 2 * t4;
            float m0 = mrow[c0]     ? 1.0f : 0.0f;
            float m1 = mrow[c0 + 1] ? 1.0f : 0.0f;
            #pragma unroll
            for (int mt = 0; mt < 4; mt++) {
                float e0 = __expf(acc[mt][nt][0] * scale) * m0;
                float e1 = __expf(acc[mt][nt][1] * scale) * m1;
                float e2 = __expf(acc[mt][nt][2] * scale) * m0;
                float e3 = __expf(acc[mt][nt][3] * scale) * m1;
                acc[mt][nt][0] = e0; acc[mt][nt][1] = e1;
                acc[mt][nt][2] = e2; acc[mt][nt][3] = e3;
                rs[mt][0] += e0 + e1;
                rs[mt][1] += e2 + e3;
            }
        }
        // quad reduce over t4 (lane bits 0..1): full 32-col slice per row
        #pragma unroll
        for (int mt = 0; mt < 4; mt++) {
            rs[mt][0] += __shfl_xor_sync(0xFFFFFFFFu, rs[mt][0], 1);
            rs[mt][0] += __shfl_xor_sync(0xFFFFFFFFu, rs[mt][0], 2);
            rs[mt][1] += __shfl_xor_sync(0xFFFFFFFFu, rs[mt][1], 1);
            rs[mt][1] += __shfl_xor_sync(0xFFFFFFFFu, rs[mt][1], 2);
        }
    } else if (EPI == EPI_DIV) {
        const float* rz = rinv + (size_t)z * SEQ + bm;
        #pragma unroll
        for (int mt = 0; mt < 4; mt++) {
            float i0 = rz[m0base + mt * 16 + g];
            float i1 = rz[m0base + mt * 16 + g + 8];
            #pragma unroll
            for (int nt = 0; nt < 4; nt++) {
                acc[mt][nt][0] *= i0; acc[mt][nt][1] *= i0;
                acc[mt][nt][2] *= i1; acc[mt][nt][3] *= i1;
            }
        }
    }

    // ---- store C ----
    #pragma unroll
    for (int mt = 0; mt < 4; mt++) {
        size_t row = bm + m0base + mt * 16 + g;
        #pragma unroll
        for (int nt = 0; nt < 4; nt++) {
            size_t col = bn + n0base + nt * 8 + 2 * t4;
            *(float2*)&C[row * (size_t)ldc + col] =
                make_float2(acc[mt][nt][0], acc[mt][nt][1]);
            *(float2*)&C[(row + 8) * (size_t)ldc + col] =
                make_float2(acc[mt][nt][2], acc[mt][nt][3]);
        }
    }

    if (EPI == EPI_EXP) {
        // cross-warp (wn) reduce via smem, then one partial per row per CTA
        __syncthreads();               // tiles no longer needed; reuse smem
        float* rsred = sm;             // [128][4]
        if (t4 == 0) {
            #pragma unroll
            for (int mt = 0; mt < 4; mt++) {
                rsred[(m0base + mt * 16 + g) * 4 + wn]     = rs[mt][0];
                rsred[(m0base + mt * 16 + g + 8) * 4 + wn] = rs[mt][1];
            }
        }
        __syncthreads();
        if (tid < 128) {
            float s = rsred[tid * 4] + rsred[tid * 4 + 1] +
                      rsred[tid * 4 + 2] + rsred[tid * 4 + 3];
            part[((size_t)z * SEQ + bm + tid) * 16 + blockIdx.x] = s;
        }
    }
}

// ---------------- rowsum reduce: rinv = 1/sum(partials) ----------------
__global__ __launch_bounds__(256)
void rowsum_reduce(const float* __restrict__ part, float* __restrict__ rinv)
{
    int i = blockIdx.x * 256 + threadIdx.x;     // 0..65535
    const float* p = part + (size_t)i * 16;
    float s = 0.0f;
    #pragma unroll
    for (int j = 0; j < 16; j++) s += p[j];
    rinv[i] = (s > 0.0f) ? (1.0f / s) : 0.0f;
}

// ---------------- RMSNorm + RoPE for Q and K heads ----------------
__global__ __launch_bounds__(64)
void norm_rope(const float* __restrict__ qkv,
               const float* __restrict__ cosb, const float* __restrict__ sinb,
               const float* __restrict__ qw, const float* __restrict__ kw,
               float* __restrict__ q, float* __restrict__ k)
{
    int tok = blockIdx.x;
    int h   = blockIdx.y;
    int i   = threadIdx.x;
    int b   = tok >> 11;
    int s   = tok & (SEQ - 1);

    const float* src = qkv + (size_t)tok * QKVD + h * HD;
    float x0 = src[2 * i];
    float x1 = src[2 * i + 1];

    float ss = x0 * x0 + x1 * x1;
    #pragma unroll
    for (int off = 16; off > 0; off >>= 1)
        ss += __shfl_xor_sync(0xFFFFFFFFu, ss, off);
    __shared__ float red[2];
    if ((i & 31) == 0) red[i >> 5] = ss;
    __syncthreads();
    float total = red[0] + red[1];

    float inv = rsqrtf(total * (1.0f / HD) + 1e-5f);
    const float* w = (h < NH) ? qw : kw;
    float y0 = x0 * inv * w[2 * i];
    float y1 = x1 * inv * w[2 * i + 1];

    float c  = cosb[(size_t)s * (HD / 2) + i];
    float sn = sinb[(size_t)s * (HD / 2) + i];
    float o0 = y0 * c - y1 * sn;
    float o1 = y0 * sn + y1 * c;

    float* dst;
    if (h < NH)  dst = q + ((size_t)(b * NH + h) * SEQ + s) * HD;
    else         dst = k + ((size_t)(b * NKV + (h - NH)) * SEQ + s) * HD;
    dst[2 * i]     = o0;
    dst[2 * i + 1] = o1;
}

// ---------------- V transpose ----------------
__global__ __launch_bounds__(256)
void vtrans(const float* __restrict__ qkv, float* __restrict__ vt)
{
    __shared__ float tile[32][33];
    int zz = blockIdx.z;
    int b  = zz >> 3;
    int kh = zz & 7;
    int s0 = blockIdx.x * 32;
    int d0 = blockIdx.y * 32;

    #pragma unroll
    for (int j = 0; j < 4; j++) {
        int s = s0 + threadIdx.y + j * 8;
        tile[threadIdx.y + j * 8][threadIdx.x] =
            qkv[((size_t)(b * SEQ + s)) * QKVD + (NH + NKV) * HD + kh * HD + d0 + threadIdx.x];
    }
    __syncthreads();
    #pragma unroll
    for (int j = 0; j < 4; j++) {
        int d = d0 + threadIdx.y + j * 8;
        vt[((size_t)zz * HD + d) * SEQ + s0 + threadIdx.x] =
            tile[threadIdx.x][threadIdx.y + j * 8];
    }
}

// ---------------- launch ----------------
extern "C" void kernel_launch(void* const* d_in, const int* in_sizes, int n_in,
                              void* d_out, int out_size)
{
    const float* x     = (const float*)d_in[0];
    const int*   xmask = (const int*)  d_in[1];
    const float* fcos  = (const float*)d_in[2];
    const float* fsin  = (const float*)d_in[3];
    const float* Wqkv  = (const float*)d_in[4];
    const float* Wout  = (const float*)d_in[5];
    const float* qw    = (const float*)d_in[6];
    const float* kw    = (const float*)d_in[7];
    float* out = (float*)d_out;

    float *qkv, *q, *k, *vt, *sc, *att, *part, *rinv;
    cudaGetSymbolAddress((void**)&qkv,  g_qkv);
    cudaGetSymbolAddress((void**)&q,    g_q);
    cudaGetSymbolAddress((void**)&k,    g_k);
    cudaGetSymbolAddress((void**)&vt,   g_vt);
    cudaGetSymbolAddress((void**)&sc,   g_sc);
    cudaGetSymbolAddress((void**)&att,  g_att);
    cudaGetSymbolAddress((void**)&part, g_part);
    cudaGetSymbolAddress((void**)&rinv, g_rinv);

    cudaFuncSetAttribute(mma_gemm<EPI_NONE>, cudaFuncAttributeMaxDynamicSharedMemorySize, SMEM_TOTAL);
    cudaFuncSetAttribute(mma_gemm<EPI_EXP>,  cudaFuncAttributeMaxDynamicSharedMemorySize, SMEM_TOTAL);
    cudaFuncSetAttribute(mma_gemm<EPI_DIV>,  cudaFuncAttributeMaxDynamicSharedMemorySize, SMEM_TOTAL);

    Off zo = {0, 0, 0, 0};
    float scale = rsqrtf((float)HD);

    // 1) qkv = x @ Wqkv^T : M=4096, N=4096, K=2048
    mma_gemm<EPI_NONE><<<dim3(QKVD / 128, NTOK / 128, 1), 256, SMEM_TOTAL>>>(
        x, Wqkv, qkv, DIM, DIM, DIM, QKVD, zo, zo, zo, nullptr, 0.f, nullptr, nullptr);

    // 2) RMSNorm + RoPE on Q,K
    norm_rope<<<dim3(NTOK, NH + NKV), 64>>>(qkv, fcos, fsin, qw, kw, q, k);

    // 3) V transpose
    vtrans<<<dim3(SEQ / 32, HD / 32, BSZ * NKV), dim3(32, 8)>>>(qkv, vt);

    // 4) P = exp(scale * Q[z] @ K[z>>1]^T) * mask, + row partial sums
    {
        Off oa = {0, (long long)SEQ * HD, 0, 0};
        Off ob = {1, (long long)SEQ * HD, 0, 0};
        Off oc = {0, (long long)SEQ * SEQ, 0, 0};
        mma_gemm<EPI_EXP><<<dim3(SEQ / 128, SEQ / 128, BSZ * NH), 256, SMEM_TOTAL>>>(
            q, k, sc, HD, HD, HD, SEQ, oa, ob, oc, xmask, scale, part, nullptr);
    }

    // 5) rinv = 1 / rowsum
    rowsum_reduce<<<(BSZ * NH * SEQ) / 256, 256>>>(part, rinv);

    // 6) att = (P[z] @ Vt[z>>1]^T) * rinv : M=2048, N=128, K=2048
    {
        Off oa = {0, (long long)SEQ * SEQ, 0, 0};
        Off ob = {1, (long long)HD * SEQ, 0, 0};
        Off oc = {4, (long long)SEQ * DIM, 15, (long long)HD};
        mma_gemm<EPI_DIV><<<dim3(1, SEQ / 128, BSZ * NH), 256, SMEM_TOTAL>>>(
            sc, vt, att, SEQ, SEQ, SEQ, DIM, oa, ob, oc, nullptr, 0.f, nullptr, rinv);
    }

    // 7) out = att @ Wout^T : M=4096, N=2048, K=2048
    mma_gemm<EPI_NONE><<<dim3(DIM / 128, NTOK / 128, 1), 256, SMEM_TOTAL>>>(
        att, Wout, out, DIM, DIM, DIM, DIM, zo, zo, zo, nullptr, 0.f, nullptr, nullptr);
}

// round 6
// speedup vs baseline: 3.8567x; 1.0060x over previous
#include <cuda_runtime.h>
#include <cuda_bf16.h>
#include <math.h>
#include <stdint.h>

// Problem constants
#define BSZ 2
#define SEQ 2048
#define DIM 2048
#define NH 16
#define NKV 8
#define HD 128
#define QKVD 4096          // (16 + 2*8) * 128
#define NTOK (BSZ*SEQ)     // 4096

// ---------------- scratch (static __device__, no allocations) ----------------
static __device__ float g_qkv[(size_t)NTOK * QKVD];                  // 64 MB
static __device__ float g_q  [(size_t)BSZ * NH  * SEQ * HD];         // 32 MB (tf32-rounded)
static __device__ float g_k  [(size_t)BSZ * NKV * SEQ * HD];         // 16 MB (tf32-rounded)
static __device__ float g_vt [(size_t)BSZ * NKV * HD  * SEQ];        // 16 MB (tf32-rounded)
static __device__ float g_sc [(size_t)BSZ * NH  * SEQ * SEQ];        // 512 MB (P, tf32-rounded)
static __device__ float g_att[(size_t)NTOK * DIM];                   // 32 MB (tf32-rounded)
static __device__ float g_part[(size_t)BSZ * NH * SEQ * 16];         // 4 MB row partials
static __device__ float g_rinv[(size_t)BSZ * NH * SEQ];              // 256 KB reciprocal row sums
static __device__ float g_xr [(size_t)NTOK * DIM];                   // 32 MB rounded x
static __device__ float g_wq [(size_t)QKVD * DIM];                   // 32 MB rounded Wqkv
static __device__ float g_wo [(size_t)DIM * DIM];                    // 16 MB rounded Wout

// batching descriptor: per-z offset = (z>>sh)*stH + (z&mk)*stL
struct Off { int sh; long long stH; int mk; long long stL; };
__device__ __forceinline__ size_t offz(Off o, int z) {
    return (size_t)((long long)(z >> o.sh) * o.stH + (long long)(z & o.mk) * o.stL);
}

__device__ __forceinline__ uint32_t smem_u32(const void* p) {
    uint32_t a;
    asm("{ .reg .u64 t; cvta.to.shared.u64 t, %1; cvt.u32.u64 %0, t; }" : "=r"(a) : "l"(p));
    return a;
}

__device__ __forceinline__ void cpa16(uint32_t saddr, const void* g) {
    asm volatile("cp.async.cg.shared.global [%0], [%1], 16;" :: "r"(saddr), "l"(g));
}

// fp32 bits -> tf32 round-to-nearest bits (HW keeps high 19 bits; pre-bias bit 12)
__device__ __forceinline__ uint32_t tf32r(float f) { return __float_as_uint(f) + 0x1000u; }
__device__ __forceinline__ float tf32rf(float f) { return __uint_as_float(__float_as_uint(f) + 0x1000u); }

// smem tile: 128 rows x 32 k, row stride 36 floats (conflict-free frag loads)
#define TSTRIDE 36
#define TFLOATS (128 * TSTRIDE)              // 4608 floats per tile buffer
#define STAGES 3
#define STAGE_FLOATS (2 * TFLOATS)           // A then B per stage
#define SMEM_TOTAL (STAGES * STAGE_FLOATS * 4)  // 110592 bytes

#define EPI_NONE 0
#define EPI_EXP  1
#define EPI_DIV  2

// ---------------- tensor-core TF32 batched GEMM: C[z] = A[z] * B[z]^T ----------------
// Operands must be PRE-ROUNDED to tf32 bits. CTA tile 128x128, 8 warps (2m x 4n),
// warp tile 64x32, K chunk 32, 3-stage cp.async ring, 2 CTAs/SM.
// EPI_EXP: C = tf32(exp(acc*scale)*mask), emit per-CTA row partial sums (unrounded).
// EPI_DIV: C = tf32(acc * rinv[row]).
template<int EPI>
__global__ __launch_bounds__(256, 2)
void mma_gemm(const float* __restrict__ A, const float* __restrict__ B, float* __restrict__ C,
              int K, int lda, int ldb, int ldc, Off oa, Off ob, Off oc,
              const int* __restrict__ mask, float scale,
              float* __restrict__ part, const float* __restrict__ rinv)
{
    extern __shared__ float sm[];

    int tid = threadIdx.x;
    int wid = tid >> 5, lane = tid & 31;
    int g = lane >> 2, t4 = lane & 3;
    int wm = wid & 1, wn = wid >> 1;
    int m0base = wm * 64, n0base = wn * 32;

    int z = blockIdx.z;
    A += offz(oa, z); B += offz(ob, z); C += offz(oc, z);
    size_t bm = (size_t)blockIdx.y * 128;
    size_t bn = (size_t)blockIdx.x * 128;

    const int NC = K >> 5;

    float acc[4][4][4];
    #pragma unroll
    for (int i = 0; i < 4; i++)
        #pragma unroll
        for (int j = 0; j < 4; j++)
            #pragma unroll
            for (int r = 0; r < 4; r++) acc[i][j][r] = 0.0f;

    int lrow = tid >> 3;            // 0..31 base row (x4 iterations of 32)
    int lkc  = tid & 7;             // which 16B of the 32-wide k chunk
    uint32_t sbase = smem_u32(sm);

    auto load_chunk = [&](int c, int st) {
        const float* Ak = A + c * 32;
        const float* Bk = B + c * 32;
        uint32_t sA = sbase + (uint32_t)(st * STAGE_FLOATS) * 4;
        uint32_t sB = sA + TFLOATS * 4;
        #pragma unroll
        for (int i = 0; i < 4; i++) {
            int row = lrow + i * 32;
            uint32_t so = (uint32_t)(row * TSTRIDE + lkc * 4) * 4;
            cpa16(sA + so, Ak + (bm + row) * (size_t)lda + lkc * 4);
            cpa16(sB + so, Bk + (bn + row) * (size_t)ldb + lkc * 4);
        }
        asm volatile("cp.async.commit_group;" ::: "memory");
    };

    load_chunk(0, 0);
    if (NC > 1) load_chunk(1, 1);

    int st = 0;
    for (int c = 0; c < NC; c++) {
        if (c + 1 < NC)
            asm volatile("cp.async.wait_group 1;" ::: "memory");
        else
            asm volatile("cp.async.wait_group 0;" ::: "memory");
        __syncthreads();   // chunk c visible; all warps done reading stage (st+2)%3

        if (c + 2 < NC) load_chunk(c + 2, (st + 2) % STAGES);

        const uint32_t* Ab = (const uint32_t*)(sm + st * STAGE_FLOATS);
        const uint32_t* Bb = Ab + TFLOATS;

        #pragma unroll
        for (int ks = 0; ks < 4; ks++) {
            int k = ks * 8;
            uint32_t bb[4][2];
            #pragma unroll
            for (int nt = 0; nt < 4; nt++) {
                const uint32_t* bp = Bb + (n0base + nt * 8 + g) * TSTRIDE + k + t4;
                bb[nt][0] = bp[0];
                bb[nt][1] = bp[4];
            }
            #pragma unroll
            for (int mt = 0; mt < 4; mt++) {
                const uint32_t* ap = Ab + (m0base + mt * 16 + g) * TSTRIDE + k + t4;
                uint32_t a0 = ap[0];
                uint32_t a1 = ap[8 * TSTRIDE];
                uint32_t a2 = ap[4];
                uint32_t a3 = ap[8 * TSTRIDE + 4];
                #pragma unroll
                for (int nt = 0; nt < 4; nt++)
                    asm volatile(
                        "mma.sync.aligned.m16n8k8.row.col.f32.tf32.tf32.f32 "
                        "{%0,%1,%2,%3}, {%4,%5,%6,%7}, {%8,%9}, {%0,%1,%2,%3};"
                        : "+f"(acc[mt][nt][0]), "+f"(acc[mt][nt][1]),
                          "+f"(acc[mt][nt][2]), "+f"(acc[mt][nt][3])
                        : "r"(a0), "r"(a1), "r"(a2), "r"(a3),
                          "r"(bb[nt][0]), "r"(bb[nt][1]));
            }
        }
        st = (st + 1) % STAGES;
    }

    // ---- epilogue transforms ----
    float rs[4][2];
    if (EPI == EPI_EXP) {
        const int* mrow = mask + ((size_t)(z >> 4)) * SEQ + bn;
        #pragma unroll
        for (int mt = 0; mt < 4; mt++) { rs[mt][0] = 0.0f; rs[mt][1] = 0.0f; }
        #pragma unroll
        for (int nt = 0; nt < 4; nt++) {
            int c0 = n0base + nt * 8 + 2 * t4;
            float m0 = mrow[c0]     ? 1.0f : 0.0f;
            float m1 = mrow[c0 + 1] ? 1.0f : 0.0f;
            #pragma unroll
            for (int mt = 0; mt < 4; mt++) {
                float e0 = __expf(acc[mt][nt][0] * scale) * m0;
                float e1 = __expf(acc[mt][nt][1] * scale) * m1;
                float e2 = __expf(acc[mt][nt][2] * scale) * m0;
                float e3 = __expf(acc[mt][nt][3] * scale) * m1;
                acc[mt][nt][0] = e0; acc[mt][nt][1] = e1;
                acc[mt][nt][2] = e2; acc[mt][nt][3] = e3;
                rs[mt][0] += e0 + e1;
                rs[mt][1] += e2 + e3;
            }
        }
        #pragma unroll
        for (int mt = 0; mt < 4; mt++) {
            rs[mt][0] += __shfl_xor_sync(0xFFFFFFFFu, rs[mt][0], 1);
            rs[mt][0] += __shfl_xor_sync(0xFFFFFFFFu, rs[mt][0], 2);
            rs[mt][1] += __shfl_xor_sync(0xFFFFFFFFu, rs[mt][1], 1);
            rs[mt][1] += __shfl_xor_sync(0xFFFFFFFFu, rs[mt][1], 2);
        }
    } else if (EPI == EPI_DIV) {
        const float* rz = rinv + (size_t)z * SEQ + bm;
        #pragma unroll
        for (int mt = 0; mt < 4; mt++) {
            float i0 = rz[m0base + mt * 16 + g];
            float i1 = rz[m0base + mt * 16 + g + 8];
            #pragma unroll
            for (int nt = 0; nt < 4; nt++) {
                acc[mt][nt][0] *= i0; acc[mt][nt][1] *= i0;
                acc[mt][nt][2] *= i1; acc[mt][nt][3] *= i1;
            }
        }
    }

    // ---- store C (EXP/DIV outputs feed later GEMMs -> store tf32-rounded) ----
    #pragma unroll
    for (int mt = 0; mt < 4; mt++) {
        size_t row = bm + m0base + mt * 16 + g;
        #pragma unroll
        for (int nt = 0; nt < 4; nt++) {
            size_t col = bn + n0base + nt * 8 + 2 * t4;
            if (EPI == EPI_NONE) {
                *(float2*)&C[row * (size_t)ldc + col] =
                    make_float2(acc[mt][nt][0], acc[mt][nt][1]);
                *(float2*)&C[(row + 8) * (size_t)ldc + col] =
                    make_float2(acc[mt][nt][2], acc[mt][nt][3]);
            } else {
                uint2 v0 = { tf32r(acc[mt][nt][0]), tf32r(acc[mt][nt][1]) };
                uint2 v1 = { tf32r(acc[mt][nt][2]), tf32r(acc[mt][nt][3]) };
                *(uint2*)&C[row * (size_t)ldc + col] = v0;
                *(uint2*)&C[(row + 8) * (size_t)ldc + col] = v1;
            }
        }
    }

    if (EPI == EPI_EXP) {
        __syncthreads();               // tiles no longer needed; reuse smem
        float* rsred = sm;             // [128][4]
        if (t4 == 0) {
            #pragma unroll
            for (int mt = 0; mt < 4; mt++) {
                rsred[(m0base + mt * 16 + g) * 4 + wn]     = rs[mt][0];
                rsred[(m0base + mt * 16 + g + 8) * 4 + wn] = rs[mt][1];
            }
        }
        __syncthreads();
        if (tid < 128) {
            float s = rsred[tid * 4] + rsred[tid * 4 + 1] +
                      rsred[tid * 4 + 2] + rsred[tid * 4 + 3];
            part[((size_t)z * SEQ + bm + tid) * 16 + blockIdx.x] = s;
        }
    }
}

// ---------------- streaming tf32 pre-round: dst = tf32(src) ----------------
__global__ __launch_bounds__(256)
void preround(const float4* __restrict__ src, float4* __restrict__ dst, int n4)
{
    int i = blockIdx.x * 256 + threadIdx.x;
    int stride = gridDim.x * 256;
    for (; i < n4; i += stride) {
        float4 v = src[i];
        uint4 r = { tf32r(v.x), tf32r(v.y), tf32r(v.z), tf32r(v.w) };
        dst[i] = *(float4*)&r;
    }
}

// ---------------- rowsum reduce: rinv = 1/sum(partials) ----------------
__global__ __launch_bounds__(256)
void rowsum_reduce(const float* __restrict__ part, float* __restrict__ rinv)
{
    int i = blockIdx.x * 256 + threadIdx.x;     // 0..65535
    const float* p = part + (size_t)i * 16;
    float s = 0.0f;
    #pragma unroll
    for (int j = 0; j < 16; j++) s += p[j];
    rinv[i] = (s > 0.0f) ? (1.0f / s) : 0.0f;
}

// ---------------- RMSNorm + RoPE for Q and K heads (stores tf32-rounded) ----------------
__global__ __launch_bounds__(64)
void norm_rope(const float* __restrict__ qkv,
               const float* __restrict__ cosb, const float* __restrict__ sinb,
               const float* __restrict__ qw, const float* __restrict__ kw,
               float* __restrict__ q, float* __restrict__ k)
{
    int tok = blockIdx.x;
    int h   = blockIdx.y;
    int i   = threadIdx.x;
    int b   = tok >> 11;
    int s   = tok & (SEQ - 1);

    const float* src = qkv + (size_t)tok * QKVD + h * HD;
    float x0 = src[2 * i];
    float x1 = src[2 * i + 1];

    float ss = x0 * x0 + x1 * x1;
    #pragma unroll
    for (int off = 16; off > 0; off >>= 1)
        ss += __shfl_xor_sync(0xFFFFFFFFu, ss, off);
    __shared__ float red[2];
    if ((i & 31) == 0) red[i >> 5] = ss;
    __syncthreads();
    float total = red[0] + red[1];

    float inv = rsqrtf(total * (1.0f / HD) + 1e-5f);
    const float* w = (h < NH) ? qw : kw;
    float y0 = x0 * inv * w[2 * i];
    float y1 = x1 * inv * w[2 * i + 1];

    float c  = cosb[(size_t)s * (HD / 2) + i];
    float sn = sinb[(size_t)s * (HD / 2) + i];
    float o0 = y0 * c - y1 * sn;
    float o1 = y0 * sn + y1 * c;

    float* dst;
    if (h < NH)  dst = q + ((size_t)(b * NH + h) * SEQ + s) * HD;
    else         dst = k + ((size_t)(b * NKV + (h - NH)) * SEQ + s) * HD;
    dst[2 * i]     = tf32rf(o0);
    dst[2 * i + 1] = tf32rf(o1);
}

// ---------------- V transpose (stores tf32-rounded) ----------------
__global__ __launch_bounds__(256)
void vtrans(const float* __restrict__ qkv, float* __restrict__ vt)
{
    __shared__ float tile[32][33];
    int zz = blockIdx.z;
    int b  = zz >> 3;
    int kh = zz & 7;
    int s0 = blockIdx.x * 32;
    int d0 = blockIdx.y * 32;

    #pragma unroll
    for (int j = 0; j < 4; j++) {
        int s = s0 + threadIdx.y + j * 8;
        tile[threadIdx.y + j * 8][threadIdx.x] =
            qkv[((size_t)(b * SEQ + s)) * QKVD + (NH + NKV) * HD + kh * HD + d0 + threadIdx.x];
    }
    __syncthreads();
    #pragma unroll
    for (int j = 0; j < 4; j++) {
        int d = d0 + threadIdx.y + j * 8;
        vt[((size_t)zz * HD + d) * SEQ + s0 + threadIdx.x] =
            tf32rf(tile[threadIdx.x][threadIdx.y + j * 8]);
    }
}

// ---------------- launch ----------------
extern "C" void kernel_launch(void* const* d_in, const int* in_sizes, int n_in,
                              void* d_out, int out_size)
{
    const float* x     = (const float*)d_in[0];
    const int*   xmask = (const int*)  d_in[1];
    const float* fcos  = (const float*)d_in[2];
    const float* fsin  = (const float*)d_in[3];
    const float* Wqkv  = (const float*)d_in[4];
    const float* Wout  = (const float*)d_in[5];
    const float* qw    = (const float*)d_in[6];
    const float* kw    = (const float*)d_in[7];
    float* out = (float*)d_out;

    float *qkv, *q, *k, *vt, *sc, *att, *part, *rinv, *xr, *wq, *wo;
    cudaGetSymbolAddress((void**)&qkv,  g_qkv);
    cudaGetSymbolAddress((void**)&q,    g_q);
    cudaGetSymbolAddress((void**)&k,    g_k);
    cudaGetSymbolAddress((void**)&vt,   g_vt);
    cudaGetSymbolAddress((void**)&sc,   g_sc);
    cudaGetSymbolAddress((void**)&att,  g_att);
    cudaGetSymbolAddress((void**)&part, g_part);
    cudaGetSymbolAddress((void**)&rinv, g_rinv);
    cudaGetSymbolAddress((void**)&xr,   g_xr);
    cudaGetSymbolAddress((void**)&wq,   g_wq);
    cudaGetSymbolAddress((void**)&wo,   g_wo);

    cudaFuncSetAttribute(mma_gemm<EPI_NONE>, cudaFuncAttributeMaxDynamicSharedMemorySize, SMEM_TOTAL);
    cudaFuncSetAttribute(mma_gemm<EPI_EXP>,  cudaFuncAttributeMaxDynamicSharedMemorySize, SMEM_TOTAL);
    cudaFuncSetAttribute(mma_gemm<EPI_DIV>,  cudaFuncAttributeMaxDynamicSharedMemorySize, SMEM_TOTAL);

    Off zo = {0, 0, 0, 0};
    float scale = rsqrtf((float)HD);

    // 0) pre-round raw GEMM inputs to tf32 bits
    preround<<<1184, 256>>>((const float4*)x,    (float4*)xr, (NTOK * DIM) / 4);
    preround<<<1184, 256>>>((const float4*)Wqkv, (float4*)wq, (QKVD * DIM) / 4);
    preround<<<1184, 256>>>((const float4*)Wout, (float4*)wo, (DIM * DIM) / 4);

    // 1) qkv = x @ Wqkv^T : M=4096, N=4096, K=2048 (exact fp32 output)
    mma_gemm<EPI_NONE><<<dim3(QKVD / 128, NTOK / 128, 1), 256, SMEM_TOTAL>>>(
        xr, wq, qkv, DIM, DIM, DIM, QKVD, zo, zo, zo, nullptr, 0.f, nullptr, nullptr);

    // 2) RMSNorm + RoPE on Q,K (rounded stores)
    norm_rope<<<dim3(NTOK, NH + NKV), 64>>>(qkv, fcos, fsin, qw, kw, q, k);

    // 3) V transpose (rounded stores)
    vtrans<<<dim3(SEQ / 32, HD / 32, BSZ * NKV), dim3(32, 8)>>>(qkv, vt);

    // 4) P = exp(scale * Q[z] @ K[z>>1]^T) * mask, + row partial sums
    {
        Off oa = {0, (long long)SEQ * HD, 0, 0};
        Off ob = {1, (long long)SEQ * HD, 0, 0};
        Off oc = {0, (long long)SEQ * SEQ, 0, 0};
        mma_gemm<EPI_EXP><<<dim3(SEQ / 128, SEQ / 128, BSZ * NH), 256, SMEM_TOTAL>>>(
            q, k, sc, HD, HD, HD, SEQ, oa, ob, oc, xmask, scale, part, nullptr);
    }

    // 5) rinv = 1 / rowsum
    rowsum_reduce<<<(BSZ * NH * SEQ) / 256, 256>>>(part, rinv);

    // 6) att = (P[z] @ Vt[z>>1]^T) * rinv : M=2048, N=128, K=2048
    {
        Off oa = {0, (long long)SEQ * SEQ, 0, 0};
        Off ob = {1, (long long)HD * SEQ, 0, 0};
        Off oc = {4, (long long)SEQ * DIM, 15, (long long)HD};
        mma_gemm<EPI_DIV><<<dim3(1, SEQ / 128, BSZ * NH), 256, SMEM_TOTAL>>>(
            sc, vt, att, SEQ, SEQ, SEQ, DIM, oa, ob, oc, nullptr, 0.f, nullptr, rinv);
    }

    // 7) out = att @ Wout^T : M=4096, N=2048, K=2048 (exact fp32 output)
    mma_gemm<EPI_NONE><<<dim3(DIM / 128, NTOK / 128, 1), 256, SMEM_TOTAL>>>(
        att, wo, out, DIM, DIM, DIM, DIM, zo, zo, zo, nullptr, 0.f, nullptr, nullptr);
}

// round 7
// speedup vs baseline: 5.8993x; 1.5296x over previous
#include <cuda_runtime.h>
#include <cuda_fp16.h>
#include <math.h>
#include <stdint.h>

// Problem constants
#define BSZ 2
#define SEQ 2048
#define DIM 2048
#define NH 16
#define NKV 8
#define HD 128
#define QKVD 4096          // (16 + 2*8) * 128
#define NTOK (BSZ*SEQ)     // 4096

// ---------------- scratch (static __device__, no allocations) ----------------
static __device__ float  g_qkv[(size_t)NTOK * QKVD];                 // 64 MB fp32
static __device__ __half g_q  [(size_t)BSZ * NH  * SEQ * HD];        // 16 MB
static __device__ __half g_k  [(size_t)BSZ * NKV * SEQ * HD];        // 8 MB
static __device__ __half g_vt [(size_t)BSZ * NKV * HD  * SEQ];       // 8 MB
static __device__ __half g_sc [(size_t)BSZ * NH  * SEQ * SEQ];       // 256 MB (P)
static __device__ __half g_att[(size_t)NTOK * DIM];                  // 16 MB
static __device__ float  g_part[(size_t)BSZ * NH * SEQ * 16];        // 4 MB row partials
static __device__ float  g_rinv[(size_t)BSZ * NH * SEQ];             // 256 KB
static __device__ __half g_xh [(size_t)NTOK * DIM];                  // 16 MB
static __device__ __half g_wq [(size_t)QKVD * DIM];                  // 16 MB
static __device__ __half g_wo [(size_t)DIM * DIM];                   // 8 MB

// batching descriptor: per-z offset = (z>>sh)*stH + (z&mk)*stL
struct Off { int sh; long long stH; int mk; long long stL; };
__device__ __forceinline__ size_t offz(Off o, int z) {
    return (size_t)((long long)(z >> o.sh) * o.stH + (long long)(z & o.mk) * o.stL);
}

__device__ __forceinline__ uint32_t smem_u32(const void* p) {
    uint32_t a;
    asm("{ .reg .u64 t; cvta.to.shared.u64 t, %1; cvt.u32.u64 %0, t; }" : "=r"(a) : "l"(p));
    return a;
}

__device__ __forceinline__ void cpa16(uint32_t saddr, const void* g) {
    asm volatile("cp.async.cg.shared.global [%0], [%1], 16;" :: "r"(saddr), "l"(g));
}

// smem tile (fp16): 128 rows x 32 k, row stride 40 halves (80B) -> conflict-free frags
#define STH 40
#define TILE_BYTES (128 * STH * 2)           // 10240 B per tile
#define STAGE_BYTES (2 * TILE_BYTES)         // A then B
#define STAGES 4
#define SMEM_TOTAL (STAGES * STAGE_BYTES)    // 81920 B

#define EPI_NONE 0
#define EPI_EXP  1
#define EPI_DIV  2

// ---------------- tensor-core FP16 batched GEMM: C[z] = A[z] * B[z]^T ----------------
// A,B fp16 K-major. CTA tile 128x128, 8 warps (2m x 4n), warp tile 64x32,
// K chunk 32 (2 x m16n8k16), 4-stage cp.async ring, 2 CTAs/SM, fp32 accum.
// EPI_NONE: C float. EPI_EXP: C half = exp(acc*scale)*mask + fp32 row partials.
// EPI_DIV: C half = acc * rinv[row].
template<int EPI>
__global__ __launch_bounds__(256, 2)
void mma_gemm(const __half* __restrict__ A, const __half* __restrict__ B, void* __restrict__ Cv,
              int K, int lda, int ldb, int ldc, Off oa, Off ob, Off oc,
              const int* __restrict__ mask, float scale,
              float* __restrict__ part, const float* __restrict__ rinv)
{
    extern __shared__ char smc[];
    float* smf = (float*)smc;

    int tid = threadIdx.x;
    int wid = tid >> 5, lane = tid & 31;
    int g = lane >> 2, t4 = lane & 3;
    int wm = wid & 1, wn = wid >> 1;
    int m0base = wm * 64, n0base = wn * 32;

    int z = blockIdx.z;
    A += offz(oa, z); B += offz(ob, z);
    size_t coff = offz(oc, z);
    size_t bm = (size_t)blockIdx.y * 128;
    size_t bn = (size_t)blockIdx.x * 128;

    const int NC = K >> 5;

    float acc[4][4][4];
    #pragma unroll
    for (int i = 0; i < 4; i++)
        #pragma unroll
        for (int j = 0; j < 4; j++)
            #pragma unroll
            for (int r = 0; r < 4; r++) acc[i][j][r] = 0.0f;

    int lrow = tid >> 2;            // 0..63 base row (x2 iterations of 64)
    int lseg = tid & 3;             // which 16B (8 halves) of the 64B row
    uint32_t sbase = smem_u32(smc);

    auto load_chunk = [&](int c, int st) {
        const __half* Ak = A + c * 32;
        const __half* Bk = B + c * 32;
        uint32_t sA = sbase + (uint32_t)st * STAGE_BYTES;
        uint32_t sB = sA + TILE_BYTES;
        #pragma unroll
        for (int i = 0; i < 2; i++) {
            int row = lrow + i * 64;
            uint32_t so = (uint32_t)(row * (STH * 2) + lseg * 16);
            cpa16(sA + so, Ak + (bm + row) * (size_t)lda + lseg * 8);
            cpa16(sB + so, Bk + (bn + row) * (size_t)ldb + lseg * 8);
        }
        asm volatile("cp.async.commit_group;" ::: "memory");
    };

    load_chunk(0, 0);
    if (NC > 1) load_chunk(1, 1);
    if (NC > 2) load_chunk(2, 2);

    for (int c = 0; c < NC; c++) {
        int st = c & 3;
        int left = NC - c - 1;
        if (left >= 2)      asm volatile("cp.async.wait_group 2;" ::: "memory");
        else if (left == 1) asm volatile("cp.async.wait_group 1;" ::: "memory");
        else                asm volatile("cp.async.wait_group 0;" ::: "memory");
        __syncthreads();

        if (c + 3 < NC) load_chunk(c + 3, (c + 3) & 3);

        const uint32_t* Ab = (const uint32_t*)(smc + st * STAGE_BYTES);
        const uint32_t* Bb = (const uint32_t*)(smc + st * STAGE_BYTES + TILE_BYTES);

        #pragma unroll
        for (int ks = 0; ks < 2; ks++) {
            int kb = ks * 8 + t4;                   // u32 units within row
            uint32_t bb[4][2];
            #pragma unroll
            for (int nt = 0; nt < 4; nt++) {
                const uint32_t* bp = Bb + (n0base + nt * 8 + g) * (STH / 2) + kb;
                bb[nt][0] = bp[0];
                bb[nt][1] = bp[4];
            }
            #pragma unroll
            for (int mt = 0; mt < 4; mt++) {
                const uint32_t* ap = Ab + (m0base + mt * 16 + g) * (STH / 2) + kb;
                uint32_t a0 = ap[0];
                uint32_t a1 = ap[8 * (STH / 2)];
                uint32_t a2 = ap[4];
                uint32_t a3 = ap[8 * (STH / 2) + 4];
                #pragma unroll
                for (int nt = 0; nt < 4; nt++)
                    asm volatile(
                        "mma.sync.aligned.m16n8k16.row.col.f32.f16.f16.f32 "
                        "{%0,%1,%2,%3}, {%4,%5,%6,%7}, {%8,%9}, {%0,%1,%2,%3};"
                        : "+f"(acc[mt][nt][0]), "+f"(acc[mt][nt][1]),
                          "+f"(acc[mt][nt][2]), "+f"(acc[mt][nt][3])
                        : "r"(a0), "r"(a1), "r"(a2), "r"(a3),
                          "r"(bb[nt][0]), "r"(bb[nt][1]));
            }
        }
    }

    // ---- epilogue ----
    float rs[4][2];
    if (EPI == EPI_EXP) {
        const int* mrow = mask + ((size_t)(z >> 4)) * SEQ + bn;
        #pragma unroll
        for (int mt = 0; mt < 4; mt++) { rs[mt][0] = 0.0f; rs[mt][1] = 0.0f; }
        #pragma unroll
        for (int nt = 0; nt < 4; nt++) {
            int c0 = n0base + nt * 8 + 2 * t4;
            float m0 = mrow[c0]     ? 1.0f : 0.0f;
            float m1 = mrow[c0 + 1] ? 1.0f : 0.0f;
            #pragma unroll
            for (int mt = 0; mt < 4; mt++) {
                float e0 = __expf(acc[mt][nt][0] * scale) * m0;
                float e1 = __expf(acc[mt][nt][1] * scale) * m1;
                float e2 = __expf(acc[mt][nt][2] * scale) * m0;
                float e3 = __expf(acc[mt][nt][3] * scale) * m1;
                acc[mt][nt][0] = e0; acc[mt][nt][1] = e1;
                acc[mt][nt][2] = e2; acc[mt][nt][3] = e3;
                rs[mt][0] += e0 + e1;
                rs[mt][1] += e2 + e3;
            }
        }
        #pragma unroll
        for (int mt = 0; mt < 4; mt++) {
            rs[mt][0] += __shfl_xor_sync(0xFFFFFFFFu, rs[mt][0], 1);
            rs[mt][0] += __shfl_xor_sync(0xFFFFFFFFu, rs[mt][0], 2);
            rs[mt][1] += __shfl_xor_sync(0xFFFFFFFFu, rs[mt][1], 1);
            rs[mt][1] += __shfl_xor_sync(0xFFFFFFFFu, rs[mt][1], 2);
        }
    } else if (EPI == EPI_DIV) {
        const float* rz = rinv + (size_t)z * SEQ + bm;
        #pragma unroll
        for (int mt = 0; mt < 4; mt++) {
            float i0 = rz[m0base + mt * 16 + g];
            float i1 = rz[m0base + mt * 16 + g + 8];
            #pragma unroll
            for (int nt = 0; nt < 4; nt++) {
                acc[mt][nt][0] *= i0; acc[mt][nt][1] *= i0;
                acc[mt][nt][2] *= i1; acc[mt][nt][3] *= i1;
            }
        }
    }

    // ---- store C ----
    if (EPI == EPI_NONE) {
        float* C = (float*)Cv + coff;
        #pragma unroll
        for (int mt = 0; mt < 4; mt++) {
            size_t row = bm + m0base + mt * 16 + g;
            #pragma unroll
            for (int nt = 0; nt < 4; nt++) {
                size_t col = bn + n0base + nt * 8 + 2 * t4;
                *(float2*)&C[row * (size_t)ldc + col] =
                    make_float2(acc[mt][nt][0], acc[mt][nt][1]);
                *(float2*)&C[(row + 8) * (size_t)ldc + col] =
                    make_float2(acc[mt][nt][2], acc[mt][nt][3]);
            }
        }
    } else {
        __half* C = (__half*)Cv + coff;
        #pragma unroll
        for (int mt = 0; mt < 4; mt++) {
            size_t row = bm + m0base + mt * 16 + g;
            #pragma unroll
            for (int nt = 0; nt < 4; nt++) {
                size_t col = bn + n0base + nt * 8 + 2 * t4;
                *(__half2*)&C[row * (size_t)ldc + col] =
                    __floats2half2_rn(acc[mt][nt][0], acc[mt][nt][1]);
                *(__half2*)&C[(row + 8) * (size_t)ldc + col] =
                    __floats2half2_rn(acc[mt][nt][2], acc[mt][nt][3]);
            }
        }
    }

    if (EPI == EPI_EXP) {
        __syncthreads();               // tiles done; reuse smem
        float* rsred = smf;            // [128][4]
        if (t4 == 0) {
            #pragma unroll
            for (int mt = 0; mt < 4; mt++) {
                rsred[(m0base + mt * 16 + g) * 4 + wn]     = rs[mt][0];
                rsred[(m0base + mt * 16 + g + 8) * 4 + wn] = rs[mt][1];
            }
        }
        __syncthreads();
        if (tid < 128) {
            float s = rsred[tid * 4] + rsred[tid * 4 + 1] +
                      rsred[tid * 4 + 2] + rsred[tid * 4 + 3];
            part[((size_t)z * SEQ + bm + tid) * 16 + blockIdx.x] = s;
        }
    }
}

// ---------------- streaming fp32 -> fp16 ----------------
__global__ __launch_bounds__(256)
void tohalf(const float2* __restrict__ src, __half2* __restrict__ dst, int n2)
{
    int i = blockIdx.x * 256 + threadIdx.x;
    int stride = gridDim.x * 256;
    for (; i < n2; i += stride) {
        float2 v = src[i];
        dst[i] = __floats2half2_rn(v.x, v.y);
    }
}

// ---------------- rowsum reduce: rinv = 1/sum(partials) ----------------
__global__ __launch_bounds__(256)
void rowsum_reduce(const float* __restrict__ part, float* __restrict__ rinv)
{
    int i = blockIdx.x * 256 + threadIdx.x;     // 0..65535
    const float* p = part + (size_t)i * 16;
    float s = 0.0f;
    #pragma unroll
    for (int j = 0; j < 16; j++) s += p[j];
    rinv[i] = (s > 0.0f) ? (1.0f / s) : 0.0f;
}

// ---------------- RMSNorm + RoPE for Q and K heads (fp16 stores) ----------------
__global__ __launch_bounds__(64)
void norm_rope(const float* __restrict__ qkv,
               const float* __restrict__ cosb, const float* __restrict__ sinb,
               const float* __restrict__ qw, const float* __restrict__ kw,
               __half* __restrict__ q, __half* __restrict__ k)
{
    int tok = blockIdx.x;
    int h   = blockIdx.y;
    int i   = threadIdx.x;
    int b   = tok >> 11;
    int s   = tok & (SEQ - 1);

    const float* src = qkv + (size_t)tok * QKVD + h * HD;
    float x0 = src[2 * i];
    float x1 = src[2 * i + 1];

    float ss = x0 * x0 + x1 * x1;
    #pragma unroll
    for (int off = 16; off > 0; off >>= 1)
        ss += __shfl_xor_sync(0xFFFFFFFFu, ss, off);
    __shared__ float red[2];
    if ((i & 31) == 0) red[i >> 5] = ss;
    __syncthreads();
    float total = red[0] + red[1];

    float inv = rsqrtf(total * (1.0f / HD) + 1e-5f);
    const float* w = (h < NH) ? qw : kw;
    float y0 = x0 * inv * w[2 * i];
    float y1 = x1 * inv * w[2 * i + 1];

    float c  = cosb[(size_t)s * (HD / 2) + i];
    float sn = sinb[(size_t)s * (HD / 2) + i];
    float o0 = y0 * c - y1 * sn;
    float o1 = y0 * sn + y1 * c;

    __half* dst;
    if (h < NH)  dst = q + ((size_t)(b * NH + h) * SEQ + s) * HD;
    else         dst = k + ((size_t)(b * NKV + (h - NH)) * SEQ + s) * HD;
    *(__half2*)&dst[2 * i] = __floats2half2_rn(o0, o1);
}

// ---------------- V transpose (fp16 stores) ----------------
__global__ __launch_bounds__(256)
void vtrans(const float* __restrict__ qkv, __half* __restrict__ vt)
{
    __shared__ float tile[32][33];
    int zz = blockIdx.z;
    int b  = zz >> 3;
    int kh = zz & 7;
    int s0 = blockIdx.x * 32;
    int d0 = blockIdx.y * 32;

    #pragma unroll
    for (int j = 0; j < 4; j++) {
        int s = s0 + threadIdx.y + j * 8;
        tile[threadIdx.y + j * 8][threadIdx.x] =
            qkv[((size_t)(b * SEQ + s)) * QKVD + (NH + NKV) * HD + kh * HD + d0 + threadIdx.x];
    }
    __syncthreads();
    #pragma unroll
    for (int j = 0; j < 4; j++) {
        int d = d0 + threadIdx.y + j * 8;
        vt[((size_t)zz * HD + d) * SEQ + s0 + threadIdx.x] =
            __float2half_rn(tile[threadIdx.x][threadIdx.y + j * 8]);
    }
}

// ---------------- launch ----------------
extern "C" void kernel_launch(void* const* d_in, const int* in_sizes, int n_in,
                              void* d_out, int out_size)
{
    const float* x     = (const float*)d_in[0];
    const int*   xmask = (const int*)  d_in[1];
    const float* fcos  = (const float*)d_in[2];
    const float* fsin  = (const float*)d_in[3];
    const float* Wqkv  = (const float*)d_in[4];
    const float* Wout  = (const float*)d_in[5];
    const float* qw    = (const float*)d_in[6];
    const float* kw    = (const float*)d_in[7];
    float* out = (float*)d_out;

    float *qkv, *part, *rinv;
    __half *q, *k, *vt, *sc, *att, *xh, *wq, *wo;
    cudaGetSymbolAddress((void**)&qkv,  g_qkv);
    cudaGetSymbolAddress((void**)&q,    g_q);
    cudaGetSymbolAddress((void**)&k,    g_k);
    cudaGetSymbolAddress((void**)&vt,   g_vt);
    cudaGetSymbolAddress((void**)&sc,   g_sc);
    cudaGetSymbolAddress((void**)&att,  g_att);
    cudaGetSymbolAddress((void**)&part, g_part);
    cudaGetSymbolAddress((void**)&rinv, g_rinv);
    cudaGetSymbolAddress((void**)&xh,   g_xh);
    cudaGetSymbolAddress((void**)&wq,   g_wq);
    cudaGetSymbolAddress((void**)&wo,   g_wo);

    cudaFuncSetAttribute(mma_gemm<EPI_NONE>, cudaFuncAttributeMaxDynamicSharedMemorySize, SMEM_TOTAL);
    cudaFuncSetAttribute(mma_gemm<EPI_EXP>,  cudaFuncAttributeMaxDynamicSharedMemorySize, SMEM_TOTAL);
    cudaFuncSetAttribute(mma_gemm<EPI_DIV>,  cudaFuncAttributeMaxDynamicSharedMemorySize, SMEM_TOTAL);

    Off zo = {0, 0, 0, 0};
    float scale = rsqrtf((float)HD);

    // 0) convert raw GEMM inputs to fp16
    tohalf<<<1184, 256>>>((const float2*)x,    (__half2*)xh, (NTOK * DIM) / 2);
    tohalf<<<1184, 256>>>((const float2*)Wqkv, (__half2*)wq, (QKVD * DIM) / 2);
    tohalf<<<1184, 256>>>((const float2*)Wout, (__half2*)wo, (DIM * DIM) / 2);

    // 1) qkv = x @ Wqkv^T : M=4096, N=4096, K=2048 (fp32 out)
    mma_gemm<EPI_NONE><<<dim3(QKVD / 128, NTOK / 128, 1), 256, SMEM_TOTAL>>>(
        xh, wq, qkv, DIM, DIM, DIM, QKVD, zo, zo, zo, nullptr, 0.f, nullptr, nullptr);

    // 2) RMSNorm + RoPE on Q,K (fp16 out)
    norm_rope<<<dim3(NTOK, NH + NKV), 64>>>(qkv, fcos, fsin, qw, kw, q, k);

    // 3) V transpose (fp16 out)
    vtrans<<<dim3(SEQ / 32, HD / 32, BSZ * NKV), dim3(32, 8)>>>(qkv, vt);

    // 4) P = exp(scale * Q[z] @ K[z>>1]^T) * mask (fp16 out) + fp32 row partials
    {
        Off oa = {0, (long long)SEQ * HD, 0, 0};
        Off ob = {1, (long long)SEQ * HD, 0, 0};
        Off oc = {0, (long long)SEQ * SEQ, 0, 0};
        mma_gemm<EPI_EXP><<<dim3(SEQ / 128, SEQ / 128, BSZ * NH), 256, SMEM_TOTAL>>>(
            q, k, sc, HD, HD, HD, SEQ, oa, ob, oc, xmask, scale, part, nullptr);
    }

    // 5) rinv = 1 / rowsum
    rowsum_reduce<<<(BSZ * NH * SEQ) / 256, 256>>>(part, rinv);

    // 6) att = (P[z] @ Vt[z>>1]^T) * rinv (fp16 out) : M=2048, N=128, K=2048
    {
        Off oa = {0, (long long)SEQ * SEQ, 0, 0};
        Off ob = {1, (long long)HD * SEQ, 0, 0};
        Off oc = {4, (long long)SEQ * DIM, 15, (long long)HD};
        mma_gemm<EPI_DIV><<<dim3(1, SEQ / 128, BSZ * NH), 256, SMEM_TOTAL>>>(
            sc, vt, att, SEQ, SEQ, SEQ, DIM, oa, ob, oc, nullptr, 0.f, nullptr, rinv);
    }

    // 7) out = att @ Wout^T : M=4096, N=2048, K=2048 (fp32 out)
    mma_gemm<EPI_NONE><<<dim3(DIM / 128, NTOK / 128, 1), 256, SMEM_TOTAL>>>(
        att, wo, out, DIM, DIM, DIM, DIM, zo, zo, zo, nullptr, 0.f, nullptr, nullptr);
}

// round 8
// speedup vs baseline: 6.1793x; 1.0475x over previous
#include <cuda_runtime.h>
#include <cuda_fp16.h>
#include <math.h>
#include <stdint.h>

// Problem constants
#define BSZ 2
#define SEQ 2048
#define DIM 2048
#define NH 16
#define NKV 8
#define HD 128
#define QKVD 4096          // (16 + 2*8) * 128
#define NTOK (BSZ*SEQ)     // 4096

// ---------------- scratch (static __device__, no allocations) ----------------
static __device__ float  g_qkv[(size_t)NTOK * QKVD];                 // 64 MB fp32
static __device__ __half g_q  [(size_t)BSZ * NH  * SEQ * HD];        // 16 MB
static __device__ __half g_k  [(size_t)BSZ * NKV * SEQ * HD];        // 8 MB
static __device__ __half g_vt [(size_t)BSZ * NKV * HD  * SEQ];       // 8 MB
static __device__ __half g_att[(size_t)NTOK * DIM];                  // 16 MB
static __device__ __half g_xh [(size_t)NTOK * DIM];                  // 16 MB
static __device__ __half g_wq [(size_t)QKVD * DIM];                  // 16 MB
static __device__ __half g_wo [(size_t)DIM * DIM];                   // 8 MB

// batching descriptor: per-z offset = (z>>sh)*stH + (z&mk)*stL
struct Off { int sh; long long stH; int mk; long long stL; };
__device__ __forceinline__ size_t offz(Off o, int z) {
    return (size_t)((long long)(z >> o.sh) * o.stH + (long long)(z & o.mk) * o.stL);
}

__device__ __forceinline__ uint32_t smem_u32(const void* p) {
    uint32_t a;
    asm("{ .reg .u64 t; cvta.to.shared.u64 t, %1; cvt.u32.u64 %0, t; }" : "=r"(a) : "l"(p));
    return a;
}

__device__ __forceinline__ void cpa16(uint32_t saddr, const void* g) {
    asm volatile("cp.async.cg.shared.global [%0], [%1], 16;" :: "r"(saddr), "l"(g));
}

#define MMA16816(acc, a0, a1, a2, a3, b0, b1) \
    asm volatile( \
        "mma.sync.aligned.m16n8k16.row.col.f32.f16.f16.f32 " \
        "{%0,%1,%2,%3}, {%4,%5,%6,%7}, {%8,%9}, {%0,%1,%2,%3};" \
        : "+f"((acc)[0]), "+f"((acc)[1]), "+f"((acc)[2]), "+f"((acc)[3]) \
        : "r"(a0), "r"(a1), "r"(a2), "r"(a3), "r"(b0), "r"(b1))

// ============================================================================
//                       generic fp16 GEMM (QKV / out proj)
// ============================================================================
#define STH 40
#define TILE_BYTES (128 * STH * 2)           // 10240 B per tile
#define STAGE_BYTES (2 * TILE_BYTES)
#define GSTAGES 4
#define GSMEM_TOTAL (GSTAGES * STAGE_BYTES)  // 81920 B

__global__ __launch_bounds__(256, 2)
void mma_gemm(const __half* __restrict__ A, const __half* __restrict__ B, float* __restrict__ C,
              int K, int lda, int ldb, int ldc)
{
    extern __shared__ char smc[];

    int tid = threadIdx.x;
    int wid = tid >> 5, lane = tid & 31;
    int g = lane >> 2, t4 = lane & 3;
    int wm = wid & 1, wn = wid >> 1;
    int m0base = wm * 64, n0base = wn * 32;

    size_t bm = (size_t)blockIdx.y * 128;
    size_t bn = (size_t)blockIdx.x * 128;

    const int NC = K >> 5;

    float acc[4][4][4];
    #pragma unroll
    for (int i = 0; i < 4; i++)
        #pragma unroll
        for (int j = 0; j < 4; j++)
            #pragma unroll
            for (int r = 0; r < 4; r++) acc[i][j][r] = 0.0f;

    int lrow = tid >> 2;
    int lseg = tid & 3;
    uint32_t sbase = smem_u32(smc);

    auto load_chunk = [&](int c, int st) {
        const __half* Ak = A + c * 32;
        const __half* Bk = B + c * 32;
        uint32_t sA = sbase + (uint32_t)st * STAGE_BYTES;
        uint32_t sB = sA + TILE_BYTES;
        #pragma unroll
        for (int i = 0; i < 2; i++) {
            int row = lrow + i * 64;
            uint32_t so = (uint32_t)(row * (STH * 2) + lseg * 16);
            cpa16(sA + so, Ak + (bm + row) * (size_t)lda + lseg * 8);
            cpa16(sB + so, Bk + (bn + row) * (size_t)ldb + lseg * 8);
        }
        asm volatile("cp.async.commit_group;" ::: "memory");
    };

    load_chunk(0, 0);
    if (NC > 1) load_chunk(1, 1);
    if (NC > 2) load_chunk(2, 2);

    for (int c = 0; c < NC; c++) {
        int st = c & 3;
        int left = NC - c - 1;
        if (left >= 2)      asm volatile("cp.async.wait_group 2;" ::: "memory");
        else if (left == 1) asm volatile("cp.async.wait_group 1;" ::: "memory");
        else                asm volatile("cp.async.wait_group 0;" ::: "memory");
        __syncthreads();

        if (c + 3 < NC) load_chunk(c + 3, (c + 3) & 3);

        const uint32_t* Ab = (const uint32_t*)(smc + st * STAGE_BYTES);
        const uint32_t* Bb = (const uint32_t*)(smc + st * STAGE_BYTES + TILE_BYTES);

        #pragma unroll
        for (int ks = 0; ks < 2; ks++) {
            int kb = ks * 8 + t4;
            uint32_t bb[4][2];
            #pragma unroll
            for (int nt = 0; nt < 4; nt++) {
                const uint32_t* bp = Bb + (n0base + nt * 8 + g) * (STH / 2) + kb;
                bb[nt][0] = bp[0];
                bb[nt][1] = bp[4];
            }
            #pragma unroll
            for (int mt = 0; mt < 4; mt++) {
                const uint32_t* ap = Ab + (m0base + mt * 16 + g) * (STH / 2) + kb;
                uint32_t a0 = ap[0];
                uint32_t a1 = ap[8 * (STH / 2)];
                uint32_t a2 = ap[4];
                uint32_t a3 = ap[8 * (STH / 2) + 4];
                #pragma unroll
                for (int nt = 0; nt < 4; nt++)
                    MMA16816(acc[mt][nt], a0, a1, a2, a3, bb[nt][0], bb[nt][1]);
            }
        }
    }

    #pragma unroll
    for (int mt = 0; mt < 4; mt++) {
        size_t row = bm + m0base + mt * 16 + g;
        #pragma unroll
        for (int nt = 0; nt < 4; nt++) {
            size_t col = bn + n0base + nt * 8 + 2 * t4;
            *(float2*)&C[row * (size_t)ldc + col] =
                make_float2(acc[mt][nt][0], acc[mt][nt][1]);
            *(float2*)&C[(row + 8) * (size_t)ldc + col] =
                make_float2(acc[mt][nt][2], acc[mt][nt][3]);
        }
    }
}

// ============================================================================
//      fused flash attention: S = Q K^T, P = exp(S*scale)*mask, out = P V / rowsum
// ============================================================================
// 512 threads (16 warps, 4m x 4n). Per CTA: 128 q-rows of one (b,h). Loop over
// 32 kv-blocks of 64, 4-stage cp.async ring for K/V. Q resident in smem.
// No max subtraction (validated: |s*scale| <~ 8).

#define QSTRIDE 68            // u32 per Q/K row (128 halves + 8 pad)
#define PSTRIDE 36            // u32 per P/V row (64 halves + 8 pad)
#define SM_Q    0
#define SM_P    34816         // 128*136*2
#define SM_ST   53248         // SM_P + 128*72*2
#define KV_STAGE_BYTES 35840  // K 64*136*2=17408 + V 128*72*2=18432
#define FSMEM_TOTAL (SM_ST + 4 * KV_STAGE_BYTES)   // 196608 B
#define NKVB (SEQ / 64)       // 32

__global__ __launch_bounds__(512, 1)
void flash_attn(const __half* __restrict__ q, const __half* __restrict__ k,
                const __half* __restrict__ vt, const int* __restrict__ mask,
                __half* __restrict__ att, float scale)
{
    extern __shared__ char smc[];
    uint32_t sbase = smem_u32(smc);

    int tid = threadIdx.x;
    int wid = tid >> 5, lane = tid & 31;
    int g = lane >> 2, t4 = lane & 3;
    int wm = wid & 3, wn = wid >> 2;

    int z  = blockIdx.y;                 // b*NH + h
    size_t bm = (size_t)blockIdx.x * 128;

    const __half* Qg = q  + ((size_t)z * SEQ + bm) * HD;
    const __half* Kg = k  + (size_t)(z >> 1) * SEQ * HD;
    const __half* Vg = vt + (size_t)(z >> 1) * HD * SEQ;
    const int* mrow  = mask + (size_t)(z >> 4) * SEQ;

    const uint32_t* Qs = (const uint32_t*)(smc + SM_Q);
    uint32_t*       Ps = (uint32_t*)(smc + SM_P);

    float acc_o[2][4][4];
    #pragma unroll
    for (int i = 0; i < 2; i++)
        #pragma unroll
        for (int j = 0; j < 4; j++)
            #pragma unroll
            for (int r = 0; r < 4; r++) acc_o[i][j][r] = 0.0f;
    float rsum[2][2] = {};

    auto load_block = [&](int c, int st) {
        uint32_t sK = sbase + SM_ST + (uint32_t)st * KV_STAGE_BYTES;
        uint32_t sV = sK + 17408;
        #pragma unroll
        for (int i = 0; i < 2; i++) {
            int idx = tid + i * 512;
            int row = idx >> 4, seg = idx & 15;
            cpa16(sK + row * 272 + seg * 16, Kg + ((size_t)(c * 64 + row)) * HD + seg * 8);
        }
        #pragma unroll
        for (int i = 0; i < 2; i++) {
            int idx = tid + i * 512;
            int row = idx >> 3, seg = idx & 7;
            cpa16(sV + row * 144 + seg * 16, Vg + (size_t)row * SEQ + c * 64 + seg * 8);
        }
        asm volatile("cp.async.commit_group;" ::: "memory");
    };

    // Q load + block 0 in one group; blocks 1,2 separate groups
    #pragma unroll
    for (int i = 0; i < 4; i++) {
        int idx = tid + i * 512;
        int row = idx >> 4, seg = idx & 15;
        cpa16(sbase + SM_Q + row * 272 + seg * 16, Qg + (size_t)row * HD + seg * 8);
    }
    load_block(0, 0);
    load_block(1, 1);
    load_block(2, 2);

    for (int c = 0; c < NKVB; c++) {
        int st = c & 3;
        int left = NKVB - 1 - c;
        if (left >= 2)      asm volatile("cp.async.wait_group 2;" ::: "memory");
        else if (left == 1) asm volatile("cp.async.wait_group 1;" ::: "memory");
        else                asm volatile("cp.async.wait_group 0;" ::: "memory");
        __syncthreads();   // stage c ready; PV(c-1) complete everywhere

        const uint32_t* Ks = (const uint32_t*)(smc + SM_ST + st * KV_STAGE_BYTES);
        const uint32_t* Vs = (const uint32_t*)(smc + SM_ST + st * KV_STAGE_BYTES + 17408);

        // ---- S = Q (128x128) @ K^T (64x128) -> warp tile 32x16 ----
        float acc_s[2][2][4];
        #pragma unroll
        for (int i = 0; i < 2; i++)
            #pragma unroll
            for (int j = 0; j < 2; j++)
                #pragma unroll
                for (int r = 0; r < 4; r++) acc_s[i][j][r] = 0.0f;

        #pragma unroll
        for (int kt = 0; kt < 8; kt++) {
            int kb = kt * 8 + t4;
            uint32_t b0[2], b1[2];
            #pragma unroll
            for (int nt = 0; nt < 2; nt++) {
                const uint32_t* bp = Ks + (wn * 16 + nt * 8 + g) * QSTRIDE + kb;
                b0[nt] = bp[0];
                b1[nt] = bp[4];
            }
            #pragma unroll
            for (int mt = 0; mt < 2; mt++) {
                const uint32_t* ap = Qs + (wm * 32 + mt * 16 + g) * QSTRIDE + kb;
                uint32_t a0 = ap[0];
                uint32_t a1 = ap[8 * QSTRIDE];
                uint32_t a2 = ap[4];
                uint32_t a3 = ap[8 * QSTRIDE + 4];
                #pragma unroll
                for (int nt = 0; nt < 2; nt++)
                    MMA16816(acc_s[mt][nt], a0, a1, a2, a3, b0[nt], b1[nt]);
            }
        }

        // ---- exp * mask, rowsum accum, pack P to smem ----
        #pragma unroll
        for (int nt = 0; nt < 2; nt++) {
            int col0 = c * 64 + wn * 16 + nt * 8 + 2 * t4;
            float m0 = mrow[col0]     ? 1.0f : 0.0f;
            float m1 = mrow[col0 + 1] ? 1.0f : 0.0f;
            #pragma unroll
            for (int mt = 0; mt < 2; mt++) {
                float e0 = __expf(acc_s[mt][nt][0] * scale) * m0;
                float e1 = __expf(acc_s[mt][nt][1] * scale) * m1;
                float e2 = __expf(acc_s[mt][nt][2] * scale) * m0;
                float e3 = __expf(acc_s[mt][nt][3] * scale) * m1;
                rsum[mt][0] += e0 + e1;
                rsum[mt][1] += e2 + e3;
                int prow = wm * 32 + mt * 16 + g;
                int pcol = wn * 8 + nt * 4 + t4;
                __half2 h01 = __floats2half2_rn(e0, e1);
                __half2 h23 = __floats2half2_rn(e2, e3);
                Ps[prow * PSTRIDE + pcol]       = *(uint32_t*)&h01;
                Ps[(prow + 8) * PSTRIDE + pcol] = *(uint32_t*)&h23;
            }
        }

        if (c + 3 < NKVB) load_block(c + 3, (c + 3) & 3);

        __syncthreads();   // P visible

        // ---- out += P (128x64) @ V^T (128x64) -> warp tile 32x32 ----
        #pragma unroll
        for (int kt = 0; kt < 4; kt++) {
            int kb = kt * 8 + t4;
            uint32_t b0[4], b1[4];
            #pragma unroll
            for (int nt = 0; nt < 4; nt++) {
                const uint32_t* bp = Vs + (wn * 32 + nt * 8 + g) * PSTRIDE + kb;
                b0[nt] = bp[0];
                b1[nt] = bp[4];
            }
            #pragma unroll
            for (int mt = 0; mt < 2; mt++) {
                const uint32_t* ap = Ps + (wm * 32 + mt * 16 + g) * PSTRIDE + kb;
                uint32_t a0 = ap[0];
                uint32_t a1 = ap[8 * PSTRIDE];
                uint32_t a2 = ap[4];
                uint32_t a3 = ap[8 * PSTRIDE + 4];
                #pragma unroll
                for (int nt = 0; nt < 4; nt++)
                    MMA16816(acc_o[mt][nt], a0, a1, a2, a3, b0[nt], b1[nt]);
            }
        }
    }

    // ---- rowsum reduce across wn warps, divide, store ----
    __syncthreads();
    float* red = (float*)(smc + SM_P);   // [128][4]
    #pragma unroll
    for (int mt = 0; mt < 2; mt++) {
        #pragma unroll
        for (int h = 0; h < 2; h++) {
            float s = rsum[mt][h];
            s += __shfl_xor_sync(0xFFFFFFFFu, s, 1);
            s += __shfl_xor_sync(0xFFFFFFFFu, s, 2);
            rsum[mt][h] = s;
        }
    }
    if (t4 == 0) {
        #pragma unroll
        for (int mt = 0; mt < 2; mt++) {
            int r0 = wm * 32 + mt * 16 + g;
            red[r0 * 4 + wn]       = rsum[mt][0];
            red[(r0 + 8) * 4 + wn] = rsum[mt][1];
        }
    }
    __syncthreads();

    int b = z >> 4, h = z & 15;
    #pragma unroll
    for (int mt = 0; mt < 2; mt++) {
        int r0 = wm * 32 + mt * 16 + g;
        float t0 = red[r0 * 4] + red[r0 * 4 + 1] + red[r0 * 4 + 2] + red[r0 * 4 + 3];
        float t1 = red[(r0 + 8) * 4] + red[(r0 + 8) * 4 + 1] +
                   red[(r0 + 8) * 4 + 2] + red[(r0 + 8) * 4 + 3];
        float i0 = (t0 > 0.0f) ? (1.0f / t0) : 0.0f;
        float i1 = (t1 > 0.0f) ? (1.0f / t1) : 0.0f;
        size_t s0 = bm + r0;
        __half* d0 = att + ((size_t)b * SEQ + s0) * DIM + h * HD;
        __half* d1 = att + ((size_t)b * SEQ + s0 + 8) * DIM + h * HD;
        #pragma unroll
        for (int nt = 0; nt < 4; nt++) {
            int col = wn * 32 + nt * 8 + 2 * t4;
            *(__half2*)&d0[col] = __floats2half2_rn(acc_o[mt][nt][0] * i0, acc_o[mt][nt][1] * i0);
            *(__half2*)&d1[col] = __floats2half2_rn(acc_o[mt][nt][2] * i1, acc_o[mt][nt][3] * i1);
        }
    }
}

// ---------------- streaming fp32 -> fp16 ----------------
__global__ __launch_bounds__(256)
void tohalf(const float2* __restrict__ src, __half2* __restrict__ dst, int n2)
{
    int i = blockIdx.x * 256 + threadIdx.x;
    int stride = gridDim.x * 256;
    for (; i < n2; i += stride) {
        float2 v = src[i];
        dst[i] = __floats2half2_rn(v.x, v.y);
    }
}

// ---------------- RMSNorm + RoPE for Q and K heads (fp16 stores) ----------------
__global__ __launch_bounds__(64)
void norm_rope(const float* __restrict__ qkv,
               const float* __restrict__ cosb, const float* __restrict__ sinb,
               const float* __restrict__ qw, const float* __restrict__ kw,
               __half* __restrict__ q, __half* __restrict__ k)
{
    int tok = blockIdx.x;
    int h   = blockIdx.y;
    int i   = threadIdx.x;
    int b   = tok >> 11;
    int s   = tok & (SEQ - 1);

    const float* src = qkv + (size_t)tok * QKVD + h * HD;
    float x0 = src[2 * i];
    float x1 = src[2 * i + 1];

    float ss = x0 * x0 + x1 * x1;
    #pragma unroll
    for (int off = 16; off > 0; off >>= 1)
        ss += __shfl_xor_sync(0xFFFFFFFFu, ss, off);
    __shared__ float red[2];
    if ((i & 31) == 0) red[i >> 5] = ss;
    __syncthreads();
    float total = red[0] + red[1];

    float inv = rsqrtf(total * (1.0f / HD) + 1e-5f);
    const float* w = (h < NH) ? qw : kw;
    float y0 = x0 * inv * w[2 * i];
    float y1 = x1 * inv * w[2 * i + 1];

    float c  = cosb[(size_t)s * (HD / 2) + i];
    float sn = sinb[(size_t)s * (HD / 2) + i];
    float o0 = y0 * c - y1 * sn;
    float o1 = y0 * sn + y1 * c;

    __half* dst;
    if (h < NH)  dst = q + ((size_t)(b * NH + h) * SEQ + s) * HD;
    else         dst = k + ((size_t)(b * NKV + (h - NH)) * SEQ + s) * HD;
    *(__half2*)&dst[2 * i] = __floats2half2_rn(o0, o1);
}

// ---------------- V transpose (fp16 stores) ----------------
__global__ __launch_bounds__(256)
void vtrans(const float* __restrict__ qkv, __half* __restrict__ vt)
{
    __shared__ float tile[32][33];
    int zz = blockIdx.z;
    int b  = zz >> 3;
    int kh = zz & 7;
    int s0 = blockIdx.x * 32;
    int d0 = blockIdx.y * 32;

    #pragma unroll
    for (int j = 0; j < 4; j++) {
        int s = s0 + threadIdx.y + j * 8;
        tile[threadIdx.y + j * 8][threadIdx.x] =
            qkv[((size_t)(b * SEQ + s)) * QKVD + (NH + NKV) * HD + kh * HD + d0 + threadIdx.x];
    }
    __syncthreads();
    #pragma unroll
    for (int j = 0; j < 4; j++) {
        int d = d0 + threadIdx.y + j * 8;
        vt[((size_t)zz * HD + d) * SEQ + s0 + threadIdx.x] =
            __float2half_rn(tile[threadIdx.x][threadIdx.y + j * 8]);
    }
}

// ---------------- launch ----------------
extern "C" void kernel_launch(void* const* d_in, const int* in_sizes, int n_in,
                              void* d_out, int out_size)
{
    const float* x     = (const float*)d_in[0];
    const int*   xmask = (const int*)  d_in[1];
    const float* fcos  = (const float*)d_in[2];
    const float* fsin  = (const float*)d_in[3];
    const float* Wqkv  = (const float*)d_in[4];
    const float* Wout  = (const float*)d_in[5];
    const float* qw    = (const float*)d_in[6];
    const float* kw    = (const float*)d_in[7];
    float* out = (float*)d_out;

    float *qkv;
    __half *q, *k, *vt, *att, *xh, *wq, *wo;
    cudaGetSymbolAddress((void**)&qkv,  g_qkv);
    cudaGetSymbolAddress((void**)&q,    g_q);
    cudaGetSymbolAddress((void**)&k,    g_k);
    cudaGetSymbolAddress((void**)&vt,   g_vt);
    cudaGetSymbolAddress((void**)&att,  g_att);
    cudaGetSymbolAddress((void**)&xh,   g_xh);
    cudaGetSymbolAddress((void**)&wq,   g_wq);
    cudaGetSymbolAddress((void**)&wo,   g_wo);

    cudaFuncSetAttribute(mma_gemm, cudaFuncAttributeMaxDynamicSharedMemorySize, GSMEM_TOTAL);
    cudaFuncSetAttribute(flash_attn, cudaFuncAttributeMaxDynamicSharedMemorySize, FSMEM_TOTAL);

    float scale = rsqrtf((float)HD);

    // 0) convert raw GEMM inputs to fp16
    tohalf<<<1184, 256>>>((const float2*)x,    (__half2*)xh, (NTOK * DIM) / 2);
    tohalf<<<1184, 256>>>((const float2*)Wqkv, (__half2*)wq, (QKVD * DIM) / 2);
    tohalf<<<1184, 256>>>((const float2*)Wout, (__half2*)wo, (DIM * DIM) / 2);

    // 1) qkv = x @ Wqkv^T : M=4096, N=4096, K=2048
    mma_gemm<<<dim3(QKVD / 128, NTOK / 128), 256, GSMEM_TOTAL>>>(
        xh, wq, qkv, DIM, DIM, DIM, QKVD);

    // 2) RMSNorm + RoPE on Q,K (fp16 out)
    norm_rope<<<dim3(NTOK, NH + NKV), 64>>>(qkv, fcos, fsin, qw, kw, q, k);

    // 3) V transpose (fp16 out)
    vtrans<<<dim3(SEQ / 32, HD / 32, BSZ * NKV), dim3(32, 8)>>>(qkv, vt);

    // 4) fused attention -> att (fp16)
    flash_attn<<<dim3(SEQ / 128, BSZ * NH), 512, FSMEM_TOTAL>>>(
        q, k, vt, xmask, att, scale);

    // 5) out = att @ Wout^T : M=4096, N=2048, K=2048
    mma_gemm<<<dim3(DIM / 128, NTOK / 128), 256, GSMEM_TOTAL>>>(
        att, wo, out, DIM, DIM, DIM, DIM);
}

// round 9
// speedup vs baseline: 6.3277x; 1.0240x over previous
#include <cuda_runtime.h>
#include <cuda_fp16.h>
#include <math.h>
#include <stdint.h>

// Problem constants
#define BSZ 2
#define SEQ 2048
#define DIM 2048
#define NH 16
#define NKV 8
#define HD 128
#define QKVD 4096          // (16 + 2*8) * 128
#define NTOK (BSZ*SEQ)     // 4096

// ---------------- scratch (static __device__, no allocations) ----------------
static __device__ float  g_qkv[(size_t)NTOK * QKVD];                 // 64 MB fp32
static __device__ __half g_q  [(size_t)BSZ * NH  * SEQ * HD];        // 16 MB
static __device__ __half g_k  [(size_t)BSZ * NKV * SEQ * HD];        // 8 MB
static __device__ __half g_vt [(size_t)BSZ * NKV * HD  * SEQ];       // 8 MB
static __device__ __half g_att[(size_t)NTOK * DIM];                  // 16 MB
static __device__ __half g_xh [(size_t)NTOK * DIM];                  // 16 MB
static __device__ __half g_wq [(size_t)QKVD * DIM];                  // 16 MB
static __device__ __half g_wo [(size_t)DIM * DIM];                   // 8 MB

__device__ __forceinline__ uint32_t smem_u32(const void* p) {
    uint32_t a;
    asm("{ .reg .u64 t; cvta.to.shared.u64 t, %1; cvt.u32.u64 %0, t; }" : "=r"(a) : "l"(p));
    return a;
}

__device__ __forceinline__ void cpa16(uint32_t saddr, const void* g) {
    asm volatile("cp.async.cg.shared.global [%0], [%1], 16;" :: "r"(saddr), "l"(g));
}

#define MMA16816(acc, a0, a1, a2, a3, b0, b1) \
    asm volatile( \
        "mma.sync.aligned.m16n8k16.row.col.f32.f16.f16.f32 " \
        "{%0,%1,%2,%3}, {%4,%5,%6,%7}, {%8,%9}, {%0,%1,%2,%3};" \
        : "+f"((acc)[0]), "+f"((acc)[1]), "+f"((acc)[2]), "+f"((acc)[3]) \
        : "r"(a0), "r"(a1), "r"(a2), "r"(a3), "r"(b0), "r"(b1))

#define LDMX4(d, addr) \
    asm volatile("ldmatrix.sync.aligned.m8n8.x4.shared.b16 {%0,%1,%2,%3}, [%4];" \
        : "=r"((d)[0]), "=r"((d)[1]), "=r"((d)[2]), "=r"((d)[3]) : "r"(addr))

// ============================================================================
//          projection GEMM (QKV / out proj): C = A @ B^T, fp32 out
// ============================================================================
// CTA tile 128x64, 8 warps (4m x 2n), warp tile 32x32, K chunk 32,
// ldmatrix fragment loads, 3-stage cp.async ring, 4 CTAs/SM.
// smem stage: A 128 rows x 80B + B 64 rows x 80B = 15360 B
#define GROWB 80
#define GSTAGE_BYTES (192 * GROWB)           // 15360
#define GB_OFF (128 * GROWB)                 // 10240 (B tile offset in stage)
#define GSTAGES 3
#define GSMEM_TOTAL (GSTAGES * GSTAGE_BYTES) // 46080 B

__global__ __launch_bounds__(256, 4)
void mma_gemm(const __half* __restrict__ A, const __half* __restrict__ B, float* __restrict__ C,
              int K, int lda, int ldb, int ldc)
{
    extern __shared__ char smc[];
    uint32_t sbase = smem_u32(smc);

    int tid = threadIdx.x;
    int wid = tid >> 5, lane = tid & 31;
    int g = lane >> 2, t4 = lane & 3;
    int wm = wid & 3, wn = wid >> 2;
    int m0 = wm * 32, n0 = wn * 32;

    size_t bm = (size_t)blockIdx.y * 128;
    size_t bn = (size_t)blockIdx.x * 64;

    const int NC = K >> 5;

    float acc[2][4][4];
    #pragma unroll
    for (int i = 0; i < 2; i++)
        #pragma unroll
        for (int j = 0; j < 4; j++)
            #pragma unroll
            for (int r = 0; r < 4; r++) acc[i][j][r] = 0.0f;

    // ldmatrix per-lane base offsets (bytes within stage)
    int lr = lane & 7;
    uint32_t aoff = (uint32_t)((m0 + ((lane >> 3) & 1) * 8 + lr) * GROWB + (lane >> 4) * 16);
    uint32_t boff = (uint32_t)(GB_OFF + (n0 + (lane >> 4) * 8 + lr) * GROWB + ((lane >> 3) & 1) * 16);

    // loader coords
    int arow = tid >> 2, aseg = tid & 3;       // + 256 -> second A half
    int brow = tid >> 2, bseg = tid & 3;       // single pass covers 64 rows

    auto load_chunk = [&](int c, int st) {
        const __half* Ak = A + c * 32;
        const __half* Bk = B + c * 32;
        uint32_t sA = sbase + (uint32_t)st * GSTAGE_BYTES;
        #pragma unroll
        for (int i = 0; i < 2; i++) {
            int row = arow + i * 64;
            cpa16(sA + row * GROWB + aseg * 16, Ak + (bm + row) * (size_t)lda + aseg * 8);
        }
        cpa16(sA + GB_OFF + brow * GROWB + bseg * 16, Bk + (bn + brow) * (size_t)ldb + bseg * 8);
        asm volatile("cp.async.commit_group;" ::: "memory");
    };

    load_chunk(0, 0);
    if (NC > 1) load_chunk(1, 1);

    int st = 0;
    for (int c = 0; c < NC; c++) {
        if (c + 1 < NC) asm volatile("cp.async.wait_group 1;" ::: "memory");
        else            asm volatile("cp.async.wait_group 0;" ::: "memory");
        __syncthreads();

        if (c + 2 < NC) load_chunk(c + 2, (st + 2) % GSTAGES);

        uint32_t sg = sbase + (uint32_t)st * GSTAGE_BYTES;

        #pragma unroll
        for (int ks = 0; ks < 2; ks++) {
            uint32_t a[2][4], b[2][4];
            #pragma unroll
            for (int mt = 0; mt < 2; mt++)
                LDMX4(a[mt], sg + aoff + mt * (16 * GROWB) + ks * 32);
            #pragma unroll
            for (int np = 0; np < 2; np++)
                LDMX4(b[np], sg + boff + np * (16 * GROWB) + ks * 32);
            #pragma unroll
            for (int mt = 0; mt < 2; mt++)
                #pragma unroll
                for (int np = 0; np < 2; np++)
                    #pragma unroll
                    for (int j = 0; j < 2; j++)
                        MMA16816(acc[mt][np * 2 + j],
                                 a[mt][0], a[mt][1], a[mt][2], a[mt][3],
                                 b[np][j * 2], b[np][j * 2 + 1]);
        }
        st++; if (st == GSTAGES) st = 0;
    }

    #pragma unroll
    for (int mt = 0; mt < 2; mt++) {
        size_t row = bm + m0 + mt * 16 + g;
        #pragma unroll
        for (int nt = 0; nt < 4; nt++) {
            size_t col = bn + n0 + nt * 8 + 2 * t4;
            *(float2*)&C[row * (size_t)ldc + col] =
                make_float2(acc[mt][nt][0], acc[mt][nt][1]);
            *(float2*)&C[(row + 8) * (size_t)ldc + col] =
                make_float2(acc[mt][nt][2], acc[mt][nt][3]);
        }
    }
}

// ============================================================================
//      fused flash attention: S = Q K^T, P = exp(S*scale)*mask, out = P V / rowsum
// ============================================================================
#define QSTRIDE 68            // u32 per Q/K row (128 halves + 8 pad)
#define PSTRIDE 36            // u32 per P/V row (64 halves + 8 pad)
#define SM_Q    0
#define SM_P    34816         // 128*136*2
#define SM_ST   53248         // SM_P + 128*72*2
#define KV_STAGE_BYTES 35840  // K 64*136*2=17408 + V 128*72*2=18432
#define FSMEM_TOTAL (SM_ST + 4 * KV_STAGE_BYTES)   // 196608 B
#define NKVB (SEQ / 64)       // 32

__global__ __launch_bounds__(512, 1)
void flash_attn(const __half* __restrict__ q, const __half* __restrict__ k,
                const __half* __restrict__ vt, const int* __restrict__ mask,
                __half* __restrict__ att, float scale)
{
    extern __shared__ char smc[];
    uint32_t sbase = smem_u32(smc);

    int tid = threadIdx.x;
    int wid = tid >> 5, lane = tid & 31;
    int g = lane >> 2, t4 = lane & 3;
    int wm = wid & 3, wn = wid >> 2;

    int z  = blockIdx.y;
    size_t bm = (size_t)blockIdx.x * 128;

    const __half* Qg = q  + ((size_t)z * SEQ + bm) * HD;
    const __half* Kg = k  + (size_t)(z >> 1) * SEQ * HD;
    const __half* Vg = vt + (size_t)(z >> 1) * HD * SEQ;
    const int* mrow  = mask + (size_t)(z >> 4) * SEQ;

    const uint32_t* Qs = (const uint32_t*)(smc + SM_Q);
    uint32_t*       Ps = (uint32_t*)(smc + SM_P);

    float acc_o[2][4][4];
    #pragma unroll
    for (int i = 0; i < 2; i++)
        #pragma unroll
        for (int j = 0; j < 4; j++)
            #pragma unroll
            for (int r = 0; r < 4; r++) acc_o[i][j][r] = 0.0f;
    float rsum[2][2] = {};

    auto load_block = [&](int c, int st) {
        uint32_t sK = sbase + SM_ST + (uint32_t)st * KV_STAGE_BYTES;
        uint32_t sV = sK + 17408;
        #pragma unroll
        for (int i = 0; i < 2; i++) {
            int idx = tid + i * 512;
            int row = idx >> 4, seg = idx & 15;
            cpa16(sK + row * 272 + seg * 16, Kg + ((size_t)(c * 64 + row)) * HD + seg * 8);
        }
        #pragma unroll
        for (int i = 0; i < 2; i++) {
            int idx = tid + i * 512;
            int row = idx >> 3, seg = idx & 7;
            cpa16(sV + row * 144 + seg * 16, Vg + (size_t)row * SEQ + c * 64 + seg * 8);
        }
        asm volatile("cp.async.commit_group;" ::: "memory");
    };

    #pragma unroll
    for (int i = 0; i < 4; i++) {
        int idx = tid + i * 512;
        int row = idx >> 4, seg = idx & 15;
        cpa16(sbase + SM_Q + row * 272 + seg * 16, Qg + (size_t)row * HD + seg * 8);
    }
    load_block(0, 0);
    load_block(1, 1);
    load_block(2, 2);

    for (int c = 0; c < NKVB; c++) {
        int st = c & 3;
        int left = NKVB - 1 - c;
        if (left >= 2)      asm volatile("cp.async.wait_group 2;" ::: "memory");
        else if (left == 1) asm volatile("cp.async.wait_group 1;" ::: "memory");
        else                asm volatile("cp.async.wait_group 0;" ::: "memory");
        __syncthreads();

        const uint32_t* Ks = (const uint32_t*)(smc + SM_ST + st * KV_STAGE_BYTES);
        const uint32_t* Vs = (const uint32_t*)(smc + SM_ST + st * KV_STAGE_BYTES + 17408);

        // ---- S = Q (128x128) @ K^T (64x128) -> warp tile 32x16 ----
        float acc_s[2][2][4];
        #pragma unroll
        for (int i = 0; i < 2; i++)
            #pragma unroll
            for (int j = 0; j < 2; j++)
                #pragma unroll
                for (int r = 0; r < 4; r++) acc_s[i][j][r] = 0.0f;

        #pragma unroll
        for (int kt = 0; kt < 8; kt++) {
            int kb = kt * 8 + t4;
            uint32_t b0[2], b1[2];
            #pragma unroll
            for (int nt = 0; nt < 2; nt++) {
                const uint32_t* bp = Ks + (wn * 16 + nt * 8 + g) * QSTRIDE + kb;
                b0[nt] = bp[0];
                b1[nt] = bp[4];
            }
            #pragma unroll
            for (int mt = 0; mt < 2; mt++) {
                const uint32_t* ap = Qs + (wm * 32 + mt * 16 + g) * QSTRIDE + kb;
                uint32_t a0 = ap[0];
                uint32_t a1 = ap[8 * QSTRIDE];
                uint32_t a2 = ap[4];
                uint32_t a3 = ap[8 * QSTRIDE + 4];
                #pragma unroll
                for (int nt = 0; nt < 2; nt++)
                    MMA16816(acc_s[mt][nt], a0, a1, a2, a3, b0[nt], b1[nt]);
            }
        }

        // ---- exp * mask, rowsum accum, pack P to smem ----
        #pragma unroll
        for (int nt = 0; nt < 2; nt++) {
            int col0 = c * 64 + wn * 16 + nt * 8 + 2 * t4;
            float m0 = mrow[col0]     ? 1.0f : 0.0f;
            float m1 = mrow[col0 + 1] ? 1.0f : 0.0f;
            #pragma unroll
            for (int mt = 0; mt < 2; mt++) {
                float e0 = __expf(acc_s[mt][nt][0] * scale) * m0;
                float e1 = __expf(acc_s[mt][nt][1] * scale) * m1;
                float e2 = __expf(acc_s[mt][nt][2] * scale) * m0;
                float e3 = __expf(acc_s[mt][nt][3] * scale) * m1;
                rsum[mt][0] += e0 + e1;
                rsum[mt][1] += e2 + e3;
                int prow = wm * 32 + mt * 16 + g;
                int pcol = wn * 8 + nt * 4 + t4;
                __half2 h01 = __floats2half2_rn(e0, e1);
                __half2 h23 = __floats2half2_rn(e2, e3);
                Ps[prow * PSTRIDE + pcol]       = *(uint32_t*)&h01;
                Ps[(prow + 8) * PSTRIDE + pcol] = *(uint32_t*)&h23;
            }
        }

        if (c + 3 < NKVB) load_block(c + 3, (c + 3) & 3);

        __syncthreads();

        // ---- out += P (128x64) @ V^T (128x64) -> warp tile 32x32 ----
        #pragma unroll
        for (int kt = 0; kt < 4; kt++) {
            int kb = kt * 8 + t4;
            uint32_t b0[4], b1[4];
            #pragma unroll
            for (int nt = 0; nt < 4; nt++) {
                const uint32_t* bp = Vs + (wn * 32 + nt * 8 + g) * PSTRIDE + kb;
                b0[nt] = bp[0];
                b1[nt] = bp[4];
            }
            #pragma unroll
            for (int mt = 0; mt < 2; mt++) {
                const uint32_t* ap = Ps + (wm * 32 + mt * 16 + g) * PSTRIDE + kb;
                uint32_t a0 = ap[0];
                uint32_t a1 = ap[8 * PSTRIDE];
                uint32_t a2 = ap[4];
                uint32_t a3 = ap[8 * PSTRIDE + 4];
                #pragma unroll
                for (int nt = 0; nt < 4; nt++)
                    MMA16816(acc_o[mt][nt], a0, a1, a2, a3, b0[nt], b1[nt]);
            }
        }
    }

    // ---- rowsum reduce across wn warps, divide, store ----
    __syncthreads();
    float* red = (float*)(smc + SM_P);
    #pragma unroll
    for (int mt = 0; mt < 2; mt++) {
        #pragma unroll
        for (int h = 0; h < 2; h++) {
            float s = rsum[mt][h];
            s += __shfl_xor_sync(0xFFFFFFFFu, s, 1);
            s += __shfl_xor_sync(0xFFFFFFFFu, s, 2);
            rsum[mt][h] = s;
        }
    }
    if (t4 == 0) {
        #pragma unroll
        for (int mt = 0; mt < 2; mt++) {
            int r0 = wm * 32 + mt * 16 + g;
            red[r0 * 4 + wn]       = rsum[mt][0];
            red[(r0 + 8) * 4 + wn] = rsum[mt][1];
        }
    }
    __syncthreads();

    int b = z >> 4, h = z & 15;
    #pragma unroll
    for (int mt = 0; mt < 2; mt++) {
        int r0 = wm * 32 + mt * 16 + g;
        float t0 = red[r0 * 4] + red[r0 * 4 + 1] + red[r0 * 4 + 2] + red[r0 * 4 + 3];
        float t1 = red[(r0 + 8) * 4] + red[(r0 + 8) * 4 + 1] +
                   red[(r0 + 8) * 4 + 2] + red[(r0 + 8) * 4 + 3];
        float i0 = (t0 > 0.0f) ? (1.0f / t0) : 0.0f;
        float i1 = (t1 > 0.0f) ? (1.0f / t1) : 0.0f;
        size_t s0 = bm + r0;
        __half* d0 = att + ((size_t)b * SEQ + s0) * DIM + h * HD;
        __half* d1 = att + ((size_t)b * SEQ + s0 + 8) * DIM + h * HD;
        #pragma unroll
        for (int nt = 0; nt < 4; nt++) {
            int col = wn * 32 + nt * 8 + 2 * t4;
            *(__half2*)&d0[col] = __floats2half2_rn(acc_o[mt][nt][0] * i0, acc_o[mt][nt][1] * i0);
            *(__half2*)&d1[col] = __floats2half2_rn(acc_o[mt][nt][2] * i1, acc_o[mt][nt][3] * i1);
        }
    }
}

// ---------------- streaming fp32 -> fp16 ----------------
__global__ __launch_bounds__(256)
void tohalf(const float2* __restrict__ src, __half2* __restrict__ dst, int n2)
{
    int i = blockIdx.x * 256 + threadIdx.x;
    int stride = gridDim.x * 256;
    for (; i < n2; i += stride) {
        float2 v = src[i];
        dst[i] = __floats2half2_rn(v.x, v.y);
    }
}

// ---------------- RMSNorm + RoPE for Q and K heads (fp16 stores) ----------------
__global__ __launch_bounds__(64)
void norm_rope(const float* __restrict__ qkv,
               const float* __restrict__ cosb, const float* __restrict__ sinb,
               const float* __restrict__ qw, const float* __restrict__ kw,
               __half* __restrict__ q, __half* __restrict__ k)
{
    int tok = blockIdx.x;
    int h   = blockIdx.y;
    int i   = threadIdx.x;
    int b   = tok >> 11;
    int s   = tok & (SEQ - 1);

    const float* src = qkv + (size_t)tok * QKVD + h * HD;
    float x0 = src[2 * i];
    float x1 = src[2 * i + 1];

    float ss = x0 * x0 + x1 * x1;
    #pragma unroll
    for (int off = 16; off > 0; off >>= 1)
        ss += __shfl_xor_sync(0xFFFFFFFFu, ss, off);
    __shared__ float red[2];
    if ((i & 31) == 0) red[i >> 5] = ss;
    __syncthreads();
    float total = red[0] + red[1];

    float inv = rsqrtf(total * (1.0f / HD) + 1e-5f);
    const float* w = (h < NH) ? qw : kw;
    float y0 = x0 * inv * w[2 * i];
    float y1 = x1 * inv * w[2 * i + 1];

    float c  = cosb[(size_t)s * (HD / 2) + i];
    float sn = sinb[(size_t)s * (HD / 2) + i];
    float o0 = y0 * c - y1 * sn;
    float o1 = y0 * sn + y1 * c;

    __half* dst;
    if (h < NH)  dst = q + ((size_t)(b * NH + h) * SEQ + s) * HD;
    else         dst = k + ((size_t)(b * NKV + (h - NH)) * SEQ + s) * HD;
    *(__half2*)&dst[2 * i] = __floats2half2_rn(o0, o1);
}

// ---------------- V transpose (fp16 stores) ----------------
__global__ __launch_bounds__(256)
void vtrans(const float* __restrict__ qkv, __half* __restrict__ vt)
{
    __shared__ float tile[32][33];
    int zz = blockIdx.z;
    int b  = zz >> 3;
    int kh = zz & 7;
    int s0 = blockIdx.x * 32;
    int d0 = blockIdx.y * 32;

    #pragma unroll
    for (int j = 0; j < 4; j++) {
        int s = s0 + threadIdx.y + j * 8;
        tile[threadIdx.y + j * 8][threadIdx.x] =
            qkv[((size_t)(b * SEQ + s)) * QKVD + (NH + NKV) * HD + kh * HD + d0 + threadIdx.x];
    }
    __syncthreads();
    #pragma unroll
    for (int j = 0; j < 4; j++) {
        int d = d0 + threadIdx.y + j * 8;
        vt[((size_t)zz * HD + d) * SEQ + s0 + threadIdx.x] =
            __float2half_rn(tile[threadIdx.x][threadIdx.y + j * 8]);
    }
}

// ---------------- launch ----------------
extern "C" void kernel_launch(void* const* d_in, const int* in_sizes, int n_in,
                              void* d_out, int out_size)
{
    const float* x     = (const float*)d_in[0];
    const int*   xmask = (const int*)  d_in[1];
    const float* fcos  = (const float*)d_in[2];
    const float* fsin  = (const float*)d_in[3];
    const float* Wqkv  = (const float*)d_in[4];
    const float* Wout  = (const float*)d_in[5];
    const float* qw    = (const float*)d_in[6];
    const float* kw    = (const float*)d_in[7];
    float* out = (float*)d_out;

    float *qkv;
    __half *q, *k, *vt, *att, *xh, *wq, *wo;
    cudaGetSymbolAddress((void**)&qkv,  g_qkv);
    cudaGetSymbolAddress((void**)&q,    g_q);
    cudaGetSymbolAddress((void**)&k,    g_k);
    cudaGetSymbolAddress((void**)&vt,   g_vt);
    cudaGetSymbolAddress((void**)&att,  g_att);
    cudaGetSymbolAddress((void**)&xh,   g_xh);
    cudaGetSymbolAddress((void**)&wq,   g_wq);
    cudaGetSymbolAddress((void**)&wo,   g_wo);

    cudaFuncSetAttribute(mma_gemm, cudaFuncAttributeMaxDynamicSharedMemorySize, GSMEM_TOTAL);
    cudaFuncSetAttribute(flash_attn, cudaFuncAttributeMaxDynamicSharedMemorySize, FSMEM_TOTAL);

    float scale = rsqrtf((float)HD);

    // 0) convert raw GEMM inputs to fp16
    tohalf<<<1184, 256>>>((const float2*)x,    (__half2*)xh, (NTOK * DIM) / 2);
    tohalf<<<1184, 256>>>((const float2*)Wqkv, (__half2*)wq, (QKVD * DIM) / 2);
    tohalf<<<1184, 256>>>((const float2*)Wout, (__half2*)wo, (DIM * DIM) / 2);

    // 1) qkv = x @ Wqkv^T : M=4096, N=4096, K=2048
    mma_gemm<<<dim3(QKVD / 64, NTOK / 128), 256, GSMEM_TOTAL>>>(
        xh, wq, qkv, DIM, DIM, DIM, QKVD);

    // 2) RMSNorm + RoPE on Q,K (fp16 out)
    norm_rope<<<dim3(NTOK, NH + NKV), 64>>>(qkv, fcos, fsin, qw, kw, q, k);

    // 3) V transpose (fp16 out)
    vtrans<<<dim3(SEQ / 32, HD / 32, BSZ * NKV), dim3(32, 8)>>>(qkv, vt);

    // 4) fused attention -> att (fp16)
    flash_attn<<<dim3(SEQ / 128, BSZ * NH), 512, FSMEM_TOTAL>>>(
        q, k, vt, xmask, att, scale);

    // 5) out = att @ Wout^T : M=4096, N=2048, K=2048
    mma_gemm<<<dim3(DIM / 64, NTOK / 128), 256, GSMEM_TOTAL>>>(
        att, wo, out, DIM, DIM, DIM, DIM);
}

// round 10
// speedup vs baseline: 6.5472x; 1.0347x over previous
#include <cuda_runtime.h>
#include <cuda_fp16.h>
#include <math.h>
#include <stdint.h>

// Problem constants
#define BSZ 2
#define SEQ 2048
#define DIM 2048
#define NH 16
#define NKV 8
#define HD 128
#define QKVD 4096          // (16 + 2*8) * 128
#define NTOK (BSZ*SEQ)     // 4096

// ---------------- scratch (static __device__, no allocations) ----------------
static __device__ float  g_qkv[(size_t)NTOK * QKVD];                 // 64 MB fp32
static __device__ __half g_q  [(size_t)BSZ * NH  * SEQ * HD];        // 16 MB
static __device__ __half g_k  [(size_t)BSZ * NKV * SEQ * HD];        // 8 MB
static __device__ __half g_vt [(size_t)BSZ * NKV * HD  * SEQ];       // 8 MB
static __device__ __half g_att[(size_t)NTOK * DIM];                  // 16 MB
static __device__ __half g_xh [(size_t)NTOK * DIM];                  // 16 MB
static __device__ __half g_wq [(size_t)QKVD * DIM];                  // 16 MB
static __device__ __half g_wo [(size_t)DIM * DIM];                   // 8 MB

__device__ __forceinline__ uint32_t smem_u32(const void* p) {
    uint32_t a;
    asm("{ .reg .u64 t; cvta.to.shared.u64 t, %1; cvt.u32.u64 %0, t; }" : "=r"(a) : "l"(p));
    return a;
}

__device__ __forceinline__ void cpa16(uint32_t saddr, const void* g) {
    asm volatile("cp.async.cg.shared.global [%0], [%1], 16;" :: "r"(saddr), "l"(g));
}

#define MMA16816(acc, a0, a1, a2, a3, b0, b1) \
    asm volatile( \
        "mma.sync.aligned.m16n8k16.row.col.f32.f16.f16.f32 " \
        "{%0,%1,%2,%3}, {%4,%5,%6,%7}, {%8,%9}, {%0,%1,%2,%3};" \
        : "+f"((acc)[0]), "+f"((acc)[1]), "+f"((acc)[2]), "+f"((acc)[3]) \
        : "r"(a0), "r"(a1), "r"(a2), "r"(a3), "r"(b0), "r"(b1))

#define LDMX4(d, addr) \
    asm volatile("ldmatrix.sync.aligned.m8n8.x4.shared.b16 {%0,%1,%2,%3}, [%4];" \
        : "=r"((d)[0]), "=r"((d)[1]), "=r"((d)[2]), "=r"((d)[3]) : "r"(addr))

// ============================================================================
//          projection GEMM (QKV / out proj): C = A @ B^T, fp32 out
// ============================================================================
// CTA tile 128x128, 4 warps (2m x 2n), warp tile 64x64, K chunk 32,
// ldmatrix fragment loads, 3-stage cp.async ring, 3 CTAs/SM.
// crossbar: 32KB reads + 20KB writes per chunk (416 cyc) < 512 tensor cyc.
#define GROWB 80
#define GSTAGE_BYTES (256 * GROWB)           // A 128 rows + B 128 rows = 20480
#define GB_OFF (128 * GROWB)                 // 10240
#define GSTAGES 3
#define GSMEM_TOTAL (GSTAGES * GSTAGE_BYTES) // 61440 B

__global__ __launch_bounds__(128, 3)
void mma_gemm(const __half* __restrict__ A, const __half* __restrict__ B, float* __restrict__ C,
              int K, int lda, int ldb, int ldc)
{
    extern __shared__ char smc[];
    uint32_t sbase = smem_u32(smc);

    int tid = threadIdx.x;
    int wid = tid >> 5, lane = tid & 31;
    int g = lane >> 2, t4 = lane & 3;
    int wm = wid & 1, wn = wid >> 1;
    int m0 = wm * 64, n0 = wn * 64;

    size_t bm = (size_t)blockIdx.y * 128;
    size_t bn = (size_t)blockIdx.x * 128;

    const int NC = K >> 5;

    float acc[4][8][4];
    #pragma unroll
    for (int i = 0; i < 4; i++)
        #pragma unroll
        for (int j = 0; j < 8; j++)
            #pragma unroll
            for (int r = 0; r < 4; r++) acc[i][j][r] = 0.0f;

    // ldmatrix per-lane base offsets (bytes within stage)
    int lr = lane & 7;
    uint32_t aoff = (uint32_t)((m0 + ((lane >> 3) & 1) * 8 + lr) * GROWB + (lane >> 4) * 16);
    uint32_t boff = (uint32_t)(GB_OFF + (n0 + (lane >> 4) * 8 + lr) * GROWB + ((lane >> 3) & 1) * 16);

    int lrow = tid >> 2, lseg = tid & 3;

    auto load_chunk = [&](int c, int st) {
        const __half* Ak = A + c * 32;
        const __half* Bk = B + c * 32;
        uint32_t sA = sbase + (uint32_t)st * GSTAGE_BYTES;
        #pragma unroll
        for (int i = 0; i < 4; i++) {
            int row = lrow + i * 32;
            cpa16(sA + row * GROWB + lseg * 16, Ak + (bm + row) * (size_t)lda + lseg * 8);
            cpa16(sA + GB_OFF + row * GROWB + lseg * 16, Bk + (bn + row) * (size_t)ldb + lseg * 8);
        }
        asm volatile("cp.async.commit_group;" ::: "memory");
    };

    load_chunk(0, 0);
    if (NC > 1) load_chunk(1, 1);

    int st = 0;
    for (int c = 0; c < NC; c++) {
        if (c + 1 < NC) asm volatile("cp.async.wait_group 1;" ::: "memory");
        else            asm volatile("cp.async.wait_group 0;" ::: "memory");
        __syncthreads();

        if (c + 2 < NC) load_chunk(c + 2, (st + 2) % GSTAGES);

        uint32_t sg = sbase + (uint32_t)st * GSTAGE_BYTES;

        #pragma unroll
        for (int ks = 0; ks < 2; ks++) {
            uint32_t a[4][4];
            #pragma unroll
            for (int mt = 0; mt < 4; mt++)
                LDMX4(a[mt], sg + aoff + mt * (16 * GROWB) + ks * 32);
            #pragma unroll
            for (int np = 0; np < 4; np++) {
                uint32_t b[4];
                LDMX4(b, sg + boff + np * (16 * GROWB) + ks * 32);
                #pragma unroll
                for (int mt = 0; mt < 4; mt++) {
                    MMA16816(acc[mt][np * 2],
                             a[mt][0], a[mt][1], a[mt][2], a[mt][3], b[0], b[1]);
                    MMA16816(acc[mt][np * 2 + 1],
                             a[mt][0], a[mt][1], a[mt][2], a[mt][3], b[2], b[3]);
                }
            }
        }
        st++; if (st == GSTAGES) st = 0;
    }

    #pragma unroll
    for (int mt = 0; mt < 4; mt++) {
        size_t row = bm + m0 + mt * 16 + g;
        #pragma unroll
        for (int nt = 0; nt < 8; nt++) {
            size_t col = bn + n0 + nt * 8 + 2 * t4;
            *(float2*)&C[row * (size_t)ldc + col] =
                make_float2(acc[mt][nt][0], acc[mt][nt][1]);
            *(float2*)&C[(row + 8) * (size_t)ldc + col] =
                make_float2(acc[mt][nt][2], acc[mt][nt][3]);
        }
    }
}

// ============================================================================
//      fused flash attention: S = Q K^T, P = exp(S*scale)*mask, out = P V / rowsum
// ============================================================================
#define QSTRIDE 68            // u32 per Q/K row (128 halves + 8 pad)
#define PSTRIDE 36            // u32 per P/V row (64 halves + 8 pad)
#define SM_Q    0
#define SM_P    34816         // 128*136*2
#define SM_ST   53248         // SM_P + 128*72*2
#define KV_STAGE_BYTES 35840  // K 64*136*2=17408 + V 128*72*2=18432
#define FSMEM_TOTAL (SM_ST + 4 * KV_STAGE_BYTES)   // 196608 B
#define NKVB (SEQ / 64)       // 32

__global__ __launch_bounds__(512, 1)
void flash_attn(const __half* __restrict__ q, const __half* __restrict__ k,
                const __half* __restrict__ vt, const int* __restrict__ mask,
                __half* __restrict__ att, float scale)
{
    extern __shared__ char smc[];
    uint32_t sbase = smem_u32(smc);

    int tid = threadIdx.x;
    int wid = tid >> 5, lane = tid & 31;
    int g = lane >> 2, t4 = lane & 3;
    int wm = wid & 3, wn = wid >> 2;

    int z  = blockIdx.y;
    size_t bm = (size_t)blockIdx.x * 128;

    const __half* Qg = q  + ((size_t)z * SEQ + bm) * HD;
    const __half* Kg = k  + (size_t)(z >> 1) * SEQ * HD;
    const __half* Vg = vt + (size_t)(z >> 1) * HD * SEQ;
    const int* mrow  = mask + (size_t)(z >> 4) * SEQ;

    const uint32_t* Qs = (const uint32_t*)(smc + SM_Q);
    uint32_t*       Ps = (uint32_t*)(smc + SM_P);

    float acc_o[2][4][4];
    #pragma unroll
    for (int i = 0; i < 2; i++)
        #pragma unroll
        for (int j = 0; j < 4; j++)
            #pragma unroll
            for (int r = 0; r < 4; r++) acc_o[i][j][r] = 0.0f;
    float rsum[2][2] = {};

    auto load_block = [&](int c, int st) {
        uint32_t sK = sbase + SM_ST + (uint32_t)st * KV_STAGE_BYTES;
        uint32_t sV = sK + 17408;
        #pragma unroll
        for (int i = 0; i < 2; i++) {
            int idx = tid + i * 512;
            int row = idx >> 4, seg = idx & 15;
            cpa16(sK + row * 272 + seg * 16, Kg + ((size_t)(c * 64 + row)) * HD + seg * 8);
        }
        #pragma unroll
        for (int i = 0; i < 2; i++) {
            int idx = tid + i * 512;
            int row = idx >> 3, seg = idx & 7;
            cpa16(sV + row * 144 + seg * 16, Vg + (size_t)row * SEQ + c * 64 + seg * 8);
        }
        asm volatile("cp.async.commit_group;" ::: "memory");
    };

    #pragma unroll
    for (int i = 0; i < 4; i++) {
        int idx = tid + i * 512;
        int row = idx >> 4, seg = idx & 15;
        cpa16(sbase + SM_Q + row * 272 + seg * 16, Qg + (size_t)row * HD + seg * 8);
    }
    load_block(0, 0);
    load_block(1, 1);
    load_block(2, 2);

    for (int c = 0; c < NKVB; c++) {
        int st = c & 3;
        int left = NKVB - 1 - c;
        if (left >= 2)      asm volatile("cp.async.wait_group 2;" ::: "memory");
        else if (left == 1) asm volatile("cp.async.wait_group 1;" ::: "memory");
        else                asm volatile("cp.async.wait_group 0;" ::: "memory");
        __syncthreads();

        const uint32_t* Ks = (const uint32_t*)(smc + SM_ST + st * KV_STAGE_BYTES);
        const uint32_t* Vs = (const uint32_t*)(smc + SM_ST + st * KV_STAGE_BYTES + 17408);

        // ---- S = Q (128x128) @ K^T (64x128) -> warp tile 32x16 ----
        float acc_s[2][2][4];
        #pragma unroll
        for (int i = 0; i < 2; i++)
            #pragma unroll
            for (int j = 0; j < 2; j++)
                #pragma unroll
                for (int r = 0; r < 4; r++) acc_s[i][j][r] = 0.0f;

        #pragma unroll
        for (int kt = 0; kt < 8; kt++) {
            int kb = kt * 8 + t4;
            uint32_t b0[2], b1[2];
            #pragma unroll
            for (int nt = 0; nt < 2; nt++) {
                const uint32_t* bp = Ks + (wn * 16 + nt * 8 + g) * QSTRIDE + kb;
                b0[nt] = bp[0];
                b1[nt] = bp[4];
            }
            #pragma unroll
            for (int mt = 0; mt < 2; mt++) {
                const uint32_t* ap = Qs + (wm * 32 + mt * 16 + g) * QSTRIDE + kb;
                uint32_t a0 = ap[0];
                uint32_t a1 = ap[8 * QSTRIDE];
                uint32_t a2 = ap[4];
                uint32_t a3 = ap[8 * QSTRIDE + 4];
                #pragma unroll
                for (int nt = 0; nt < 2; nt++)
                    MMA16816(acc_s[mt][nt], a0, a1, a2, a3, b0[nt], b1[nt]);
            }
        }

        // ---- exp * mask, rowsum accum, pack P to smem ----
        #pragma unroll
        for (int nt = 0; nt < 2; nt++) {
            int col0 = c * 64 + wn * 16 + nt * 8 + 2 * t4;
            float m0 = mrow[col0]     ? 1.0f : 0.0f;
            float m1 = mrow[col0 + 1] ? 1.0f : 0.0f;
            #pragma unroll
            for (int mt = 0; mt < 2; mt++) {
                float e0 = __expf(acc_s[mt][nt][0] * scale) * m0;
                float e1 = __expf(acc_s[mt][nt][1] * scale) * m1;
                float e2 = __expf(acc_s[mt][nt][2] * scale) * m0;
                float e3 = __expf(acc_s[mt][nt][3] * scale) * m1;
                rsum[mt][0] += e0 + e1;
                rsum[mt][1] += e2 + e3;
                int prow = wm * 32 + mt * 16 + g;
                int pcol = wn * 8 + nt * 4 + t4;
                __half2 h01 = __floats2half2_rn(e0, e1);
                __half2 h23 = __floats2half2_rn(e2, e3);
                Ps[prow * PSTRIDE + pcol]       = *(uint32_t*)&h01;
                Ps[(prow + 8) * PSTRIDE + pcol] = *(uint32_t*)&h23;
            }
        }

        if (c + 3 < NKVB) load_block(c + 3, (c + 3) & 3);

        __syncthreads();

        // ---- out += P (128x64) @ V^T (128x64) -> warp tile 32x32 ----
        #pragma unroll
        for (int kt = 0; kt < 4; kt++) {
            int kb = kt * 8 + t4;
            uint32_t b0[4], b1[4];
            #pragma unroll
            for (int nt = 0; nt < 4; nt++) {
                const uint32_t* bp = Vs + (wn * 32 + nt * 8 + g) * PSTRIDE + kb;
                b0[nt] = bp[0];
                b1[nt] = bp[4];
            }
            #pragma unroll
            for (int mt = 0; mt < 2; mt++) {
                const uint32_t* ap = Ps + (wm * 32 + mt * 16 + g) * PSTRIDE + kb;
                uint32_t a0 = ap[0];
                uint32_t a1 = ap[8 * PSTRIDE];
                uint32_t a2 = ap[4];
                uint32_t a3 = ap[8 * PSTRIDE + 4];
                #pragma unroll
                for (int nt = 0; nt < 4; nt++)
                    MMA16816(acc_o[mt][nt], a0, a1, a2, a3, b0[nt], b1[nt]);
            }
        }
    }

    // ---- rowsum reduce across wn warps, divide, store ----
    __syncthreads();
    float* red = (float*)(smc + SM_P);
    #pragma unroll
    for (int mt = 0; mt < 2; mt++) {
        #pragma unroll
        for (int h = 0; h < 2; h++) {
            float s = rsum[mt][h];
            s += __shfl_xor_sync(0xFFFFFFFFu, s, 1);
            s += __shfl_xor_sync(0xFFFFFFFFu, s, 2);
            rsum[mt][h] = s;
        }
    }
    if (t4 == 0) {
        #pragma unroll
        for (int mt = 0; mt < 2; mt++) {
            int r0 = wm * 32 + mt * 16 + g;
            red[r0 * 4 + wn]       = rsum[mt][0];
            red[(r0 + 8) * 4 + wn] = rsum[mt][1];
        }
    }
    __syncthreads();

    int b = z >> 4, h = z & 15;
    #pragma unroll
    for (int mt = 0; mt < 2; mt++) {
        int r0 = wm * 32 + mt * 16 + g;
        float t0 = red[r0 * 4] + red[r0 * 4 + 1] + red[r0 * 4 + 2] + red[r0 * 4 + 3];
        float t1 = red[(r0 + 8) * 4] + red[(r0 + 8) * 4 + 1] +
                   red[(r0 + 8) * 4 + 2] + red[(r0 + 8) * 4 + 3];
        float i0 = (t0 > 0.0f) ? (1.0f / t0) : 0.0f;
        float i1 = (t1 > 0.0f) ? (1.0f / t1) : 0.0f;
        size_t s0 = bm + r0;
        __half* d0 = att + ((size_t)b * SEQ + s0) * DIM + h * HD;
        __half* d1 = att + ((size_t)b * SEQ + s0 + 8) * DIM + h * HD;
        #pragma unroll
        for (int nt = 0; nt < 4; nt++) {
            int col = wn * 32 + nt * 8 + 2 * t4;
            *(__half2*)&d0[col] = __floats2half2_rn(acc_o[mt][nt][0] * i0, acc_o[mt][nt][1] * i0);
            *(__half2*)&d1[col] = __floats2half2_rn(acc_o[mt][nt][2] * i1, acc_o[mt][nt][3] * i1);
        }
    }
}

// ---------------- streaming fp32 -> fp16 ----------------
__global__ __launch_bounds__(256)
void tohalf(const float2* __restrict__ src, __half2* __restrict__ dst, int n2)
{
    int i = blockIdx.x * 256 + threadIdx.x;
    int stride = gridDim.x * 256;
    for (; i < n2; i += stride) {
        float2 v = src[i];
        dst[i] = __floats2half2_rn(v.x, v.y);
    }
}

// ---------------- RMSNorm + RoPE for Q and K heads (fp16 stores) ----------------
__global__ __launch_bounds__(64)
void norm_rope(const float* __restrict__ qkv,
               const float* __restrict__ cosb, const float* __restrict__ sinb,
               const float* __restrict__ qw, const float* __restrict__ kw,
               __half* __restrict__ q, __half* __restrict__ k)
{
    int tok = blockIdx.x;
    int h   = blockIdx.y;
    int i   = threadIdx.x;
    int b   = tok >> 11;
    int s   = tok & (SEQ - 1);

    const float* src = qkv + (size_t)tok * QKVD + h * HD;
    float x0 = src[2 * i];
    float x1 = src[2 * i + 1];

    float ss = x0 * x0 + x1 * x1;
    #pragma unroll
    for (int off = 16; off > 0; off >>= 1)
        ss += __shfl_xor_sync(0xFFFFFFFFu, ss, off);
    __shared__ float red[2];
    if ((i & 31) == 0) red[i >> 5] = ss;
    __syncthreads();
    float total = red[0] + red[1];

    float inv = rsqrtf(total * (1.0f / HD) + 1e-5f);
    const float* w = (h < NH) ? qw : kw;
    float y0 = x0 * inv * w[2 * i];
    float y1 = x1 * inv * w[2 * i + 1];

    float c  = cosb[(size_t)s * (HD / 2) + i];
    float sn = sinb[(size_t)s * (HD / 2) + i];
    float o0 = y0 * c - y1 * sn;
    float o1 = y0 * sn + y1 * c;

    __half* dst;
    if (h < NH)  dst = q + ((size_t)(b * NH + h) * SEQ + s) * HD;
    else         dst = k + ((size_t)(b * NKV + (h - NH)) * SEQ + s) * HD;
    *(__half2*)&dst[2 * i] = __floats2half2_rn(o0, o1);
}

// ---------------- V transpose (fp16 stores) ----------------
__global__ __launch_bounds__(256)
void vtrans(const float* __restrict__ qkv, __half* __restrict__ vt)
{
    __shared__ float tile[32][33];
    int zz = blockIdx.z;
    int b  = zz >> 3;
    int kh = zz & 7;
    int s0 = blockIdx.x * 32;
    int d0 = blockIdx.y * 32;

    #pragma unroll
    for (int j = 0; j < 4; j++) {
        int s = s0 + threadIdx.y + j * 8;
        tile[threadIdx.y + j * 8][threadIdx.x] =
            qkv[((size_t)(b * SEQ + s)) * QKVD + (NH + NKV) * HD + kh * HD + d0 + threadIdx.x];
    }
    __syncthreads();
    #pragma unroll
    for (int j = 0; j < 4; j++) {
        int d = d0 + threadIdx.y + j * 8;
        vt[((size_t)zz * HD + d) * SEQ + s0 + threadIdx.x] =
            __float2half_rn(tile[threadIdx.x][threadIdx.y + j * 8]);
    }
}

// ---------------- launch ----------------
extern "C" void kernel_launch(void* const* d_in, const int* in_sizes, int n_in,
                              void* d_out, int out_size)
{
    const float* x     = (const float*)d_in[0];
    const int*   xmask = (const int*)  d_in[1];
    const float* fcos  = (const float*)d_in[2];
    const float* fsin  = (const float*)d_in[3];
    const float* Wqkv  = (const float*)d_in[4];
    const float* Wout  = (const float*)d_in[5];
    const float* qw    = (const float*)d_in[6];
    const float* kw    = (const float*)d_in[7];
    float* out = (float*)d_out;

    float *qkv;
    __half *q, *k, *vt, *att, *xh, *wq, *wo;
    cudaGetSymbolAddress((void**)&qkv,  g_qkv);
    cudaGetSymbolAddress((void**)&q,    g_q);
    cudaGetSymbolAddress((void**)&k,    g_k);
    cudaGetSymbolAddress((void**)&vt,   g_vt);
    cudaGetSymbolAddress((void**)&att,  g_att);
    cudaGetSymbolAddress((void**)&xh,   g_xh);
    cudaGetSymbolAddress((void**)&wq,   g_wq);
    cudaGetSymbolAddress((void**)&wo,   g_wo);

    cudaFuncSetAttribute(mma_gemm, cudaFuncAttributeMaxDynamicSharedMemorySize, GSMEM_TOTAL);
    cudaFuncSetAttribute(flash_attn, cudaFuncAttributeMaxDynamicSharedMemorySize, FSMEM_TOTAL);

    float scale = rsqrtf((float)HD);

    // 0) convert raw GEMM inputs to fp16
    tohalf<<<1184, 256>>>((const float2*)x,    (__half2*)xh, (NTOK * DIM) / 2);
    tohalf<<<1184, 256>>>((const float2*)Wqkv, (__half2*)wq, (QKVD * DIM) / 2);
    tohalf<<<1184, 256>>>((const float2*)Wout, (__half2*)wo, (DIM * DIM) / 2);

    // 1) qkv = x @ Wqkv^T : M=4096, N=4096, K=2048
    mma_gemm<<<dim3(QKVD / 128, NTOK / 128), 128, GSMEM_TOTAL>>>(
        xh, wq, qkv, DIM, DIM, DIM, QKVD);

    // 2) RMSNorm + RoPE on Q,K (fp16 out)
    norm_rope<<<dim3(NTOK, NH + NKV), 64>>>(qkv, fcos, fsin, qw, kw, q, k);

    // 3) V transpose (fp16 out)
    vtrans<<<dim3(SEQ / 32, HD / 32, BSZ * NKV), dim3(32, 8)>>>(qkv, vt);

    // 4) fused attention -> att (fp16)
    flash_attn<<<dim3(SEQ / 128, BSZ * NH), 512, FSMEM_TOTAL>>>(
        q, k, vt, xmask, att, scale);

    // 5) out = att @ Wout^T : M=4096, N=2048, K=2048
    mma_gemm<<<dim3(DIM / 128, NTOK / 128), 128, GSMEM_TOTAL>>>(
        att, wo, out, DIM, DIM, DIM, DIM);
}

// round 11
// speedup vs baseline: 7.1500x; 1.0921x over previous
#include <cuda_runtime.h>
#include <cuda_fp16.h>
#include <math.h>
#include <stdint.h>

// Problem constants
#define BSZ 2
#define SEQ 2048
#define DIM 2048
#define NH 16
#define NKV 8
#define HD 128
#define QKVD 4096          // (16 + 2*8) * 128
#define NTOK (BSZ*SEQ)     // 4096

// ---------------- scratch (static __device__, no allocations) ----------------
static __device__ float  g_qkv[(size_t)NTOK * QKVD];                 // 64 MB fp32
static __device__ __half g_q  [(size_t)BSZ * NH  * SEQ * HD];        // 16 MB
static __device__ __half g_k  [(size_t)BSZ * NKV * SEQ * HD];        // 8 MB
static __device__ __half g_vt [(size_t)BSZ * NKV * HD  * SEQ];       // 8 MB
static __device__ __half g_att[(size_t)NTOK * DIM];                  // 16 MB
static __device__ __half g_xh [(size_t)NTOK * DIM];                  // 16 MB
static __device__ __half g_wq [(size_t)QKVD * DIM];                  // 16 MB
static __device__ __half g_wo [(size_t)DIM * DIM];                   // 8 MB

__device__ __forceinline__ uint32_t smem_u32(const void* p) {
    uint32_t a;
    asm("{ .reg .u64 t; cvta.to.shared.u64 t, %1; cvt.u32.u64 %0, t; }" : "=r"(a) : "l"(p));
    return a;
}

__device__ __forceinline__ void cpa16(uint32_t saddr, const void* g) {
    asm volatile("cp.async.cg.shared.global [%0], [%1], 16;" :: "r"(saddr), "l"(g));
}

#define MMA16816(acc, a0, a1, a2, a3, b0, b1) \
    asm volatile( \
        "mma.sync.aligned.m16n8k16.row.col.f32.f16.f16.f32 " \
        "{%0,%1,%2,%3}, {%4,%5,%6,%7}, {%8,%9}, {%0,%1,%2,%3};" \
        : "+f"((acc)[0]), "+f"((acc)[1]), "+f"((acc)[2]), "+f"((acc)[3]) \
        : "r"(a0), "r"(a1), "r"(a2), "r"(a3), "r"(b0), "r"(b1))

#define LDMX4(d, addr) \
    asm volatile("ldmatrix.sync.aligned.m8n8.x4.shared.b16 {%0,%1,%2,%3}, [%4];" \
        : "=r"((d)[0]), "=r"((d)[1]), "=r"((d)[2]), "=r"((d)[3]) : "r"(addr))

// ============================================================================
//          projection GEMM (QKV / out proj): C = A @ B^T, fp32 out
// ============================================================================
#define GROWB 80
#define GSTAGE_BYTES (256 * GROWB)           // A 128 rows + B 128 rows = 20480
#define GB_OFF (128 * GROWB)                 // 10240
#define GSTAGES 3
#define GSMEM_TOTAL (GSTAGES * GSTAGE_BYTES) // 61440 B

__global__ __launch_bounds__(128, 3)
void mma_gemm(const __half* __restrict__ A, const __half* __restrict__ B, float* __restrict__ C,
              int K, int lda, int ldb, int ldc)
{
    extern __shared__ char smc[];
    uint32_t sbase = smem_u32(smc);

    int tid = threadIdx.x;
    int wid = tid >> 5, lane = tid & 31;
    int g = lane >> 2, t4 = lane & 3;
    int wm = wid & 1, wn = wid >> 1;
    int m0 = wm * 64, n0 = wn * 64;

    size_t bm = (size_t)blockIdx.y * 128;
    size_t bn = (size_t)blockIdx.x * 128;

    const int NC = K >> 5;

    float acc[4][8][4];
    #pragma unroll
    for (int i = 0; i < 4; i++)
        #pragma unroll
        for (int j = 0; j < 8; j++)
            #pragma unroll
            for (int r = 0; r < 4; r++) acc[i][j][r] = 0.0f;

    int lr = lane & 7;
    uint32_t aoff = (uint32_t)((m0 + ((lane >> 3) & 1) * 8 + lr) * GROWB + (lane >> 4) * 16);
    uint32_t boff = (uint32_t)(GB_OFF + (n0 + (lane >> 4) * 8 + lr) * GROWB + ((lane >> 3) & 1) * 16);

    int lrow = tid >> 2, lseg = tid & 3;

    auto load_chunk = [&](int c, int st) {
        const __half* Ak = A + c * 32;
        const __half* Bk = B + c * 32;
        uint32_t sA = sbase + (uint32_t)st * GSTAGE_BYTES;
        #pragma unroll
        for (int i = 0; i < 4; i++) {
            int row = lrow + i * 32;
            cpa16(sA + row * GROWB + lseg * 16, Ak + (bm + row) * (size_t)lda + lseg * 8);
            cpa16(sA + GB_OFF + row * GROWB + lseg * 16, Bk + (bn + row) * (size_t)ldb + lseg * 8);
        }
        asm volatile("cp.async.commit_group;" ::: "memory");
    };

    load_chunk(0, 0);
    if (NC > 1) load_chunk(1, 1);

    int st = 0;
    for (int c = 0; c < NC; c++) {
        if (c + 1 < NC) asm volatile("cp.async.wait_group 1;" ::: "memory");
        else            asm volatile("cp.async.wait_group 0;" ::: "memory");
        __syncthreads();

        if (c + 2 < NC) load_chunk(c + 2, (st + 2) % GSTAGES);

        uint32_t sg = sbase + (uint32_t)st * GSTAGE_BYTES;

        #pragma unroll
        for (int ks = 0; ks < 2; ks++) {
            uint32_t a[4][4];
            #pragma unroll
            for (int mt = 0; mt < 4; mt++)
                LDMX4(a[mt], sg + aoff + mt * (16 * GROWB) + ks * 32);
            #pragma unroll
            for (int np = 0; np < 4; np++) {
                uint32_t b[4];
                LDMX4(b, sg + boff + np * (16 * GROWB) + ks * 32);
                #pragma unroll
                for (int mt = 0; mt < 4; mt++) {
                    MMA16816(acc[mt][np * 2],
                             a[mt][0], a[mt][1], a[mt][2], a[mt][3], b[0], b[1]);
                    MMA16816(acc[mt][np * 2 + 1],
                             a[mt][0], a[mt][1], a[mt][2], a[mt][3], b[2], b[3]);
                }
            }
        }
        st++; if (st == GSTAGES) st = 0;
    }

    #pragma unroll
    for (int mt = 0; mt < 4; mt++) {
        size_t row = bm + m0 + mt * 16 + g;
        #pragma unroll
        for (int nt = 0; nt < 8; nt++) {
            size_t col = bn + n0 + nt * 8 + 2 * t4;
            *(float2*)&C[row * (size_t)ldc + col] =
                make_float2(acc[mt][nt][0], acc[mt][nt][1]);
            *(float2*)&C[(row + 8) * (size_t)ldc + col] =
                make_float2(acc[mt][nt][2], acc[mt][nt][3]);
        }
    }
}

// ============================================================================
//  fused flash attention (kv-block 128, ldmatrix, warp 32x32 S and PV)
// ============================================================================
// 512 threads, 16 warps 4m x 4n over a 128q x 128kv block. 2-stage K+V ring.
// rows everywhere: 128 halves + 8 pad = 272 B (conflict-free ldmatrix).
#define FRB  272              // row bytes
#define FRU  68               // row u32
#define SM_Q   0
#define SM_P   34816
#define SM_KV  69632
#define KV_STG 69632          // K 34816 + V 34816
#define FSMEM_TOTAL (SM_KV + 2 * KV_STG)   // 208896 B
#define NKVB (SEQ / 128)      // 16

__global__ __launch_bounds__(512, 1)
void flash_attn(const __half* __restrict__ q, const __half* __restrict__ k,
                const __half* __restrict__ vt, const int* __restrict__ mask,
                __half* __restrict__ att, float scale)
{
    extern __shared__ char smc[];
    uint32_t sbase = smem_u32(smc);

    int tid = threadIdx.x;
    int wid = tid >> 5, lane = tid & 31;
    int g = lane >> 2, t4 = lane & 3, lr = lane & 7;
    int wm = wid & 3, wn = wid >> 2;
    int m0 = wm * 32, n0 = wn * 32;

    int z  = blockIdx.y;
    size_t bm = (size_t)blockIdx.x * 128;

    const __half* Qg = q  + ((size_t)z * SEQ + bm) * HD;
    const __half* Kg = k  + (size_t)(z >> 1) * SEQ * HD;
    const __half* Vg = vt + (size_t)(z >> 1) * HD * SEQ;
    const int* mrow  = mask + (size_t)(z >> 4) * SEQ;

    // ldmatrix per-lane base offsets (bytes within a 128-row, 272B-stride tile)
    uint32_t a_base = (uint32_t)((m0 + ((lane >> 3) & 1) * 8 + lr) * FRB + (lane >> 4) * 16);
    uint32_t b_base = (uint32_t)((n0 + (lane >> 4) * 8 + lr) * FRB + ((lane >> 3) & 1) * 16);

    float acc_o[2][4][4];
    #pragma unroll
    for (int i = 0; i < 2; i++)
        #pragma unroll
        for (int j = 0; j < 4; j++)
            #pragma unroll
            for (int r = 0; r < 4; r++) acc_o[i][j][r] = 0.0f;
    float rsum[2][2] = {};

    auto load_stage = [&](int c, int st) {
        uint32_t sK = sbase + SM_KV + (uint32_t)st * KV_STG;
        uint32_t sV = sK + 34816;
        #pragma unroll
        for (int i = 0; i < 4; i++) {
            int idx = tid + i * 512;
            int row = idx >> 4, seg = idx & 15;
            cpa16(sK + row * FRB + seg * 16, Kg + ((size_t)(c * 128 + row)) * HD + seg * 8);
            cpa16(sV + row * FRB + seg * 16, Vg + (size_t)row * SEQ + c * 128 + seg * 8);
        }
        asm volatile("cp.async.commit_group;" ::: "memory");
    };

    // Q load (folded into stage-0's commit group)
    #pragma unroll
    for (int i = 0; i < 4; i++) {
        int idx = tid + i * 512;
        int row = idx >> 4, seg = idx & 15;
        cpa16(sbase + SM_Q + row * FRB + seg * 16, Qg + (size_t)row * HD + seg * 8);
    }
    load_stage(0, 0);

    for (int c = 0; c < NKVB; c++) {
        int st = c & 1;
        asm volatile("cp.async.wait_group 0;" ::: "memory");
        __syncthreads();   // stage st ready; PV(c-1) done (stage st^1 + P free)

        if (c + 1 < NKVB) load_stage(c + 1, st ^ 1);

        uint32_t sQ = sbase + SM_Q;
        uint32_t sK = sbase + SM_KV + (uint32_t)st * KV_STG;
        uint32_t sV = sK + 34816;
        uint32_t sP = sbase + SM_P;

        // ---- S = Q (128x128) @ K^T (128x128), warp tile 32x32 ----
        float acc_s[2][4][4];
        #pragma unroll
        for (int i = 0; i < 2; i++)
            #pragma unroll
            for (int j = 0; j < 4; j++)
                #pragma unroll
                for (int r = 0; r < 4; r++) acc_s[i][j][r] = 0.0f;

        #pragma unroll
        for (int kt = 0; kt < 8; kt++) {
            uint32_t a[2][4], b[2][4];
            LDMX4(a[0], sQ + a_base + kt * 32);
            LDMX4(a[1], sQ + a_base + 16 * FRB + kt * 32);
            LDMX4(b[0], sK + b_base + kt * 32);
            LDMX4(b[1], sK + b_base + 16 * FRB + kt * 32);
            #pragma unroll
            for (int mt = 0; mt < 2; mt++)
                #pragma unroll
                for (int np = 0; np < 2; np++) {
                    MMA16816(acc_s[mt][np * 2],
                             a[mt][0], a[mt][1], a[mt][2], a[mt][3], b[np][0], b[np][1]);
                    MMA16816(acc_s[mt][np * 2 + 1],
                             a[mt][0], a[mt][1], a[mt][2], a[mt][3], b[np][2], b[np][3]);
                }
        }

        // ---- exp * mask, rowsum accum, pack P to smem ----
        uint32_t* Ps = (uint32_t*)(smc + SM_P);
        #pragma unroll
        for (int nb = 0; nb < 4; nb++) {
            int col0 = c * 128 + n0 + nb * 8 + 2 * t4;
            float mk0 = mrow[col0]     ? 1.0f : 0.0f;
            float mk1 = mrow[col0 + 1] ? 1.0f : 0.0f;
            #pragma unroll
            for (int mt = 0; mt < 2; mt++) {
                float e0 = __expf(acc_s[mt][nb][0] * scale) * mk0;
                float e1 = __expf(acc_s[mt][nb][1] * scale) * mk1;
                float e2 = __expf(acc_s[mt][nb][2] * scale) * mk0;
                float e3 = __expf(acc_s[mt][nb][3] * scale) * mk1;
                rsum[mt][0] += e0 + e1;
                rsum[mt][1] += e2 + e3;
                int prow = m0 + mt * 16 + g;
                int pcol = wn * 16 + nb * 4 + t4;
                __half2 h01 = __floats2half2_rn(e0, e1);
                __half2 h23 = __floats2half2_rn(e2, e3);
                Ps[prow * FRU + pcol]       = *(uint32_t*)&h01;
                Ps[(prow + 8) * FRU + pcol] = *(uint32_t*)&h23;
            }
        }
        __syncthreads();   // P visible

        // ---- out += P (128x128) @ V^T (128x128 hd), warp tile 32x32 ----
        #pragma unroll
        for (int kt = 0; kt < 8; kt++) {
            uint32_t a[2][4], b[2][4];
            LDMX4(a[0], sP + a_base + kt * 32);
            LDMX4(a[1], sP + a_base + 16 * FRB + kt * 32);
            LDMX4(b[0], sV + b_base + kt * 32);
            LDMX4(b[1], sV + b_base + 16 * FRB + kt * 32);
            #pragma unroll
            for (int mt = 0; mt < 2; mt++)
                #pragma unroll
                for (int np = 0; np < 2; np++) {
                    MMA16816(acc_o[mt][np * 2],
                             a[mt][0], a[mt][1], a[mt][2], a[mt][3], b[np][0], b[np][1]);
                    MMA16816(acc_o[mt][np * 2 + 1],
                             a[mt][0], a[mt][1], a[mt][2], a[mt][3], b[np][2], b[np][3]);
                }
        }
    }

    // ---- rowsum reduce across wn warps, divide, store ----
    __syncthreads();
    float* red = (float*)(smc + SM_P);
    #pragma unroll
    for (int mt = 0; mt < 2; mt++) {
        #pragma unroll
        for (int h = 0; h < 2; h++) {
            float s = rsum[mt][h];
            s += __shfl_xor_sync(0xFFFFFFFFu, s, 1);
            s += __shfl_xor_sync(0xFFFFFFFFu, s, 2);
            rsum[mt][h] = s;
        }
    }
    if (t4 == 0) {
        #pragma unroll
        for (int mt = 0; mt < 2; mt++) {
            int r0 = m0 + mt * 16 + g;
            red[r0 * 4 + wn]       = rsum[mt][0];
            red[(r0 + 8) * 4 + wn] = rsum[mt][1];
        }
    }
    __syncthreads();

    int b = z >> 4, h = z & 15;
    #pragma unroll
    for (int mt = 0; mt < 2; mt++) {
        int r0 = m0 + mt * 16 + g;
        float t0 = red[r0 * 4] + red[r0 * 4 + 1] + red[r0 * 4 + 2] + red[r0 * 4 + 3];
        float t1 = red[(r0 + 8) * 4] + red[(r0 + 8) * 4 + 1] +
                   red[(r0 + 8) * 4 + 2] + red[(r0 + 8) * 4 + 3];
        float i0 = (t0 > 0.0f) ? (1.0f / t0) : 0.0f;
        float i1 = (t1 > 0.0f) ? (1.0f / t1) : 0.0f;
        size_t s0 = bm + r0;
        __half* d0 = att + ((size_t)b * SEQ + s0) * DIM + h * HD;
        __half* d1 = att + ((size_t)b * SEQ + s0 + 8) * DIM + h * HD;
        #pragma unroll
        for (int nt = 0; nt < 4; nt++) {
            int col = n0 + nt * 8 + 2 * t4;
            *(__half2*)&d0[col] = __floats2half2_rn(acc_o[mt][nt][0] * i0, acc_o[mt][nt][1] * i0);
            *(__half2*)&d1[col] = __floats2half2_rn(acc_o[mt][nt][2] * i1, acc_o[mt][nt][3] * i1);
        }
    }
}

// ---------------- streaming fp32 -> fp16 ----------------
__global__ __launch_bounds__(256)
void tohalf(const float2* __restrict__ src, __half2* __restrict__ dst, int n2)
{
    int i = blockIdx.x * 256 + threadIdx.x;
    int stride = gridDim.x * 256;
    for (; i < n2; i += stride) {
        float2 v = src[i];
        dst[i] = __floats2half2_rn(v.x, v.y);
    }
}

// ---------------- RMSNorm + RoPE for Q and K heads (fp16 stores) ----------------
__global__ __launch_bounds__(64)
void norm_rope(const float* __restrict__ qkv,
               const float* __restrict__ cosb, const float* __restrict__ sinb,
               const float* __restrict__ qw, const float* __restrict__ kw,
               __half* __restrict__ q, __half* __restrict__ k)
{
    int tok = blockIdx.x;
    int h   = blockIdx.y;
    int i   = threadIdx.x;
    int b   = tok >> 11;
    int s   = tok & (SEQ - 1);

    const float* src = qkv + (size_t)tok * QKVD + h * HD;
    float x0 = src[2 * i];
    float x1 = src[2 * i + 1];

    float ss = x0 * x0 + x1 * x1;
    #pragma unroll
    for (int off = 16; off > 0; off >>= 1)
        ss += __shfl_xor_sync(0xFFFFFFFFu, ss, off);
    __shared__ float red[2];
    if ((i & 31) == 0) red[i >> 5] = ss;
    __syncthreads();
    float total = red[0] + red[1];

    float inv = rsqrtf(total * (1.0f / HD) + 1e-5f);
    const float* w = (h < NH) ? qw : kw;
    float y0 = x0 * inv * w[2 * i];
    float y1 = x1 * inv * w[2 * i + 1];

    float c  = cosb[(size_t)s * (HD / 2) + i];
    float sn = sinb[(size_t)s * (HD / 2) + i];
    float o0 = y0 * c - y1 * sn;
    float o1 = y0 * sn + y1 * c;

    __half* dst;
    if (h < NH)  dst = q + ((size_t)(b * NH + h) * SEQ + s) * HD;
    else         dst = k + ((size_t)(b * NKV + (h - NH)) * SEQ + s) * HD;
    *(__half2*)&dst[2 * i] = __floats2half2_rn(o0, o1);
}

// ---------------- V transpose (fp16 stores) ----------------
__global__ __launch_bounds__(256)
void vtrans(const float* __restrict__ qkv, __half* __restrict__ vt)
{
    __shared__ float tile[32][33];
    int zz = blockIdx.z;
    int b  = zz >> 3;
    int kh = zz & 7;
    int s0 = blockIdx.x * 32;
    int d0 = blockIdx.y * 32;

    #pragma unroll
    for (int j = 0; j < 4; j++) {
        int s = s0 + threadIdx.y + j * 8;
        tile[threadIdx.y + j * 8][threadIdx.x] =
            qkv[((size_t)(b * SEQ + s)) * QKVD + (NH + NKV) * HD + kh * HD + d0 + threadIdx.x];
    }
    __syncthreads();
    #pragma unroll
    for (int j = 0; j < 4; j++) {
        int d = d0 + threadIdx.y + j * 8;
        vt[((size_t)zz * HD + d) * SEQ + s0 + threadIdx.x] =
            __float2half_rn(tile[threadIdx.x][threadIdx.y + j * 8]);
    }
}

// ---------------- launch ----------------
extern "C" void kernel_launch(void* const* d_in, const int* in_sizes, int n_in,
                              void* d_out, int out_size)
{
    const float* x     = (const float*)d_in[0];
    const int*   xmask = (const int*)  d_in[1];
    const float* fcos  = (const float*)d_in[2];
    const float* fsin  = (const float*)d_in[3];
    const float* Wqkv  = (const float*)d_in[4];
    const float* Wout  = (const float*)d_in[5];
    const float* qw    = (const float*)d_in[6];
    const float* kw    = (const float*)d_in[7];
    float* out = (float*)d_out;

    float *qkv;
    __half *q, *k, *vt, *att, *xh, *wq, *wo;
    cudaGetSymbolAddress((void**)&qkv,  g_qkv);
    cudaGetSymbolAddress((void**)&q,    g_q);
    cudaGetSymbolAddress((void**)&k,    g_k);
    cudaGetSymbolAddress((void**)&vt,   g_vt);
    cudaGetSymbolAddress((void**)&att,  g_att);
    cudaGetSymbolAddress((void**)&xh,   g_xh);
    cudaGetSymbolAddress((void**)&wq,   g_wq);
    cudaGetSymbolAddress((void**)&wo,   g_wo);

    cudaFuncSetAttribute(mma_gemm, cudaFuncAttributeMaxDynamicSharedMemorySize, GSMEM_TOTAL);
    cudaFuncSetAttribute(flash_attn, cudaFuncAttributeMaxDynamicSharedMemorySize, FSMEM_TOTAL);

    float scale = rsqrtf((float)HD);

    // 0) convert raw GEMM inputs to fp16
    tohalf<<<1184, 256>>>((const float2*)x,    (__half2*)xh, (NTOK * DIM) / 2);
    tohalf<<<1184, 256>>>((const float2*)Wqkv, (__half2*)wq, (QKVD * DIM) / 2);
    tohalf<<<1184, 256>>>((const float2*)Wout, (__half2*)wo, (DIM * DIM) / 2);

    // 1) qkv = x @ Wqkv^T : M=4096, N=4096, K=2048
    mma_gemm<<<dim3(QKVD / 128, NTOK / 128), 128, GSMEM_TOTAL>>>(
        xh, wq, qkv, DIM, DIM, DIM, QKVD);

    // 2) RMSNorm + RoPE on Q,K (fp16 out)
    norm_rope<<<dim3(NTOK, NH + NKV), 64>>>(qkv, fcos, fsin, qw, kw, q, k);

    // 3) V transpose (fp16 out)
    vtrans<<<dim3(SEQ / 32, HD / 32, BSZ * NKV), dim3(32, 8)>>>(qkv, vt);

    // 4) fused attention -> att (fp16)
    flash_attn<<<dim3(SEQ / 128, BSZ * NH), 512, FSMEM_TOTAL>>>(
        q, k, vt, xmask, att, scale);

    // 5) out = att @ Wout^T : M=4096, N=2048, K=2048
    mma_gemm<<<dim3(DIM / 128, NTOK / 128), 128, GSMEM_TOTAL>>>(
        att, wo, out, DIM, DIM, DIM, DIM);
}

// round 12
// speedup vs baseline: 7.4601x; 1.0434x over previous
#include <cuda_runtime.h>
#include <cuda_fp16.h>
#include <math.h>
#include <stdint.h>

// Problem constants
#define BSZ 2
#define SEQ 2048
#define DIM 2048
#define NH 16
#define NKV 8
#define HD 128
#define QKVD 4096          // (16 + 2*8) * 128
#define NTOK (BSZ*SEQ)     // 4096

// ---------------- scratch (static __device__, no allocations) ----------------
static __device__ __half g_q  [(size_t)BSZ * NH  * SEQ * HD];        // 16 MB
static __device__ __half g_k  [(size_t)BSZ * NKV * SEQ * HD];        // 8 MB
static __device__ __half g_v  [(size_t)BSZ * NKV * SEQ * HD];        // 8 MB (K-major, same as g_k)
static __device__ __half g_att[(size_t)NTOK * DIM];                  // 16 MB
static __device__ __half g_xh [(size_t)NTOK * DIM];                  // 16 MB
static __device__ __half g_wq [(size_t)QKVD * DIM];                  // 16 MB
static __device__ __half g_wo [(size_t)DIM * DIM];                   // 8 MB

__device__ __forceinline__ uint32_t smem_u32(const void* p) {
    uint32_t a;
    asm("{ .reg .u64 t; cvta.to.shared.u64 t, %1; cvt.u32.u64 %0, t; }" : "=r"(a) : "l"(p));
    return a;
}

__device__ __forceinline__ void cpa16(uint32_t saddr, const void* g) {
    asm volatile("cp.async.cg.shared.global [%0], [%1], 16;" :: "r"(saddr), "l"(g));
}

#define MMA16816(acc, a0, a1, a2, a3, b0, b1) \
    asm volatile( \
        "mma.sync.aligned.m16n8k16.row.col.f32.f16.f16.f32 " \
        "{%0,%1,%2,%3}, {%4,%5,%6,%7}, {%8,%9}, {%0,%1,%2,%3};" \
        : "+f"((acc)[0]), "+f"((acc)[1]), "+f"((acc)[2]), "+f"((acc)[3]) \
        : "r"(a0), "r"(a1), "r"(a2), "r"(a3), "r"(b0), "r"(b1))

#define LDMX4(d, addr) \
    asm volatile("ldmatrix.sync.aligned.m8n8.x4.shared.b16 {%0,%1,%2,%3}, [%4];" \
        : "=r"((d)[0]), "=r"((d)[1]), "=r"((d)[2]), "=r"((d)[3]) : "r"(addr))

#define LDMX4T(d, addr) \
    asm volatile("ldmatrix.sync.aligned.m8n8.x4.trans.shared.b16 {%0,%1,%2,%3}, [%4];" \
        : "=r"((d)[0]), "=r"((d)[1]), "=r"((d)[2]), "=r"((d)[3]) : "r"(addr))

// ============================================================================
//          projection GEMM: C = A @ B^T
//  EPI_PLAIN: fp32 C out (out projection).
//  EPI_QKV: CTA n-tile == one head. RMSNorm+RoPE for Q/K heads, plain fp16
//           store for V heads, direct to g_q/g_k/g_v. No C buffer.
// ============================================================================
#define GROWB 80
#define GSTAGE_BYTES (256 * GROWB)           // A 128 rows + B 128 rows = 20480
#define GB_OFF (128 * GROWB)                 // 10240
#define GSTAGES 3
#define GSMEM_TOTAL (GSTAGES * GSTAGE_BYTES) // 61440 B

#define EPI_PLAIN 0
#define EPI_QKV   1

template<int EPI>
__global__ __launch_bounds__(128, 3)
void mma_gemm(const __half* __restrict__ A, const __half* __restrict__ B, float* __restrict__ C,
              int K, int lda, int ldb, int ldc,
              const float* __restrict__ cosb, const float* __restrict__ sinb,
              const float* __restrict__ qw, const float* __restrict__ kw,
              __half* __restrict__ qo, __half* __restrict__ ko, __half* __restrict__ vo)
{
    extern __shared__ char smc[];
    uint32_t sbase = smem_u32(smc);

    int tid = threadIdx.x;
    int wid = tid >> 5, lane = tid & 31;
    int g = lane >> 2, t4 = lane & 3;
    int wm = wid & 1, wn = wid >> 1;
    int m0 = wm * 64, n0 = wn * 64;

    size_t bm = (size_t)blockIdx.y * 128;
    size_t bn = (size_t)blockIdx.x * 128;
    int z = blockIdx.x;                  // head slot for EPI_QKV

    const int NC = K >> 5;

    float acc[4][8][4];
    #pragma unroll
    for (int i = 0; i < 4; i++)
        #pragma unroll
        for (int j = 0; j < 8; j++)
            #pragma unroll
            for (int r = 0; r < 4; r++) acc[i][j][r] = 0.0f;

    int lr = lane & 7;
    uint32_t aoff = (uint32_t)((m0 + ((lane >> 3) & 1) * 8 + lr) * GROWB + (lane >> 4) * 16);
    uint32_t boff = (uint32_t)(GB_OFF + (n0 + (lane >> 4) * 8 + lr) * GROWB + ((lane >> 3) & 1) * 16);

    int lrow = tid >> 2, lseg = tid & 3;

    auto load_chunk = [&](int c, int st) {
        const __half* Ak = A + c * 32;
        const __half* Bk = B + c * 32;
        uint32_t sA = sbase + (uint32_t)st * GSTAGE_BYTES;
        #pragma unroll
        for (int i = 0; i < 4; i++) {
            int row = lrow + i * 32;
            cpa16(sA + row * GROWB + lseg * 16, Ak + (bm + row) * (size_t)lda + lseg * 8);
            cpa16(sA + GB_OFF + row * GROWB + lseg * 16, Bk + (bn + row) * (size_t)ldb + lseg * 8);
        }
        asm volatile("cp.async.commit_group;" ::: "memory");
    };

    load_chunk(0, 0);
    if (NC > 1) load_chunk(1, 1);

    int st = 0;
    for (int c = 0; c < NC; c++) {
        if (c + 1 < NC) asm volatile("cp.async.wait_group 1;" ::: "memory");
        else            asm volatile("cp.async.wait_group 0;" ::: "memory");
        __syncthreads();

        if (c + 2 < NC) load_chunk(c + 2, (st + 2) % GSTAGES);

        uint32_t sg = sbase + (uint32_t)st * GSTAGE_BYTES;

        #pragma unroll
        for (int ks = 0; ks < 2; ks++) {
            uint32_t a[4][4];
            #pragma unroll
            for (int mt = 0; mt < 4; mt++)
                LDMX4(a[mt], sg + aoff + mt * (16 * GROWB) + ks * 32);
            #pragma unroll
            for (int np = 0; np < 4; np++) {
                uint32_t b[4];
                LDMX4(b, sg + boff + np * (16 * GROWB) + ks * 32);
                #pragma unroll
                for (int mt = 0; mt < 4; mt++) {
                    MMA16816(acc[mt][np * 2],
                             a[mt][0], a[mt][1], a[mt][2], a[mt][3], b[0], b[1]);
                    MMA16816(acc[mt][np * 2 + 1],
                             a[mt][0], a[mt][1], a[mt][2], a[mt][3], b[2], b[3]);
                }
            }
        }
        st++; if (st == GSTAGES) st = 0;
    }

    if (EPI == EPI_PLAIN) {
        #pragma unroll
        for (int mt = 0; mt < 4; mt++) {
            size_t row = bm + m0 + mt * 16 + g;
            #pragma unroll
            for (int nt = 0; nt < 8; nt++) {
                size_t col = bn + n0 + nt * 8 + 2 * t4;
                *(float2*)&C[row * (size_t)ldc + col] =
                    make_float2(acc[mt][nt][0], acc[mt][nt][1]);
                *(float2*)&C[(row + 8) * (size_t)ldc + col] =
                    make_float2(acc[mt][nt][2], acc[mt][nt][3]);
            }
        }
        return;
    }

    // ---------------- EPI_QKV ----------------
    if (z >= NH + NKV) {
        // V head: plain fp16 store, K-major layout
        int kh = z - (NH + NKV);
        #pragma unroll
        for (int mt = 0; mt < 4; mt++) {
            size_t tok = bm + m0 + mt * 16 + g;
            int bb = (int)(tok >> 11);
            int s  = (int)(tok & (SEQ - 1));
            __half* d0 = vo + ((size_t)(bb * NKV + kh) * SEQ + s) * HD;
            __half* d1 = d0 + (size_t)8 * HD;
            #pragma unroll
            for (int nt = 0; nt < 8; nt++) {
                int cc = n0 + nt * 8 + 2 * t4;
                *(__half2*)&d0[cc] = __floats2half2_rn(acc[mt][nt][0], acc[mt][nt][1]);
                *(__half2*)&d1[cc] = __floats2half2_rn(acc[mt][nt][2], acc[mt][nt][3]);
            }
        }
        return;
    }

    // Q or K head: RMSNorm + RoPE
    __syncthreads();                      // smem tiles free
    float* red = (float*)smc;             // [128][2]

    #pragma unroll
    for (int mt = 0; mt < 4; mt++) {
        float s0 = 0.0f, s1 = 0.0f;
        #pragma unroll
        for (int nt = 0; nt < 8; nt++) {
            s0 += acc[mt][nt][0] * acc[mt][nt][0] + acc[mt][nt][1] * acc[mt][nt][1];
            s1 += acc[mt][nt][2] * acc[mt][nt][2] + acc[mt][nt][3] * acc[mt][nt][3];
        }
        s0 += __shfl_xor_sync(0xFFFFFFFFu, s0, 1);
        s0 += __shfl_xor_sync(0xFFFFFFFFu, s0, 2);
        s1 += __shfl_xor_sync(0xFFFFFFFFu, s1, 1);
        s1 += __shfl_xor_sync(0xFFFFFFFFu, s1, 2);
        if (t4 == 0) {
            int r0 = m0 + mt * 16 + g;
            red[r0 * 2 + wn]       = s0;
            red[(r0 + 8) * 2 + wn] = s1;
        }
    }
    __syncthreads();

    const float* w = (z < NH) ? qw : kw;
    #pragma unroll
    for (int mt = 0; mt < 4; mt++) {
        int r0 = m0 + mt * 16 + g;
        float inv0 = rsqrtf((red[r0 * 2] + red[r0 * 2 + 1]) * (1.0f / HD) + 1e-5f);
        float inv1 = rsqrtf((red[(r0 + 8) * 2] + red[(r0 + 8) * 2 + 1]) * (1.0f / HD) + 1e-5f);
        size_t tok = bm + r0;
        int bb = (int)(tok >> 11);
        int s  = (int)(tok & (SEQ - 1));
        __half* d0;
        if (z < NH) d0 = qo + ((size_t)(bb * NH + z) * SEQ + s) * HD;
        else        d0 = ko + ((size_t)(bb * NKV + (z - NH)) * SEQ + s) * HD;
        __half* d1 = d0 + (size_t)8 * HD;
        const float* cr0 = cosb + (size_t)s * (HD / 2);
        const float* sr0 = sinb + (size_t)s * (HD / 2);
        const float* cr1 = cr0 + 8 * (HD / 2);
        const float* sr1 = sr0 + 8 * (HD / 2);
        #pragma unroll
        for (int nt = 0; nt < 8; nt++) {
            int cc = n0 + nt * 8 + 2 * t4;
            int ii = cc >> 1;
            float w0 = w[cc], w1 = w[cc + 1];
            float c0 = cr0[ii], sn0 = sr0[ii];
            float c1 = cr1[ii], sn1 = sr1[ii];
            float y0 = acc[mt][nt][0] * inv0 * w0;
            float y1 = acc[mt][nt][1] * inv0 * w1;
            float y2 = acc[mt][nt][2] * inv1 * w0;
            float y3 = acc[mt][nt][3] * inv1 * w1;
            *(__half2*)&d0[cc] = __floats2half2_rn(y0 * c0 - y1 * sn0, y0 * sn0 + y1 * c0);
            *(__half2*)&d1[cc] = __floats2half2_rn(y2 * c1 - y3 * sn1, y2 * sn1 + y3 * c1);
        }
    }
}

// ============================================================================
//  fused flash attention (kv-block 128; V in K-major via ldmatrix.trans)
// ============================================================================
#define FRB  272              // row bytes (128 halves + 8 pad)
#define FRU  68               // row u32
#define SM_Q   0
#define SM_P   34816
#define SM_KV  69632
#define KV_STG 69632          // K 34816 + V 34816
#define FSMEM_TOTAL (SM_KV + 2 * KV_STG)   // 208896 B
#define NKVB (SEQ / 128)      // 16

__global__ __launch_bounds__(512, 1)
void flash_attn(const __half* __restrict__ q, const __half* __restrict__ k,
                const __half* __restrict__ v, const int* __restrict__ mask,
                __half* __restrict__ att, float scale)
{
    extern __shared__ char smc[];
    uint32_t sbase = smem_u32(smc);

    int tid = threadIdx.x;
    int wid = tid >> 5, lane = tid & 31;
    int g = lane >> 2, t4 = lane & 3, lr = lane & 7;
    int wm = wid & 3, wn = wid >> 2;
    int m0 = wm * 32, n0 = wn * 32;

    int z  = blockIdx.y;
    size_t bm = (size_t)blockIdx.x * 128;

    const __half* Qg = q + ((size_t)z * SEQ + bm) * HD;
    const __half* Kg = k + (size_t)(z >> 1) * SEQ * HD;
    const __half* Vg = v + (size_t)(z >> 1) * SEQ * HD;
    const int* mrow  = mask + (size_t)(z >> 4) * SEQ;

    uint32_t a_base = (uint32_t)((m0 + ((lane >> 3) & 1) * 8 + lr) * FRB + (lane >> 4) * 16);
    uint32_t b_base = (uint32_t)((n0 + (lane >> 4) * 8 + lr) * FRB + ((lane >> 3) & 1) * 16);
    // trans addressing for V [s][d]: rows = k (s) tiles, cols = n (d) window
    uint32_t vb_base = (uint32_t)((((lane >> 3) & 1) * 8 + lr) * FRB + (n0 + (lane >> 4) * 8) * 2);

    float acc_o[2][4][4];
    #pragma unroll
    for (int i = 0; i < 2; i++)
        #pragma unroll
        for (int j = 0; j < 4; j++)
            #pragma unroll
            for (int r = 0; r < 4; r++) acc_o[i][j][r] = 0.0f;
    float rsum[2][2] = {};

    auto load_stage = [&](int c, int st) {
        uint32_t sK = sbase + SM_KV + (uint32_t)st * KV_STG;
        uint32_t sV = sK + 34816;
        #pragma unroll
        for (int i = 0; i < 4; i++) {
            int idx = tid + i * 512;
            int row = idx >> 4, seg = idx & 15;
            cpa16(sK + row * FRB + seg * 16, Kg + ((size_t)(c * 128 + row)) * HD + seg * 8);
            cpa16(sV + row * FRB + seg * 16, Vg + ((size_t)(c * 128 + row)) * HD + seg * 8);
        }
        asm volatile("cp.async.commit_group;" ::: "memory");
    };

    #pragma unroll
    for (int i = 0; i < 4; i++) {
        int idx = tid + i * 512;
        int row = idx >> 4, seg = idx & 15;
        cpa16(sbase + SM_Q + row * FRB + seg * 16, Qg + (size_t)row * HD + seg * 8);
    }
    load_stage(0, 0);

    for (int c = 0; c < NKVB; c++) {
        int st = c & 1;
        asm volatile("cp.async.wait_group 0;" ::: "memory");
        __syncthreads();

        if (c + 1 < NKVB) load_stage(c + 1, st ^ 1);

        uint32_t sQ = sbase + SM_Q;
        uint32_t sK = sbase + SM_KV + (uint32_t)st * KV_STG;
        uint32_t sV = sK + 34816;
        uint32_t sP = sbase + SM_P;

        // ---- S = Q @ K^T, warp tile 32x32 ----
        float acc_s[2][4][4];
        #pragma unroll
        for (int i = 0; i < 2; i++)
            #pragma unroll
            for (int j = 0; j < 4; j++)
                #pragma unroll
                for (int r = 0; r < 4; r++) acc_s[i][j][r] = 0.0f;

        #pragma unroll
        for (int kt = 0; kt < 8; kt++) {
            uint32_t a[2][4], b[2][4];
            LDMX4(a[0], sQ + a_base + kt * 32);
            LDMX4(a[1], sQ + a_base + 16 * FRB + kt * 32);
            LDMX4(b[0], sK + b_base + kt * 32);
            LDMX4(b[1], sK + b_base + 16 * FRB + kt * 32);
            #pragma unroll
            for (int mt = 0; mt < 2; mt++)
                #pragma unroll
                for (int np = 0; np < 2; np++) {
                    MMA16816(acc_s[mt][np * 2],
                             a[mt][0], a[mt][1], a[mt][2], a[mt][3], b[np][0], b[np][1]);
                    MMA16816(acc_s[mt][np * 2 + 1],
                             a[mt][0], a[mt][1], a[mt][2], a[mt][3], b[np][2], b[np][3]);
                }
        }

        // ---- exp * mask, rowsum accum, pack P ----
        uint32_t* Ps = (uint32_t*)(smc + SM_P);
        #pragma unroll
        for (int nb = 0; nb < 4; nb++) {
            int col0 = c * 128 + n0 + nb * 8 + 2 * t4;
            float mk0 = mrow[col0]     ? 1.0f : 0.0f;
            float mk1 = mrow[col0 + 1] ? 1.0f : 0.0f;
            #pragma unroll
            for (int mt = 0; mt < 2; mt++) {
                float e0 = __expf(acc_s[mt][nb][0] * scale) * mk0;
                float e1 = __expf(acc_s[mt][nb][1] * scale) * mk1;
                float e2 = __expf(acc_s[mt][nb][2] * scale) * mk0;
                float e3 = __expf(acc_s[mt][nb][3] * scale) * mk1;
                rsum[mt][0] += e0 + e1;
                rsum[mt][1] += e2 + e3;
                int prow = m0 + mt * 16 + g;
                int pcol = wn * 16 + nb * 4 + t4;
                __half2 h01 = __floats2half2_rn(e0, e1);
                __half2 h23 = __floats2half2_rn(e2, e3);
                Ps[prow * FRU + pcol]       = *(uint32_t*)&h01;
                Ps[(prow + 8) * FRU + pcol] = *(uint32_t*)&h23;
            }
        }
        __syncthreads();

        // ---- out += P @ V, V loaded transposed via ldmatrix.trans ----
        #pragma unroll
        for (int kt = 0; kt < 8; kt++) {
            uint32_t a[2][4], b[2][4];
            LDMX4(a[0], sP + a_base + kt * 32);
            LDMX4(a[1], sP + a_base + 16 * FRB + kt * 32);
            LDMX4T(b[0], sV + vb_base + kt * (16 * FRB));
            LDMX4T(b[1], sV + vb_base + kt * (16 * FRB) + 32);
            #pragma unroll
            for (int mt = 0; mt < 2; mt++)
                #pragma unroll
                for (int np = 0; np < 2; np++) {
                    MMA16816(acc_o[mt][np * 2],
                             a[mt][0], a[mt][1], a[mt][2], a[mt][3], b[np][0], b[np][1]);
                    MMA16816(acc_o[mt][np * 2 + 1],
                             a[mt][0], a[mt][1], a[mt][2], a[mt][3], b[np][2], b[np][3]);
                }
        }
    }

    // ---- rowsum reduce, divide, store ----
    __syncthreads();
    float* red = (float*)(smc + SM_P);
    #pragma unroll
    for (int mt = 0; mt < 2; mt++) {
        #pragma unroll
        for (int h = 0; h < 2; h++) {
            float s = rsum[mt][h];
            s += __shfl_xor_sync(0xFFFFFFFFu, s, 1);
            s += __shfl_xor_sync(0xFFFFFFFFu, s, 2);
            rsum[mt][h] = s;
        }
    }
    if (t4 == 0) {
        #pragma unroll
        for (int mt = 0; mt < 2; mt++) {
            int r0 = m0 + mt * 16 + g;
            red[r0 * 4 + wn]       = rsum[mt][0];
            red[(r0 + 8) * 4 + wn] = rsum[mt][1];
        }
    }
    __syncthreads();

    int b = z >> 4, h = z & 15;
    #pragma unroll
    for (int mt = 0; mt < 2; mt++) {
        int r0 = m0 + mt * 16 + g;
        float t0 = red[r0 * 4] + red[r0 * 4 + 1] + red[r0 * 4 + 2] + red[r0 * 4 + 3];
        float t1 = red[(r0 + 8) * 4] + red[(r0 + 8) * 4 + 1] +
                   red[(r0 + 8) * 4 + 2] + red[(r0 + 8) * 4 + 3];
        float i0 = (t0 > 0.0f) ? (1.0f / t0) : 0.0f;
        float i1 = (t1 > 0.0f) ? (1.0f / t1) : 0.0f;
        size_t s0 = bm + r0;
        __half* d0 = att + ((size_t)b * SEQ + s0) * DIM + h * HD;
        __half* d1 = att + ((size_t)b * SEQ + s0 + 8) * DIM + h * HD;
        #pragma unroll
        for (int nt = 0; nt < 4; nt++) {
            int col = n0 + nt * 8 + 2 * t4;
            *(__half2*)&d0[col] = __floats2half2_rn(acc_o[mt][nt][0] * i0, acc_o[mt][nt][1] * i0);
            *(__half2*)&d1[col] = __floats2half2_rn(acc_o[mt][nt][2] * i1, acc_o[mt][nt][3] * i1);
        }
    }
}

// ---------------- streaming fp32 -> fp16 ----------------
__global__ __launch_bounds__(256)
void tohalf(const float2* __restrict__ src, __half2* __restrict__ dst, int n2)
{
    int i = blockIdx.x * 256 + threadIdx.x;
    int stride = gridDim.x * 256;
    for (; i < n2; i += stride) {
        float2 v = src[i];
        dst[i] = __floats2half2_rn(v.x, v.y);
    }
}

// ---------------- launch ----------------
extern "C" void kernel_launch(void* const* d_in, const int* in_sizes, int n_in,
                              void* d_out, int out_size)
{
    const float* x     = (const float*)d_in[0];
    const int*   xmask = (const int*)  d_in[1];
    const float* fcos  = (const float*)d_in[2];
    const float* fsin  = (const float*)d_in[3];
    const float* Wqkv  = (const float*)d_in[4];
    const float* Wout  = (const float*)d_in[5];
    const float* qw    = (const float*)d_in[6];
    const float* kw    = (const float*)d_in[7];
    float* out = (float*)d_out;

    __half *q, *k, *v, *att, *xh, *wq, *wo;
    cudaGetSymbolAddress((void**)&q,   g_q);
    cudaGetSymbolAddress((void**)&k,   g_k);
    cudaGetSymbolAddress((void**)&v,   g_v);
    cudaGetSymbolAddress((void**)&att, g_att);
    cudaGetSymbolAddress((void**)&xh,  g_xh);
    cudaGetSymbolAddress((void**)&wq,  g_wq);
    cudaGetSymbolAddress((void**)&wo,  g_wo);

    cudaFuncSetAttribute(mma_gemm<EPI_PLAIN>, cudaFuncAttributeMaxDynamicSharedMemorySize, GSMEM_TOTAL);
    cudaFuncSetAttribute(mma_gemm<EPI_QKV>,   cudaFuncAttributeMaxDynamicSharedMemorySize, GSMEM_TOTAL);
    cudaFuncSetAttribute(flash_attn, cudaFuncAttributeMaxDynamicSharedMemorySize, FSMEM_TOTAL);

    float scale = rsqrtf((float)HD);

    // 0) convert raw GEMM inputs to fp16
    tohalf<<<1184, 256>>>((const float2*)x,    (__half2*)xh, (NTOK * DIM) / 2);
    tohalf<<<1184, 256>>>((const float2*)Wqkv, (__half2*)wq, (QKVD * DIM) / 2);
    tohalf<<<1184, 256>>>((const float2*)Wout, (__half2*)wo, (DIM * DIM) / 2);

    // 1) fused QKV GEMM + RMSNorm + RoPE -> g_q / g_k / g_v (fp16)
    mma_gemm<EPI_QKV><<<dim3(QKVD / 128, NTOK / 128), 128, GSMEM_TOTAL>>>(
        xh, wq, nullptr, DIM, DIM, DIM, 0, fcos, fsin, qw, kw, q, k, v);

    // 2) fused attention -> att (fp16)
    flash_attn<<<dim3(SEQ / 128, BSZ * NH), 512, FSMEM_TOTAL>>>(
        q, k, v, xmask, att, scale);

    // 3) out = att @ Wout^T (fp32)
    mma_gemm<EPI_PLAIN><<<dim3(DIM / 128, NTOK / 128), 128, GSMEM_TOTAL>>>(
        att, wo, out, DIM, DIM, DIM, DIM,
        nullptr, nullptr, nullptr, nullptr, nullptr, nullptr, nullptr);
}

// round 13
// speedup vs baseline: 7.4712x; 1.0015x over previous
#include <cuda_runtime.h>
#include <cuda_fp16.h>
#include <math.h>
#include <stdint.h>

// Problem constants
#define BSZ 2
#define SEQ 2048
#define DIM 2048
#define NH 16
#define NKV 8
#define HD 128
#define QKVD 4096          // (16 + 2*8) * 128
#define NTOK (BSZ*SEQ)     // 4096

// ---------------- scratch (static __device__, no allocations) ----------------
static __device__ __half g_q  [(size_t)BSZ * NH  * SEQ * HD];        // 16 MB
static __device__ __half g_k  [(size_t)BSZ * NKV * SEQ * HD];        // 8 MB
static __device__ __half g_v  [(size_t)BSZ * NKV * SEQ * HD];        // 8 MB (K-major, same as g_k)
static __device__ __half g_att[(size_t)NTOK * DIM];                  // 16 MB
static __device__ __half g_xh [(size_t)NTOK * DIM];                  // 16 MB
static __device__ __half g_wq [(size_t)QKVD * DIM];                  // 16 MB
static __device__ __half g_wo [(size_t)DIM * DIM];                   // 8 MB

__device__ __forceinline__ uint32_t smem_u32(const void* p) {
    uint32_t a;
    asm("{ .reg .u64 t; cvta.to.shared.u64 t, %1; cvt.u32.u64 %0, t; }" : "=r"(a) : "l"(p));
    return a;
}

__device__ __forceinline__ void cpa16(uint32_t saddr, const void* g) {
    asm volatile("cp.async.cg.shared.global [%0], [%1], 16;" :: "r"(saddr), "l"(g));
}

#define MMA16816(acc, a0, a1, a2, a3, b0, b1) \
    asm volatile( \
        "mma.sync.aligned.m16n8k16.row.col.f32.f16.f16.f32 " \
        "{%0,%1,%2,%3}, {%4,%5,%6,%7}, {%8,%9}, {%0,%1,%2,%3};" \
        : "+f"((acc)[0]), "+f"((acc)[1]), "+f"((acc)[2]), "+f"((acc)[3]) \
        : "r"(a0), "r"(a1), "r"(a2), "r"(a3), "r"(b0), "r"(b1))

#define LDMX4(d, addr) \
    asm volatile("ldmatrix.sync.aligned.m8n8.x4.shared.b16 {%0,%1,%2,%3}, [%4];" \
        : "=r"((d)[0]), "=r"((d)[1]), "=r"((d)[2]), "=r"((d)[3]) : "r"(addr))

#define LDMX4T(d, addr) \
    asm volatile("ldmatrix.sync.aligned.m8n8.x4.trans.shared.b16 {%0,%1,%2,%3}, [%4];" \
        : "=r"((d)[0]), "=r"((d)[1]), "=r"((d)[2]), "=r"((d)[3]) : "r"(addr))

// ============================================================================
//          projection GEMM: C = A @ B^T
//  EPI_PLAIN: fp32 C out (out projection).
//  EPI_QKV: CTA n-tile == one head. RMSNorm+RoPE for Q/K heads, plain fp16
//           store for V heads, direct to g_q/g_k/g_v. No C buffer.
// ============================================================================
#define GROWB 80
#define GSTAGE_BYTES (256 * GROWB)           // A 128 rows + B 128 rows = 20480
#define GB_OFF (128 * GROWB)                 // 10240
#define GSTAGES 3
#define GSMEM_TOTAL (GSTAGES * GSTAGE_BYTES) // 61440 B

#define EPI_PLAIN 0
#define EPI_QKV   1

template<int EPI>
__global__ __launch_bounds__(128, 3)
void mma_gemm(const __half* __restrict__ A, const __half* __restrict__ B, float* __restrict__ C,
              int K, int lda, int ldb, int ldc,
              const float* __restrict__ cosb, const float* __restrict__ sinb,
              const float* __restrict__ qw, const float* __restrict__ kw,
              __half* __restrict__ qo, __half* __restrict__ ko, __half* __restrict__ vo)
{
    extern __shared__ char smc[];
    uint32_t sbase = smem_u32(smc);

    int tid = threadIdx.x;
    int wid = tid >> 5, lane = tid & 31;
    int g = lane >> 2, t4 = lane & 3;
    int wm = wid & 1, wn = wid >> 1;
    int m0 = wm * 64, n0 = wn * 64;

    size_t bm = (size_t)blockIdx.y * 128;
    size_t bn = (size_t)blockIdx.x * 128;
    int z = blockIdx.x;                  // head slot for EPI_QKV

    const int NC = K >> 5;

    float acc[4][8][4];
    #pragma unroll
    for (int i = 0; i < 4; i++)
        #pragma unroll
        for (int j = 0; j < 8; j++)
            #pragma unroll
            for (int r = 0; r < 4; r++) acc[i][j][r] = 0.0f;

    int lr = lane & 7;
    uint32_t aoff = (uint32_t)((m0 + ((lane >> 3) & 1) * 8 + lr) * GROWB + (lane >> 4) * 16);
    uint32_t boff = (uint32_t)(GB_OFF + (n0 + (lane >> 4) * 8 + lr) * GROWB + ((lane >> 3) & 1) * 16);

    int lrow = tid >> 2, lseg = tid & 3;

    auto load_chunk = [&](int c, int st) {
        const __half* Ak = A + c * 32;
        const __half* Bk = B + c * 32;
        uint32_t sA = sbase + (uint32_t)st * GSTAGE_BYTES;
        #pragma unroll
        for (int i = 0; i < 4; i++) {
            int row = lrow + i * 32;
            cpa16(sA + row * GROWB + lseg * 16, Ak + (bm + row) * (size_t)lda + lseg * 8);
            cpa16(sA + GB_OFF + row * GROWB + lseg * 16, Bk + (bn + row) * (size_t)ldb + lseg * 8);
        }
        asm volatile("cp.async.commit_group;" ::: "memory");
    };

    load_chunk(0, 0);
    if (NC > 1) load_chunk(1, 1);

    int st = 0;
    for (int c = 0; c < NC; c++) {
        if (c + 1 < NC) asm volatile("cp.async.wait_group 1;" ::: "memory");
        else            asm volatile("cp.async.wait_group 0;" ::: "memory");
        __syncthreads();

        if (c + 2 < NC) load_chunk(c + 2, (st + 2) % GSTAGES);

        uint32_t sg = sbase + (uint32_t)st * GSTAGE_BYTES;

        #pragma unroll
        for (int ks = 0; ks < 2; ks++) {
            uint32_t a[4][4];
            #pragma unroll
            for (int mt = 0; mt < 4; mt++)
                LDMX4(a[mt], sg + aoff + mt * (16 * GROWB) + ks * 32);
            #pragma unroll
            for (int np = 0; np < 4; np++) {
                uint32_t b[4];
                LDMX4(b, sg + boff + np * (16 * GROWB) + ks * 32);
                #pragma unroll
                for (int mt = 0; mt < 4; mt++) {
                    MMA16816(acc[mt][np * 2],
                             a[mt][0], a[mt][1], a[mt][2], a[mt][3], b[0], b[1]);
                    MMA16816(acc[mt][np * 2 + 1],
                             a[mt][0], a[mt][1], a[mt][2], a[mt][3], b[2], b[3]);
                }
            }
        }
        st++; if (st == GSTAGES) st = 0;
    }

    if (EPI == EPI_PLAIN) {
        #pragma unroll
        for (int mt = 0; mt < 4; mt++) {
            size_t row = bm + m0 + mt * 16 + g;
            #pragma unroll
            for (int nt = 0; nt < 8; nt++) {
                size_t col = bn + n0 + nt * 8 + 2 * t4;
                *(float2*)&C[row * (size_t)ldc + col] =
                    make_float2(acc[mt][nt][0], acc[mt][nt][1]);
                *(float2*)&C[(row + 8) * (size_t)ldc + col] =
                    make_float2(acc[mt][nt][2], acc[mt][nt][3]);
            }
        }
        return;
    }

    // ---------------- EPI_QKV ----------------
    if (z >= NH + NKV) {
        // V head: plain fp16 store, K-major layout
        int kh = z - (NH + NKV);
        #pragma unroll
        for (int mt = 0; mt < 4; mt++) {
            size_t tok = bm + m0 + mt * 16 + g;
            int bb = (int)(tok >> 11);
            int s  = (int)(tok & (SEQ - 1));
            __half* d0 = vo + ((size_t)(bb * NKV + kh) * SEQ + s) * HD;
            __half* d1 = d0 + (size_t)8 * HD;
            #pragma unroll
            for (int nt = 0; nt < 8; nt++) {
                int cc = n0 + nt * 8 + 2 * t4;
                *(__half2*)&d0[cc] = __floats2half2_rn(acc[mt][nt][0], acc[mt][nt][1]);
                *(__half2*)&d1[cc] = __floats2half2_rn(acc[mt][nt][2], acc[mt][nt][3]);
            }
        }
        return;
    }

    // Q or K head: RMSNorm + RoPE
    __syncthreads();                      // smem tiles free
    float* red = (float*)smc;             // [128][2]

    #pragma unroll
    for (int mt = 0; mt < 4; mt++) {
        float s0 = 0.0f, s1 = 0.0f;
        #pragma unroll
        for (int nt = 0; nt < 8; nt++) {
            s0 += acc[mt][nt][0] * acc[mt][nt][0] + acc[mt][nt][1] * acc[mt][nt][1];
            s1 += acc[mt][nt][2] * acc[mt][nt][2] + acc[mt][nt][3] * acc[mt][nt][3];
        }
        s0 += __shfl_xor_sync(0xFFFFFFFFu, s0, 1);
        s0 += __shfl_xor_sync(0xFFFFFFFFu, s0, 2);
        s1 += __shfl_xor_sync(0xFFFFFFFFu, s1, 1);
        s1 += __shfl_xor_sync(0xFFFFFFFFu, s1, 2);
        if (t4 == 0) {
            int r0 = m0 + mt * 16 + g;
            red[r0 * 2 + wn]       = s0;
            red[(r0 + 8) * 2 + wn] = s1;
        }
    }
    __syncthreads();

    const float* w = (z < NH) ? qw : kw;
    #pragma unroll
    for (int mt = 0; mt < 4; mt++) {
        int r0 = m0 + mt * 16 + g;
        float inv0 = rsqrtf((red[r0 * 2] + red[r0 * 2 + 1]) * (1.0f / HD) + 1e-5f);
        float inv1 = rsqrtf((red[(r0 + 8) * 2] + red[(r0 + 8) * 2 + 1]) * (1.0f / HD) + 1e-5f);
        size_t tok = bm + r0;
        int bb = (int)(tok >> 11);
        int s  = (int)(tok & (SEQ - 1));
        __half* d0;
        if (z < NH) d0 = qo + ((size_t)(bb * NH + z) * SEQ + s) * HD;
        else        d0 = ko + ((size_t)(bb * NKV + (z - NH)) * SEQ + s) * HD;
        __half* d1 = d0 + (size_t)8 * HD;
        const float* cr0 = cosb + (size_t)s * (HD / 2);
        const float* sr0 = sinb + (size_t)s * (HD / 2);
        const float* cr1 = cr0 + 8 * (HD / 2);
        const float* sr1 = sr0 + 8 * (HD / 2);
        #pragma unroll
        for (int nt = 0; nt < 8; nt++) {
            int cc = n0 + nt * 8 + 2 * t4;
            int ii = cc >> 1;
            float w0 = w[cc], w1 = w[cc + 1];
            float c0 = cr0[ii], sn0 = sr0[ii];
            float c1 = cr1[ii], sn1 = sr1[ii];
            float y0 = acc[mt][nt][0] * inv0 * w0;
            float y1 = acc[mt][nt][1] * inv0 * w1;
            float y2 = acc[mt][nt][2] * inv1 * w0;
            float y3 = acc[mt][nt][3] * inv1 * w1;
            *(__half2*)&d0[cc] = __floats2half2_rn(y0 * c0 - y1 * sn0, y0 * sn0 + y1 * c0);
            *(__half2*)&d1[cc] = __floats2half2_rn(y2 * c1 - y3 * sn1, y2 * sn1 + y3 * c1);
        }
    }
}

// ============================================================================
//  fused flash attention (kv-block 128; V in K-major via ldmatrix.trans)
// ============================================================================
#define FRB  272              // row bytes (128 halves + 8 pad)
#define FRU  68               // row u32
#define SM_Q   0
#define SM_P   34816
#define SM_KV  69632
#define KV_STG 69632          // K 34816 + V 34816
#define FSMEM_TOTAL (SM_KV + 2 * KV_STG)   // 208896 B
#define NKVB (SEQ / 128)      // 16

__global__ __launch_bounds__(512, 1)
void flash_attn(const __half* __restrict__ q, const __half* __restrict__ k,
                const __half* __restrict__ v, const int* __restrict__ mask,
                __half* __restrict__ att, float scale)
{
    extern __shared__ char smc[];
    uint32_t sbase = smem_u32(smc);

    int tid = threadIdx.x;
    int wid = tid >> 5, lane = tid & 31;
    int g = lane >> 2, t4 = lane & 3, lr = lane & 7;
    int wm = wid & 3, wn = wid >> 2;
    int m0 = wm * 32, n0 = wn * 32;

    int z  = blockIdx.y;
    size_t bm = (size_t)blockIdx.x * 128;

    const __half* Qg = q + ((size_t)z * SEQ + bm) * HD;
    const __half* Kg = k + (size_t)(z >> 1) * SEQ * HD;
    const __half* Vg = v + (size_t)(z >> 1) * SEQ * HD;
    const int* mrow  = mask + (size_t)(z >> 4) * SEQ;

    uint32_t a_base = (uint32_t)((m0 + ((lane >> 3) & 1) * 8 + lr) * FRB + (lane >> 4) * 16);
    uint32_t b_base = (uint32_t)((n0 + (lane >> 4) * 8 + lr) * FRB + ((lane >> 3) & 1) * 16);
    // trans addressing for V [s][d]: rows = k (s) tiles, cols = n (d) window
    uint32_t vb_base = (uint32_t)((((lane >> 3) & 1) * 8 + lr) * FRB + (n0 + (lane >> 4) * 8) * 2);

    float acc_o[2][4][4];
    #pragma unroll
    for (int i = 0; i < 2; i++)
        #pragma unroll
        for (int j = 0; j < 4; j++)
            #pragma unroll
            for (int r = 0; r < 4; r++) acc_o[i][j][r] = 0.0f;
    float rsum[2][2] = {};

    auto load_stage = [&](int c, int st) {
        uint32_t sK = sbase + SM_KV + (uint32_t)st * KV_STG;
        uint32_t sV = sK + 34816;
        #pragma unroll
        for (int i = 0; i < 4; i++) {
            int idx = tid + i * 512;
            int row = idx >> 4, seg = idx & 15;
            cpa16(sK + row * FRB + seg * 16, Kg + ((size_t)(c * 128 + row)) * HD + seg * 8);
            cpa16(sV + row * FRB + seg * 16, Vg + ((size_t)(c * 128 + row)) * HD + seg * 8);
        }
        asm volatile("cp.async.commit_group;" ::: "memory");
    };

    #pragma unroll
    for (int i = 0; i < 4; i++) {
        int idx = tid + i * 512;
        int row = idx >> 4, seg = idx & 15;
        cpa16(sbase + SM_Q + row * FRB + seg * 16, Qg + (size_t)row * HD + seg * 8);
    }
    load_stage(0, 0);

    for (int c = 0; c < NKVB; c++) {
        int st = c & 1;
        asm volatile("cp.async.wait_group 0;" ::: "memory");
        __syncthreads();

        if (c + 1 < NKVB) load_stage(c + 1, st ^ 1);

        uint32_t sQ = sbase + SM_Q;
        uint32_t sK = sbase + SM_KV + (uint32_t)st * KV_STG;
        uint32_t sV = sK + 34816;
        uint32_t sP = sbase + SM_P;

        // ---- S = Q @ K^T, warp tile 32x32 ----
        float acc_s[2][4][4];
        #pragma unroll
        for (int i = 0; i < 2; i++)
            #pragma unroll
            for (int j = 0; j < 4; j++)
                #pragma unroll
                for (int r = 0; r < 4; r++) acc_s[i][j][r] = 0.0f;

        #pragma unroll
        for (int kt = 0; kt < 8; kt++) {
            uint32_t a[2][4], b[2][4];
            LDMX4(a[0], sQ + a_base + kt * 32);
            LDMX4(a[1], sQ + a_base + 16 * FRB + kt * 32);
            LDMX4(b[0], sK + b_base + kt * 32);
            LDMX4(b[1], sK + b_base + 16 * FRB + kt * 32);
            #pragma unroll
            for (int mt = 0; mt < 2; mt++)
                #pragma unroll
                for (int np = 0; np < 2; np++) {
                    MMA16816(acc_s[mt][np * 2],
                             a[mt][0], a[mt][1], a[mt][2], a[mt][3], b[np][0], b[np][1]);
                    MMA16816(acc_s[mt][np * 2 + 1],
                             a[mt][0], a[mt][1], a[mt][2], a[mt][3], b[np][2], b[np][3]);
                }
        }

        // ---- exp * mask, rowsum accum, pack P ----
        uint32_t* Ps = (uint32_t*)(smc + SM_P);
        #pragma unroll
        for (int nb = 0; nb < 4; nb++) {
            int col0 = c * 128 + n0 + nb * 8 + 2 * t4;
            float mk0 = mrow[col0]     ? 1.0f : 0.0f;
            float mk1 = mrow[col0 + 1] ? 1.0f : 0.0f;
            #pragma unroll
            for (int mt = 0; mt < 2; mt++) {
                float e0 = __expf(acc_s[mt][nb][0] * scale) * mk0;
                float e1 = __expf(acc_s[mt][nb][1] * scale) * mk1;
                float e2 = __expf(acc_s[mt][nb][2] * scale) * mk0;
                float e3 = __expf(acc_s[mt][nb][3] * scale) * mk1;
                rsum[mt][0] += e0 + e1;
                rsum[mt][1] += e2 + e3;
                int prow = m0 + mt * 16 + g;
                int pcol = wn * 16 + nb * 4 + t4;
                __half2 h01 = __floats2half2_rn(e0, e1);
                __half2 h23 = __floats2half2_rn(e2, e3);
                Ps[prow * FRU + pcol]       = *(uint32_t*)&h01;
                Ps[(prow + 8) * FRU + pcol] = *(uint32_t*)&h23;
            }
        }
        __syncthreads();

        // ---- out += P @ V, V loaded transposed via ldmatrix.trans ----
        #pragma unroll
        for (int kt = 0; kt < 8; kt++) {
            uint32_t a[2][4], b[2][4];
            LDMX4(a[0], sP + a_base + kt * 32);
            LDMX4(a[1], sP + a_base + 16 * FRB + kt * 32);
            LDMX4T(b[0], sV + vb_base + kt * (16 * FRB));
            LDMX4T(b[1], sV + vb_base + kt * (16 * FRB) + 32);
            #pragma unroll
            for (int mt = 0; mt < 2; mt++)
                #pragma unroll
                for (int np = 0; np < 2; np++) {
                    MMA16816(acc_o[mt][np * 2],
                             a[mt][0], a[mt][1], a[mt][2], a[mt][3], b[np][0], b[np][1]);
                    MMA16816(acc_o[mt][np * 2 + 1],
                             a[mt][0], a[mt][1], a[mt][2], a[mt][3], b[np][2], b[np][3]);
                }
        }
    }

    // ---- rowsum reduce, divide, store ----
    __syncthreads();
    float* red = (float*)(smc + SM_P);
    #pragma unroll
    for (int mt = 0; mt < 2; mt++) {
        #pragma unroll
        for (int h = 0; h < 2; h++) {
            float s = rsum[mt][h];
            s += __shfl_xor_sync(0xFFFFFFFFu, s, 1);
            s += __shfl_xor_sync(0xFFFFFFFFu, s, 2);
            rsum[mt][h] = s;
        }
    }
    if (t4 == 0) {
        #pragma unroll
        for (int mt = 0; mt < 2; mt++) {
            int r0 = m0 + mt * 16 + g;
            red[r0 * 4 + wn]       = rsum[mt][0];
            red[(r0 + 8) * 4 + wn] = rsum[mt][1];
        }
    }
    __syncthreads();

    int b = z >> 4, h = z & 15;
    #pragma unroll
    for (int mt = 0; mt < 2; mt++) {
        int r0 = m0 + mt * 16 + g;
        float t0 = red[r0 * 4] + red[r0 * 4 + 1] + red[r0 * 4 + 2] + red[r0 * 4 + 3];
        float t1 = red[(r0 + 8) * 4] + red[(r0 + 8) * 4 + 1] +
                   red[(r0 + 8) * 4 + 2] + red[(r0 + 8) * 4 + 3];
        float i0 = (t0 > 0.0f) ? (1.0f / t0) : 0.0f;
        float i1 = (t1 > 0.0f) ? (1.0f / t1) : 0.0f;
        size_t s0 = bm + r0;
        __half* d0 = att + ((size_t)b * SEQ + s0) * DIM + h * HD;
        __half* d1 = att + ((size_t)b * SEQ + s0 + 8) * DIM + h * HD;
        #pragma unroll
        for (int nt = 0; nt < 4; nt++) {
            int col = n0 + nt * 8 + 2 * t4;
            *(__half2*)&d0[col] = __floats2half2_rn(acc_o[mt][nt][0] * i0, acc_o[mt][nt][1] * i0);
            *(__half2*)&d1[col] = __floats2half2_rn(acc_o[mt][nt][2] * i1, acc_o[mt][nt][3] * i1);
        }
    }
}

// ---------------- streaming fp32 -> fp16 ----------------
__global__ __launch_bounds__(256)
void tohalf(const float2* __restrict__ src, __half2* __restrict__ dst, int n2)
{
    int i = blockIdx.x * 256 + threadIdx.x;
    int stride = gridDim.x * 256;
    for (; i < n2; i += stride) {
        float2 v = src[i];
        dst[i] = __floats2half2_rn(v.x, v.y);
    }
}

// ---------------- launch ----------------
extern "C" void kernel_launch(void* const* d_in, const int* in_sizes, int n_in,
                              void* d_out, int out_size)
{
    const float* x     = (const float*)d_in[0];
    const int*   xmask = (const int*)  d_in[1];
    const float* fcos  = (const float*)d_in[2];
    const float* fsin  = (const float*)d_in[3];
    const float* Wqkv  = (const float*)d_in[4];
    const float* Wout  = (const float*)d_in[5];
    const float* qw    = (const float*)d_in[6];
    const float* kw    = (const float*)d_in[7];
    float* out = (float*)d_out;

    __half *q, *k, *v, *att, *xh, *wq, *wo;
    cudaGetSymbolAddress((void**)&q,   g_q);
    cudaGetSymbolAddress((void**)&k,   g_k);
    cudaGetSymbolAddress((void**)&v,   g_v);
    cudaGetSymbolAddress((void**)&att, g_att);
    cudaGetSymbolAddress((void**)&xh,  g_xh);
    cudaGetSymbolAddress((void**)&wq,  g_wq);
    cudaGetSymbolAddress((void**)&wo,  g_wo);

    cudaFuncSetAttribute(mma_gemm<EPI_PLAIN>, cudaFuncAttributeMaxDynamicSharedMemorySize, GSMEM_TOTAL);
    cudaFuncSetAttribute(mma_gemm<EPI_QKV>,   cudaFuncAttributeMaxDynamicSharedMemorySize, GSMEM_TOTAL);
    cudaFuncSetAttribute(flash_attn, cudaFuncAttributeMaxDynamicSharedMemorySize, FSMEM_TOTAL);

    float scale = rsqrtf((float)HD);

    // 0) convert raw GEMM inputs to fp16
    tohalf<<<1184, 256>>>((const float2*)x,    (__half2*)xh, (NTOK * DIM) / 2);
    tohalf<<<1184, 256>>>((const float2*)Wqkv, (__half2*)wq, (QKVD * DIM) / 2);
    tohalf<<<1184, 256>>>((const float2*)Wout, (__half2*)wo, (DIM * DIM) / 2);

    // 1) fused QKV GEMM + RMSNorm + RoPE -> g_q / g_k / g_v (fp16)
    mma_gemm<EPI_QKV><<<dim3(QKVD / 128, NTOK / 128), 128, GSMEM_TOTAL>>>(
        xh, wq, nullptr, DIM, DIM, DIM, 0, fcos, fsin, qw, kw, q, k, v);

    // 2) fused attention -> att (fp16)
    flash_attn<<<dim3(SEQ / 128, BSZ * NH), 512, FSMEM_TOTAL>>>(
        q, k, v, xmask, att, scale);

    // 3) out = att @ Wout^T (fp32)
    mma_gemm<EPI_PLAIN><<<dim3(DIM / 128, NTOK / 128), 128, GSMEM_TOTAL>>>(
        att, wo, out, DIM, DIM, DIM, DIM,
        nullptr, nullptr, nullptr, nullptr, nullptr, nullptr, nullptr);
}

// round 14
// speedup vs baseline: 8.3661x; 1.1198x over previous
#include <cuda_runtime.h>
#include <cuda_fp16.h>
#include <math.h>
#include <stdint.h>

// Problem constants
#define BSZ 2
#define SEQ 2048
#define DIM 2048
#define NH 16
#define NKV 8
#define HD 128
#define QKVD 4096          // (16 + 2*8) * 128
#define NTOK (BSZ*SEQ)     // 4096

// ---------------- scratch (static __device__, no allocations) ----------------
static __device__ __half g_q  [(size_t)BSZ * NH  * SEQ * HD];        // 16 MB
static __device__ __half g_k  [(size_t)BSZ * NKV * SEQ * HD];        // 8 MB
static __device__ __half g_v  [(size_t)BSZ * NKV * SEQ * HD];        // 8 MB (K-major)
static __device__ __half g_att[(size_t)NTOK * DIM];                  // 16 MB
static __device__ __half g_xh [(size_t)NTOK * DIM];                  // 16 MB
static __device__ __half g_wq [(size_t)QKVD * DIM];                  // 16 MB
static __device__ __half g_wo [(size_t)DIM * DIM];                   // 8 MB

__device__ __forceinline__ uint32_t smem_u32(const void* p) {
    uint32_t a;
    asm("{ .reg .u64 t; cvta.to.shared.u64 t, %1; cvt.u32.u64 %0, t; }" : "=r"(a) : "l"(p));
    return a;
}

__device__ __forceinline__ void cpa16(uint32_t saddr, const void* g) {
    asm volatile("cp.async.cg.shared.global [%0], [%1], 16;" :: "r"(saddr), "l"(g));
}

__device__ __forceinline__ float ex2f(float x) {
    float y;
    asm("ex2.approx.f32 %0, %1;" : "=f"(y) : "f"(x));
    return y;
}

#define MMA16816(acc, a0, a1, a2, a3, b0, b1) \
    asm volatile( \
        "mma.sync.aligned.m16n8k16.row.col.f32.f16.f16.f32 " \
        "{%0,%1,%2,%3}, {%4,%5,%6,%7}, {%8,%9}, {%0,%1,%2,%3};" \
        : "+f"((acc)[0]), "+f"((acc)[1]), "+f"((acc)[2]), "+f"((acc)[3]) \
        : "r"(a0), "r"(a1), "r"(a2), "r"(a3), "r"(b0), "r"(b1))

#define LDMX4(d, addr) \
    asm volatile("ldmatrix.sync.aligned.m8n8.x4.shared.b16 {%0,%1,%2,%3}, [%4];" \
        : "=r"((d)[0]), "=r"((d)[1]), "=r"((d)[2]), "=r"((d)[3]) : "r"(addr))

#define LDMX4T(d, addr) \
    asm volatile("ldmatrix.sync.aligned.m8n8.x4.trans.shared.b16 {%0,%1,%2,%3}, [%4];" \
        : "=r"((d)[0]), "=r"((d)[1]), "=r"((d)[2]), "=r"((d)[3]) : "r"(addr))

// ============================================================================
//          projection GEMM: C = A @ B^T   (K chunk 64, 2 stages)
//  EPI_PLAIN: fp32 C out (out projection).
//  EPI_QKV: CTA n-tile == one head. RMSNorm+RoPE for Q/K, plain fp16 for V.
// ============================================================================
#define GRB 144                               // row bytes: 64 halves + 16B pad
#define GSTAGE_BYTES (256 * GRB)              // A 128 rows + B 128 rows = 36864
#define GB_OFF (128 * GRB)                    // 18432
#define GSTAGES 2
#define GSMEM_TOTAL (GSTAGES * GSTAGE_BYTES)  // 73728 B

#define EPI_PLAIN 0
#define EPI_QKV   1

template<int EPI>
__global__ __launch_bounds__(128, 3)
void mma_gemm(const __half* __restrict__ A, const __half* __restrict__ B, float* __restrict__ C,
              int K, int lda, int ldb, int ldc,
              const float* __restrict__ cosb, const float* __restrict__ sinb,
              const float* __restrict__ qw, const float* __restrict__ kw,
              __half* __restrict__ qo, __half* __restrict__ ko, __half* __restrict__ vo)
{
    extern __shared__ char smc[];
    uint32_t sbase = smem_u32(smc);

    int tid = threadIdx.x;
    int wid = tid >> 5, lane = tid & 31;
    int g = lane >> 2, t4 = lane & 3;
    int wm = wid & 1, wn = wid >> 1;
    int m0 = wm * 64, n0 = wn * 64;

    size_t bm = (size_t)blockIdx.y * 128;
    size_t bn = (size_t)blockIdx.x * 128;
    int z = blockIdx.x;                  // head slot for EPI_QKV

    const int NC = K >> 6;               // 64-wide K chunks

    float acc[4][8][4];
    #pragma unroll
    for (int i = 0; i < 4; i++)
        #pragma unroll
        for (int j = 0; j < 8; j++)
            #pragma unroll
            for (int r = 0; r < 4; r++) acc[i][j][r] = 0.0f;

    int lr = lane & 7;
    uint32_t aoff = (uint32_t)((m0 + ((lane >> 3) & 1) * 8 + lr) * GRB + (lane >> 4) * 16);
    uint32_t boff = (uint32_t)(GB_OFF + (n0 + (lane >> 4) * 8 + lr) * GRB + ((lane >> 3) & 1) * 16);

    auto load_chunk = [&](int c, int st) {
        const __half* Ak = A + c * 64;
        const __half* Bk = B + c * 64;
        uint32_t sA = sbase + (uint32_t)st * GSTAGE_BYTES;
        #pragma unroll
        for (int i = 0; i < 8; i++) {
            int idx = tid + i * 128;           // 0..1023
            int row = idx >> 3, seg = idx & 7;
            cpa16(sA + row * GRB + seg * 16, Ak + (bm + row) * (size_t)lda + seg * 8);
            cpa16(sA + GB_OFF + row * GRB + seg * 16, Bk + (bn + row) * (size_t)ldb + seg * 8);
        }
        asm volatile("cp.async.commit_group;" ::: "memory");
    };

    load_chunk(0, 0);

    for (int c = 0; c < NC; c++) {
        int st = c & 1;
        asm volatile("cp.async.wait_group 0;" ::: "memory");
        __syncthreads();

        if (c + 1 < NC) load_chunk(c + 1, st ^ 1);

        uint32_t sg = sbase + (uint32_t)st * GSTAGE_BYTES;

        #pragma unroll
        for (int ks = 0; ks < 4; ks++) {
            uint32_t a[4][4];
            #pragma unroll
            for (int mt = 0; mt < 4; mt++)
                LDMX4(a[mt], sg + aoff + mt * (16 * GRB) + ks * 32);
            #pragma unroll
            for (int np = 0; np < 4; np++) {
                uint32_t b[4];
                LDMX4(b, sg + boff + np * (16 * GRB) + ks * 32);
                #pragma unroll
                for (int mt = 0; mt < 4; mt++) {
                    MMA16816(acc[mt][np * 2],
                             a[mt][0], a[mt][1], a[mt][2], a[mt][3], b[0], b[1]);
                    MMA16816(acc[mt][np * 2 + 1],
                             a[mt][0], a[mt][1], a[mt][2], a[mt][3], b[2], b[3]);
                }
            }
        }
    }

    if (EPI == EPI_PLAIN) {
        #pragma unroll
        for (int mt = 0; mt < 4; mt++) {
            size_t row = bm + m0 + mt * 16 + g;
            #pragma unroll
            for (int nt = 0; nt < 8; nt++) {
                size_t col = bn + n0 + nt * 8 + 2 * t4;
                *(float2*)&C[row * (size_t)ldc + col] =
                    make_float2(acc[mt][nt][0], acc[mt][nt][1]);
                *(float2*)&C[(row + 8) * (size_t)ldc + col] =
                    make_float2(acc[mt][nt][2], acc[mt][nt][3]);
            }
        }
        return;
    }

    // ---------------- EPI_QKV ----------------
    if (z >= NH + NKV) {
        int kh = z - (NH + NKV);
        #pragma unroll
        for (int mt = 0; mt < 4; mt++) {
            size_t tok = bm + m0 + mt * 16 + g;
            int bb = (int)(tok >> 11);
            int s  = (int)(tok & (SEQ - 1));
            __half* d0 = vo + ((size_t)(bb * NKV + kh) * SEQ + s) * HD;
            __half* d1 = d0 + (size_t)8 * HD;
            #pragma unroll
            for (int nt = 0; nt < 8; nt++) {
                int cc = n0 + nt * 8 + 2 * t4;
                *(__half2*)&d0[cc] = __floats2half2_rn(acc[mt][nt][0], acc[mt][nt][1]);
                *(__half2*)&d1[cc] = __floats2half2_rn(acc[mt][nt][2], acc[mt][nt][3]);
            }
        }
        return;
    }

    // Q or K head: RMSNorm + RoPE
    __syncthreads();
    float* red = (float*)smc;             // [128][2]

    #pragma unroll
    for (int mt = 0; mt < 4; mt++) {
        float s0 = 0.0f, s1 = 0.0f;
        #pragma unroll
        for (int nt = 0; nt < 8; nt++) {
            s0 += acc[mt][nt][0] * acc[mt][nt][0] + acc[mt][nt][1] * acc[mt][nt][1];
            s1 += acc[mt][nt][2] * acc[mt][nt][2] + acc[mt][nt][3] * acc[mt][nt][3];
        }
        s0 += __shfl_xor_sync(0xFFFFFFFFu, s0, 1);
        s0 += __shfl_xor_sync(0xFFFFFFFFu, s0, 2);
        s1 += __shfl_xor_sync(0xFFFFFFFFu, s1, 1);
        s1 += __shfl_xor_sync(0xFFFFFFFFu, s1, 2);
        if (t4 == 0) {
            int r0 = m0 + mt * 16 + g;
            red[r0 * 2 + wn]       = s0;
            red[(r0 + 8) * 2 + wn] = s1;
        }
    }
    __syncthreads();

    const float* w = (z < NH) ? qw : kw;
    #pragma unroll
    for (int mt = 0; mt < 4; mt++) {
        int r0 = m0 + mt * 16 + g;
        float inv0 = rsqrtf((red[r0 * 2] + red[r0 * 2 + 1]) * (1.0f / HD) + 1e-5f);
        float inv1 = rsqrtf((red[(r0 + 8) * 2] + red[(r0 + 8) * 2 + 1]) * (1.0f / HD) + 1e-5f);
        size_t tok = bm + r0;
        int bb = (int)(tok >> 11);
        int s  = (int)(tok & (SEQ - 1));
        __half* d0;
        if (z < NH) d0 = qo + ((size_t)(bb * NH + z) * SEQ + s) * HD;
        else        d0 = ko + ((size_t)(bb * NKV + (z - NH)) * SEQ + s) * HD;
        __half* d1 = d0 + (size_t)8 * HD;
        const float* cr0 = cosb + (size_t)s * (HD / 2);
        const float* sr0 = sinb + (size_t)s * (HD / 2);
        const float* cr1 = cr0 + 8 * (HD / 2);
        const float* sr1 = sr0 + 8 * (HD / 2);
        #pragma unroll
        for (int nt = 0; nt < 8; nt++) {
            int cc = n0 + nt * 8 + 2 * t4;
            int ii = cc >> 1;
            float w0 = w[cc], w1 = w[cc + 1];
            float c0 = cr0[ii], sn0 = sr0[ii];
            float c1 = cr1[ii], sn1 = sr1[ii];
            float y0 = acc[mt][nt][0] * inv0 * w0;
            float y1 = acc[mt][nt][1] * inv0 * w1;
            float y2 = acc[mt][nt][2] * inv1 * w0;
            float y3 = acc[mt][nt][3] * inv1 * w1;
            *(__half2*)&d0[cc] = __floats2half2_rn(y0 * c0 - y1 * sn0, y0 * sn0 + y1 * c0);
            *(__half2*)&d1[cc] = __floats2half2_rn(y2 * c1 - y3 * sn1, y2 * sn1 + y3 * c1);
        }
    }
}

// ============================================================================
//  fused flash attention (kv-block 128; V in K-major via ldmatrix.trans)
// ============================================================================
#define FRB  272              // row bytes (128 halves + 8 pad)
#define FRU  68               // row u32
#define SM_Q   0
#define SM_P   34816
#define SM_KV  69632
#define KV_STG 69632          // K 34816 + V 34816
#define FSMEM_TOTAL (SM_KV + 2 * KV_STG)   // 208896 B
#define NKVB (SEQ / 128)      // 16

__global__ __launch_bounds__(512, 1)
void flash_attn(const __half* __restrict__ q, const __half* __restrict__ k,
                const __half* __restrict__ v, const int* __restrict__ mask,
                __half* __restrict__ att, float scale2)   // scale2 = scale * log2(e)
{
    extern __shared__ char smc[];
    uint32_t sbase = smem_u32(smc);

    int tid = threadIdx.x;
    int wid = tid >> 5, lane = tid & 31;
    int g = lane >> 2, t4 = lane & 3, lr = lane & 7;
    int wm = wid & 3, wn = wid >> 2;
    int m0 = wm * 32, n0 = wn * 32;

    int z  = blockIdx.y;
    size_t bm = (size_t)blockIdx.x * 128;

    const __half* Qg = q + ((size_t)z * SEQ + bm) * HD;
    const __half* Kg = k + (size_t)(z >> 1) * SEQ * HD;
    const __half* Vg = v + (size_t)(z >> 1) * SEQ * HD;
    const int* mrow  = mask + (size_t)(z >> 4) * SEQ;

    uint32_t a_base = (uint32_t)((m0 + ((lane >> 3) & 1) * 8 + lr) * FRB + (lane >> 4) * 16);
    uint32_t b_base = (uint32_t)((n0 + (lane >> 4) * 8 + lr) * FRB + ((lane >> 3) & 1) * 16);
    uint32_t vb_base = (uint32_t)((((lane >> 3) & 1) * 8 + lr) * FRB + (n0 + (lane >> 4) * 8) * 2);

    float acc_o[2][4][4];
    #pragma unroll
    for (int i = 0; i < 2; i++)
        #pragma unroll
        for (int j = 0; j < 4; j++)
            #pragma unroll
            for (int r = 0; r < 4; r++) acc_o[i][j][r] = 0.0f;
    float rsum[2][2] = {};

    auto load_stage = [&](int c, int st) {
        uint32_t sK = sbase + SM_KV + (uint32_t)st * KV_STG;
        uint32_t sV = sK + 34816;
        #pragma unroll
        for (int i = 0; i < 4; i++) {
            int idx = tid + i * 512;
            int row = idx >> 4, seg = idx & 15;
            cpa16(sK + row * FRB + seg * 16, Kg + ((size_t)(c * 128 + row)) * HD + seg * 8);
            cpa16(sV + row * FRB + seg * 16, Vg + ((size_t)(c * 128 + row)) * HD + seg * 8);
        }
        asm volatile("cp.async.commit_group;" ::: "memory");
    };

    #pragma unroll
    for (int i = 0; i < 4; i++) {
        int idx = tid + i * 512;
        int row = idx >> 4, seg = idx & 15;
        cpa16(sbase + SM_Q + row * FRB + seg * 16, Qg + (size_t)row * HD + seg * 8);
    }
    load_stage(0, 0);

    for (int c = 0; c < NKVB; c++) {
        int st = c & 1;
        asm volatile("cp.async.wait_group 0;" ::: "memory");
        __syncthreads();

        if (c + 1 < NKVB) load_stage(c + 1, st ^ 1);

        uint32_t sQ = sbase + SM_Q;
        uint32_t sK = sbase + SM_KV + (uint32_t)st * KV_STG;
        uint32_t sV = sK + 34816;
        uint32_t sP = sbase + SM_P;

        // ---- S = Q @ K^T, warp tile 32x32 ----
        float acc_s[2][4][4];
        #pragma unroll
        for (int i = 0; i < 2; i++)
            #pragma unroll
            for (int j = 0; j < 4; j++)
                #pragma unroll
                for (int r = 0; r < 4; r++) acc_s[i][j][r] = 0.0f;

        #pragma unroll
        for (int kt = 0; kt < 8; kt++) {
            uint32_t a[2][4], b[2][4];
            LDMX4(a[0], sQ + a_base + kt * 32);
            LDMX4(a[1], sQ + a_base + 16 * FRB + kt * 32);
            LDMX4(b[0], sK + b_base + kt * 32);
            LDMX4(b[1], sK + b_base + 16 * FRB + kt * 32);
            #pragma unroll
            for (int mt = 0; mt < 2; mt++)
                #pragma unroll
                for (int np = 0; np < 2; np++) {
                    MMA16816(acc_s[mt][np * 2],
                             a[mt][0], a[mt][1], a[mt][2], a[mt][3], b[np][0], b[np][1]);
                    MMA16816(acc_s[mt][np * 2 + 1],
                             a[mt][0], a[mt][1], a[mt][2], a[mt][3], b[np][2], b[np][3]);
                }
        }

        // ---- exp2(s*scale2) * mask, rowsum accum, pack P ----
        uint32_t* Ps = (uint32_t*)(smc + SM_P);
        #pragma unroll
        for (int nb = 0; nb < 4; nb++) {
            int col0 = c * 128 + n0 + nb * 8 + 2 * t4;
            float mk0 = mrow[col0]     ? 1.0f : 0.0f;
            float mk1 = mrow[col0 + 1] ? 1.0f : 0.0f;
            #pragma unroll
            for (int mt = 0; mt < 2; mt++) {
                float e0 = ex2f(acc_s[mt][nb][0] * scale2) * mk0;
                float e1 = ex2f(acc_s[mt][nb][1] * scale2) * mk1;
                float e2 = ex2f(acc_s[mt][nb][2] * scale2) * mk0;
                float e3 = ex2f(acc_s[mt][nb][3] * scale2) * mk1;
                rsum[mt][0] += e0 + e1;
                rsum[mt][1] += e2 + e3;
                int prow = m0 + mt * 16 + g;
                int pcol = wn * 16 + nb * 4 + t4;
                __half2 h01 = __floats2half2_rn(e0, e1);
                __half2 h23 = __floats2half2_rn(e2, e3);
                Ps[prow * FRU + pcol]       = *(uint32_t*)&h01;
                Ps[(prow + 8) * FRU + pcol] = *(uint32_t*)&h23;
            }
        }
        __syncthreads();

        // ---- out += P @ V (trans ldmatrix on V) ----
        #pragma unroll
        for (int kt = 0; kt < 8; kt++) {
            uint32_t a[2][4], b[2][4];
            LDMX4(a[0], sP + a_base + kt * 32);
            LDMX4(a[1], sP + a_base + 16 * FRB + kt * 32);
            LDMX4T(b[0], sV + vb_base + kt * (16 * FRB));
            LDMX4T(b[1], sV + vb_base + kt * (16 * FRB) + 32);
            #pragma unroll
            for (int mt = 0; mt < 2; mt++)
                #pragma unroll
                for (int np = 0; np < 2; np++) {
                    MMA16816(acc_o[mt][np * 2],
                             a[mt][0], a[mt][1], a[mt][2], a[mt][3], b[np][0], b[np][1]);
                    MMA16816(acc_o[mt][np * 2 + 1],
                             a[mt][0], a[mt][1], a[mt][2], a[mt][3], b[np][2], b[np][3]);
                }
        }
    }

    // ---- rowsum reduce, divide, store ----
    __syncthreads();
    float* red = (float*)(smc + SM_P);
    #pragma unroll
    for (int mt = 0; mt < 2; mt++) {
        #pragma unroll
        for (int h = 0; h < 2; h++) {
            float s = rsum[mt][h];
            s += __shfl_xor_sync(0xFFFFFFFFu, s, 1);
            s += __shfl_xor_sync(0xFFFFFFFFu, s, 2);
            rsum[mt][h] = s;
        }
    }
    if (t4 == 0) {
        #pragma unroll
        for (int mt = 0; mt < 2; mt++) {
            int r0 = m0 + mt * 16 + g;
            red[r0 * 4 + wn]       = rsum[mt][0];
            red[(r0 + 8) * 4 + wn] = rsum[mt][1];
        }
    }
    __syncthreads();

    int b = z >> 4, h = z & 15;
    #pragma unroll
    for (int mt = 0; mt < 2; mt++) {
        int r0 = m0 + mt * 16 + g;
        float t0 = red[r0 * 4] + red[r0 * 4 + 1] + red[r0 * 4 + 2] + red[r0 * 4 + 3];
        float t1 = red[(r0 + 8) * 4] + red[(r0 + 8) * 4 + 1] +
                   red[(r0 + 8) * 4 + 2] + red[(r0 + 8) * 4 + 3];
        float i0 = (t0 > 0.0f) ? (1.0f / t0) : 0.0f;
        float i1 = (t1 > 0.0f) ? (1.0f / t1) : 0.0f;
        size_t s0 = bm + r0;
        __half* d0 = att + ((size_t)b * SEQ + s0) * DIM + h * HD;
        __half* d1 = att + ((size_t)b * SEQ + s0 + 8) * DIM + h * HD;
        #pragma unroll
        for (int nt = 0; nt < 4; nt++) {
            int col = n0 + nt * 8 + 2 * t4;
            *(__half2*)&d0[col] = __floats2half2_rn(acc_o[mt][nt][0] * i0, acc_o[mt][nt][1] * i0);
            *(__half2*)&d1[col] = __floats2half2_rn(acc_o[mt][nt][2] * i1, acc_o[mt][nt][3] * i1);
        }
    }
}

// ---------------- merged fp32 -> fp16 conversion (3 tensors, 1 launch) ----------------
__global__ __launch_bounds__(256)
void tohalf3(const float2* __restrict__ s0, __half2* __restrict__ d0, int n0,
             const float2* __restrict__ s1, __half2* __restrict__ d1, int n1,
             const float2* __restrict__ s2, __half2* __restrict__ d2, int n2)
{
    int total = n0 + n1 + n2;
    int i = blockIdx.x * 256 + threadIdx.x;
    int stride = gridDim.x * 256;
    for (; i < total; i += stride) {
        const float2* s; __half2* d; int j = i;
        if (j < n0)            { s = s0; d = d0; }
        else if (j < n0 + n1)  { s = s1; d = d1; j -= n0; }
        else                   { s = s2; d = d2; j -= n0 + n1; }
        float2 v = s[j];
        d[j] = __floats2half2_rn(v.x, v.y);
    }
}

// ---------------- launch ----------------
extern "C" void kernel_launch(void* const* d_in, const int* in_sizes, int n_in,
                              void* d_out, int out_size)
{
    const float* x     = (const float*)d_in[0];
    const int*   xmask = (const int*)  d_in[1];
    const float* fcos  = (const float*)d_in[2];
    const float* fsin  = (const float*)d_in[3];
    const float* Wqkv  = (const float*)d_in[4];
    const float* Wout  = (const float*)d_in[5];
    const float* qw    = (const float*)d_in[6];
    const float* kw    = (const float*)d_in[7];
    float* out = (float*)d_out;

    __half *q, *k, *v, *att, *xh, *wq, *wo;
    cudaGetSymbolAddress((void**)&q,   g_q);
    cudaGetSymbolAddress((void**)&k,   g_k);
    cudaGetSymbolAddress((void**)&v,   g_v);
    cudaGetSymbolAddress((void**)&att, g_att);
    cudaGetSymbolAddress((void**)&xh,  g_xh);
    cudaGetSymbolAddress((void**)&wq,  g_wq);
    cudaGetSymbolAddress((void**)&wo,  g_wo);

    cudaFuncSetAttribute(mma_gemm<EPI_PLAIN>, cudaFuncAttributeMaxDynamicSharedMemorySize, GSMEM_TOTAL);
    cudaFuncSetAttribute(mma_gemm<EPI_QKV>,   cudaFuncAttributeMaxDynamicSharedMemorySize, GSMEM_TOTAL);
    cudaFuncSetAttribute(flash_attn, cudaFuncAttributeMaxDynamicSharedMemorySize, FSMEM_TOTAL);

    float scale2 = rsqrtf((float)HD) * 1.4426950408889634f;   // scale * log2(e)

    // 0) convert raw GEMM inputs to fp16 (single launch)
    tohalf3<<<2368, 256>>>(
        (const float2*)x,    (__half2*)xh, (NTOK * DIM) / 2,
        (const float2*)Wqkv, (__half2*)wq, (QKVD * DIM) / 2,
        (const float2*)Wout, (__half2*)wo, (DIM * DIM) / 2);

    // 1) fused QKV GEMM + RMSNorm + RoPE -> g_q / g_k / g_v (fp16)
    mma_gemm<EPI_QKV><<<dim3(QKVD / 128, NTOK / 128), 128, GSMEM_TOTAL>>>(
        xh, wq, nullptr, DIM, DIM, DIM, 0, fcos, fsin, qw, kw, q, k, v);

    // 2) fused attention -> att (fp16)
    flash_attn<<<dim3(SEQ / 128, BSZ * NH), 512, FSMEM_TOTAL>>>(
        q, k, v, xmask, att, scale2);

    // 3) out = att @ Wout^T (fp32)
    mma_gemm<EPI_PLAIN><<<dim3(DIM / 128, NTOK / 128), 128, GSMEM_TOTAL>>>(
        att, wo, out, DIM, DIM, DIM, DIM,
        nullptr, nullptr, nullptr, nullptr, nullptr, nullptr, nullptr);
}